// round 9
// baseline (speedup 1.0000x reference)
#include <cuda_runtime.h>
#include <cuda_bf16.h>
#include <math.h>
#include <stdint.h>

#define BB 2
#define SS 2048
#define EE 1024
#define HH 8
#define DHH 64
#define DAA 512
#define DMLP 2048
#define NTOK 4096
#define SCALE_ATTN 0.04419417382415922f
#define SCALE_L2E 0.06375944628228341f   // SCALE_ATTN * log2(e)
#define LN_EPS 1e-5f

// GEMM: 128x128 CTA tile, warp 64x32, K-chunk 32.
// Swizzled 64B rows (no pad): addr = row*64 + (off ^ ((row&6)<<3)) -> conflict-free ldmatrix.
// Stage = 4 planes * 128 rows * 64B = 32KB; 3 stages = 96KB; 2 CTAs/SM = 192KB <= 228KB.
#define GROWB 64
#define PLANE_B 8192
#define STAGE_B 32768
#define SMEM_GEMM (3 * STAGE_B)
#define GSWZ(row, off) ((uint32_t)(off) ^ (((uint32_t)(row) & 6u) << 3))

#define FROWB 144
#define FQPL 18432
#define FKPL 9216
#define FSTG 36864
#define SMEM_FLASH (2 * FQPL + 2 * FSTG)

// ---------------- scratch ----------------
__device__ float g_qkvI[NTOK * 1536];
__device__ float g_qkvC[NTOK * 1536];

__device__ uint16_t pLNh[NTOK * EE],     pLNl[NTOK * EE];
__device__ uint16_t pLN2h[NTOK * EE],    pLN2l[NTOK * EE];
__device__ uint16_t pMIDh[NTOK * DMLP],  pMIDl[NTOK * DMLP];
__device__ uint16_t pMID2h[NTOK * DMLP], pMID2l[NTOK * DMLP];
__device__ uint16_t pQh[NTOK * EE],      pQl[NTOK * EE];
__device__ uint16_t pTGTh[NTOK * EE],    pTGTl[NTOK * EE];
__device__ uint16_t pAOIh[NTOK * DAA],   pAOIl[NTOK * DAA];
__device__ uint16_t pAOCh[NTOK * DAA],   pAOCl[NTOK * DAA];
__device__ uint16_t pFQIh[NTOK * DAA],   pFQIl[NTOK * DAA];
__device__ uint16_t pFKIh[NTOK * DAA],   pFKIl[NTOK * DAA];
__device__ uint16_t pFVIh[NTOK * DAA],   pFVIl[NTOK * DAA];
__device__ uint16_t pFQCh[NTOK * DAA],   pFQCl[NTOK * DAA];
__device__ uint16_t pFKCh[NTOK * DAA],   pFKCl[NTOK * DAA];
__device__ uint16_t pFVCh[NTOK * DAA],   pFVCl[NTOK * DAA];

__device__ uint16_t pW1h[DMLP * EE],    pW1l[DMLP * EE];
__device__ uint16_t pW2h[EE * DMLP],    pW2l[EE * DMLP];
__device__ uint16_t pIQKh[1024 * EE],   pIQKl[1024 * EE];
__device__ uint16_t pIVh[DAA * EE],     pIVl[DAA * EE];
__device__ uint16_t pIOh[EE * DAA],     pIOl[EE * DAA];
__device__ uint16_t pCQKVh[1536 * EE],  pCQKVl[1536 * EE];
__device__ uint16_t pCOh[EE * DAA],     pCOl[EE * DAA];

// ---------------- helpers ----------------
__device__ __forceinline__ uint32_t pk2(__nv_bfloat16 a, __nv_bfloat16 b) {
    uint16_t ra = *reinterpret_cast<uint16_t*>(&a);
    uint16_t rb = *reinterpret_cast<uint16_t*>(&b);
    return (uint32_t)ra | ((uint32_t)rb << 16);
}
__device__ __forceinline__ void split1(float x, __nv_bfloat16& h, __nv_bfloat16& l) {
    h = __float2bfloat16(x);
    l = __float2bfloat16(x - __bfloat162float(h));
}
__device__ __forceinline__ void mma16816(float* c, const uint32_t* a, const uint32_t* b) {
    asm volatile(
        "mma.sync.aligned.m16n8k16.row.col.f32.bf16.bf16.f32 "
        "{%0,%1,%2,%3}, {%4,%5,%6,%7}, {%8,%9}, {%0,%1,%2,%3};"
        : "+f"(c[0]), "+f"(c[1]), "+f"(c[2]), "+f"(c[3])
        : "r"(a[0]), "r"(a[1]), "r"(a[2]), "r"(a[3]), "r"(b[0]), "r"(b[1]));
}
__device__ __forceinline__ void ldsm4(uint32_t& r0, uint32_t& r1, uint32_t& r2, uint32_t& r3,
                                      uint32_t addr) {
    asm volatile("ldmatrix.sync.aligned.m8n8.x4.shared.b16 {%0,%1,%2,%3}, [%4];"
                 : "=r"(r0), "=r"(r1), "=r"(r2), "=r"(r3) : "r"(addr));
}
__device__ __forceinline__ void ldsm4t(uint32_t& r0, uint32_t& r1, uint32_t& r2, uint32_t& r3,
                                       uint32_t addr) {
    asm volatile("ldmatrix.sync.aligned.m8n8.x4.trans.shared.b16 {%0,%1,%2,%3}, [%4];"
                 : "=r"(r0), "=r"(r1), "=r"(r2), "=r"(r3) : "r"(addr));
}
__device__ __forceinline__ void cpa16(uint32_t s, const void* g) {
    asm volatile("cp.async.ca.shared.global [%0], [%1], 16;" :: "r"(s), "l"(g));
}
__device__ __forceinline__ void cpa_commit() {
    asm volatile("cp.async.commit_group;" ::: "memory");
}
template<int N>
__device__ __forceinline__ void cpa_wait() {
    asm volatile("cp.async.wait_group %0;" :: "n"(N) : "memory");
}
__device__ __forceinline__ float exp2p(float x) {
    x = fmaxf(x, -80.f);
    float n = rintf(x);
    float f = x - n;
    float p = 1.3333558146428443e-3f;
    p = p * f + 9.618129107628477e-3f;
    p = p * f + 5.550410866482158e-2f;
    p = p * f + 2.402265069591007e-1f;
    p = p * f + 6.931471805599453e-1f;
    p = p * f + 1.0f;
    return p * __int_as_float(((int)n + 127) << 23);
}

__device__ __forceinline__ float block_reduce_sum(float v) {
    __shared__ float red[32];
    int lane = threadIdx.x & 31, w = threadIdx.x >> 5;
#pragma unroll
    for (int o = 16; o > 0; o >>= 1) v += __shfl_xor_sync(0xffffffffu, v, o);
    __syncthreads();
    if (lane == 0) red[w] = v;
    __syncthreads();
    v = (lane < 8) ? red[lane] : 0.f;
#pragma unroll
    for (int o = 16; o > 0; o >>= 1) v += __shfl_xor_sync(0xffffffffu, v, o);
    return v;
}

// ---------------- LayerNorm -> bf16 hi/lo planes ----------------
__global__ void ln_split(const float* __restrict__ x, const float* __restrict__ g,
                         const float* __restrict__ b,
                         uint16_t* __restrict__ oh, uint16_t* __restrict__ ol) {
    int row = blockIdx.x, t = threadIdx.x;
    float4 v = *(const float4*)&x[(size_t)row * EE + 4 * t];
    float s = v.x + v.y + v.z + v.w;
    float mean = block_reduce_sum(s) * (1.0f / EE);
    float d0 = v.x - mean, d1 = v.y - mean, d2 = v.z - mean, d3 = v.w - mean;
    float var = block_reduce_sum(d0 * d0 + d1 * d1 + d2 * d2 + d3 * d3) * (1.0f / EE);
    float rstd = rsqrtf(var + LN_EPS);
    float4 gg = *(const float4*)&g[4 * t];
    float4 bb = *(const float4*)&b[4 * t];
    float y0 = d0 * rstd * gg.x + bb.x;
    float y1 = d1 * rstd * gg.y + bb.y;
    float y2 = d2 * rstd * gg.z + bb.z;
    float y3 = d3 * rstd * gg.w + bb.w;
    __nv_bfloat16 h0, h1, h2, h3, l0, l1, l2, l3;
    split1(y0, h0, l0); split1(y1, h1, l1); split1(y2, h2, l2); split1(y3, h3, l3);
    size_t off = (size_t)row * EE + 4 * t;
    *(uint2*)&oh[off] = make_uint2(pk2(h0, h1), pk2(h2, h3));
    *(uint2*)&ol[off] = make_uint2(pk2(l0, l1), pk2(l2, l3));
}

// ---------------- weight conversion, single launch ----------------
__device__ __forceinline__ void convB_body(const float* __restrict__ W,
                                           uint16_t* __restrict__ Bh,
                                           uint16_t* __restrict__ Bl, int K, int N) {
    __shared__ float ts[64][129];
    int nt = blockIdx.x, kt = blockIdx.y, tid = threadIdx.x;
    int k0 = kt * 64, n0 = nt * 128;
#pragma unroll
    for (int i = 0; i < 32; i++) {
        int idx = tid + i * 256;
        int kk = idx >> 7, nn = idx & 127;
        ts[kk][nn] = W[(size_t)(k0 + kk) * N + n0 + nn];
    }
    __syncthreads();
#pragma unroll
    for (int j = 0; j < 4; j++) {
        int job = tid + j * 256;
        int n = job >> 3, kg = (job & 7) * 8;
        __nv_bfloat16 h[8], l[8];
#pragma unroll
        for (int i = 0; i < 8; i++) split1(ts[kg + i][n], h[i], l[i]);
        uint4 uh = make_uint4(pk2(h[0], h[1]), pk2(h[2], h[3]), pk2(h[4], h[5]), pk2(h[6], h[7]));
        uint4 ul = make_uint4(pk2(l[0], l[1]), pk2(l[2], l[3]), pk2(l[4], l[5]), pk2(l[6], l[7]));
        size_t off = (size_t)(n0 + n) * K + k0 + kg;
        *(uint4*)&Bh[off] = uh;
        *(uint4*)&Bl[off] = ul;
    }
}

struct ConvJobs {
    const float* src[10];
    uint16_t* dh[10];
    uint16_t* dl[10];
    int K[10], N[10];
};
__global__ void conv_all(ConvJobs j) {
    int w = blockIdx.z;
    int K = j.K[w], N = j.N[w];
    if (blockIdx.x * 128 >= N || blockIdx.y * 64 >= K) return;
    convB_body(j.src[w], j.dh[w], j.dl[w], K, N);
}

// ---------------- HMMA bf16-split GEMM: 128x128, warp 64x32, 3-stage, 1 sync/chunk ----------------
// MODE 0: C=AB(fp32, ldC)  1: planes=gelu(AB+bias)  2: C=AB+bias+R (+planes)  3: C=AB+R
template<int MODE>
__global__ void __launch_bounds__(256) gemm_tc(
    const uint16_t* __restrict__ Ah, const uint16_t* __restrict__ Al,
    const uint16_t* __restrict__ Bh, const uint16_t* __restrict__ Bl,
    const float* __restrict__ bias, const float* __restrict__ R,
    float* __restrict__ C, uint16_t* __restrict__ Ch, uint16_t* __restrict__ Cl,
    int N, int K, int ldC)
{
    extern __shared__ char sm[];
    const uint32_t sbase = (uint32_t)__cvta_generic_to_shared(sm);
    const int tid = threadIdx.x;
    const int warp = tid >> 5, lane = tid & 31;
    const int wm = warp & 1, wn = warp >> 1;
    const int m0 = blockIdx.y * 128, n0 = blockIdx.x * 128;
    const int KT = K >> 5;

    const uint16_t* gA[2] = { Ah + (size_t)m0 * K, Al + (size_t)m0 * K };
    const uint16_t* gB[2] = { Bh + (size_t)n0 * K, Bl + (size_t)n0 * K };

    const int rl = lane & 7, grp = lane >> 3;
    const int a_r = rl + (grp & 1) * 8;
    const int a_c = (grp >> 1) * 8;      // bytes offset = a_c*2 in {0,16}
    const int b_r = rl + ((grp >> 1) & 1) * 8;
    const int b_c = (grp & 1) * 8;

    float acc[4][4][4];
#pragma unroll
    for (int i = 0; i < 4; i++)
#pragma unroll
        for (int j = 0; j < 4; j++)
#pragma unroll
            for (int k = 0; k < 4; k++) acc[i][j][k] = 0.f;

    auto issue = [&](int stage, int kt) {
        uint32_t s0 = sbase + stage * STAGE_B;
        int kel = kt * 32;
#pragma unroll
        for (int pl = 0; pl < 4; pl++) {
            const uint16_t* g = (pl < 2) ? gA[pl] : gB[pl - 2];
#pragma unroll
            for (int i = 0; i < 2; i++) {
                int seg = tid + i * 256;
                int m = seg >> 2, s = seg & 3;
                cpa16(s0 + pl * PLANE_B + m * GROWB + GSWZ(m, s * 16),
                      g + (size_t)m * K + kel + s * 8);
            }
        }
        cpa_commit();
    };

    issue(0, 0);
    if (KT > 1) issue(1, 1);

    int st = 0;
    for (int kt = 0; kt < KT; kt++) {
        if (kt + 1 < KT) cpa_wait<1>(); else cpa_wait<0>();
        __syncthreads();
        if (kt + 2 < KT) {
            int s2 = st + 2; if (s2 >= 3) s2 -= 3;
            issue(s2, kt + 2);
        }

        uint32_t sA_h = sbase + st * STAGE_B;
        uint32_t sA_l = sA_h + PLANE_B;
        uint32_t sB_h = sA_h + 2 * PLANE_B;
        uint32_t sB_l = sA_h + 3 * PLANE_B;

#pragma unroll
        for (int ks = 0; ks < 2; ks++) {
            const int kkb = ks * 32;   // byte offset of this k16 slice
            uint32_t bh[2][4], bl[2][4];
#pragma unroll
            for (int ntp = 0; ntp < 2; ntp++) {
                int row = wn * 32 + ntp * 16 + b_r;
                uint32_t off = (uint32_t)row * GROWB + GSWZ(row, kkb + b_c * 2);
                ldsm4(bh[ntp][0], bh[ntp][1], bh[ntp][2], bh[ntp][3], sB_h + off);
                ldsm4(bl[ntp][0], bl[ntp][1], bl[ntp][2], bl[ntp][3], sB_l + off);
            }
#pragma unroll
            for (int mt = 0; mt < 4; mt++) {
                int row = wm * 64 + mt * 16 + a_r;
                uint32_t off = (uint32_t)row * GROWB + GSWZ(row, kkb + a_c * 2);
                uint32_t ah[4], al[4];
                ldsm4(ah[0], ah[1], ah[2], ah[3], sA_h + off);
                ldsm4(al[0], al[1], al[2], al[3], sA_l + off);
#pragma unroll
                for (int nt = 0; nt < 4; nt++) {
                    uint32_t bfh[2] = { bh[nt >> 1][(nt & 1) * 2], bh[nt >> 1][(nt & 1) * 2 + 1] };
                    uint32_t bfl[2] = { bl[nt >> 1][(nt & 1) * 2], bl[nt >> 1][(nt & 1) * 2 + 1] };
                    mma16816(acc[mt][nt], ah, bfh);
                    mma16816(acc[mt][nt], ah, bfl);
                    mma16816(acc[mt][nt], al, bfh);
                }
            }
        }
        st++; if (st >= 3) st -= 3;
    }

    const int r = lane >> 2, q = lane & 3;
#pragma unroll
    for (int mt = 0; mt < 4; mt++) {
#pragma unroll
        for (int nt = 0; nt < 4; nt++) {
            int row = m0 + wm * 64 + mt * 16 + r;
            int col = n0 + wn * 32 + nt * 8 + q * 2;
#pragma unroll
            for (int half = 0; half < 2; half++) {
                int rr2 = row + half * 8;
                float v0 = acc[mt][nt][half * 2 + 0];
                float v1 = acc[mt][nt][half * 2 + 1];
                size_t gidx = (size_t)rr2 * ldC + col;
                if (MODE == 1) {
                    v0 += bias[col];
                    v1 += bias[col + 1];
                    v0 = 0.5f * v0 * (1.0f + erff(v0 * 0.70710678118654752f));
                    v1 = 0.5f * v1 * (1.0f + erff(v1 * 0.70710678118654752f));
                    __nv_bfloat16 h0, h1, l0, l1;
                    split1(v0, h0, l0); split1(v1, h1, l1);
                    *(uint32_t*)&Ch[gidx] = pk2(h0, h1);
                    *(uint32_t*)&Cl[gidx] = pk2(l0, l1);
                } else {
                    if (MODE == 2) {
                        float2 rv = *(const float2*)&R[gidx];
                        v0 += bias[col] + rv.x;
                        v1 += bias[col + 1] + rv.y;
                    } else if (MODE == 3) {
                        float2 rv = *(const float2*)&R[gidx];
                        v0 += rv.x;
                        v1 += rv.y;
                    }
                    *(float2*)&C[gidx] = make_float2(v0, v1);
                    if (MODE == 2 && Ch) {
                        __nv_bfloat16 h0, h1, l0, l1;
                        split1(v0, h0, l0); split1(v1, h1, l1);
                        *(uint32_t*)&Ch[gidx] = pk2(h0, h1);
                        *(uint32_t*)&Cl[gidx] = pk2(l0, l1);
                    }
                }
            }
        }
    }
}

// ---------------- RoPE + split to flash planes ----------------
__global__ void rope_split(const float* __restrict__ qkv,
                           uint16_t* __restrict__ fqh, uint16_t* __restrict__ fql,
                           uint16_t* __restrict__ fkh, uint16_t* __restrict__ fkl,
                           uint16_t* __restrict__ fvh, uint16_t* __restrict__ fvl) {
    int row = blockIdx.x, t = threadIdx.x;
    int i = t & 31;
    int s = row & (SS - 1);
    float inv = __expf(-logf(10000.0f) * ((float)i / 32.0f));
    float ang = (float)s * inv;
    float c = cosf(ang), sn = sinf(ang);
    const float* base = qkv + (size_t)row * 1536;
    size_t dst = (size_t)row * DAA + 2 * t;

    float x1 = base[2 * t], x2 = base[2 * t + 1];
    float o1 = x1 * c - x2 * sn, o2 = x1 * sn + x2 * c;
    __nv_bfloat16 h0, h1, l0, l1;
    split1(o1, h0, l0); split1(o2, h1, l1);
    *(uint32_t*)&fqh[dst] = pk2(h0, h1);
    *(uint32_t*)&fql[dst] = pk2(l0, l1);

    x1 = base[512 + 2 * t]; x2 = base[512 + 2 * t + 1];
    o1 = x1 * c - x2 * sn; o2 = x1 * sn + x2 * c;
    split1(o1, h0, l0); split1(o2, h1, l1);
    *(uint32_t*)&fkh[dst] = pk2(h0, h1);
    *(uint32_t*)&fkl[dst] = pk2(l0, l1);

    x1 = base[1024 + 2 * t]; x2 = base[1024 + 2 * t + 1];
    split1(x1, h0, l0); split1(x2, h1, l1);
    *(uint32_t*)&fvh[dst] = pk2(h0, h1);
    *(uint32_t*)&fvl[dst] = pk2(l0, l1);
}

// ---------------- Flash attention, HMMA + poly exp2 ----------------
template<int ICL>
__global__ void __launch_bounds__(256) flash_mma(
    const uint16_t* __restrict__ Qh, const uint16_t* __restrict__ Ql,
    const uint16_t* __restrict__ Kh, const uint16_t* __restrict__ Kl,
    const uint16_t* __restrict__ Vh, const uint16_t* __restrict__ Vl,
    uint16_t* __restrict__ Oh, uint16_t* __restrict__ Ol)
{
    extern __shared__ char sm[];
    const uint32_t sb = (uint32_t)__cvta_generic_to_shared(sm);
    const uint32_t sQh = sb, sQl = sb + FQPL;
    const uint32_t sKV = sb + 2 * FQPL;
    const int tid = threadIdx.x, warp = tid >> 5, lane = tid & 31;
    const int qt = gridDim.x - 1 - blockIdx.x;
    const int bh = blockIdx.y, b = bh >> 3, h = bh & 7;
    const int qg0 = qt * 128;
    const size_t tokb = (size_t)b * SS;
    const int rb = warp * 16;

    const int rl = lane & 7, grp = lane >> 3;
    const int a_r = rl + (grp & 1) * 8;
    const int a_c = (grp >> 1) * 8;
    const int b_r = rl + ((grp >> 1) & 1) * 8;
    const int b_c = (grp & 1) * 8;

#pragma unroll
    for (int i = 0; i < 8; i++) {
        int job = tid + i * 256;
        int pl = job >> 10, r = (job >> 3) & 127, s = job & 7;
        const uint16_t* g = (pl ? Ql : Qh) + (tokb + qg0 + r) * DAA + h * DHH + s * 8;
        cpa16((pl ? sQl : sQh) + r * FROWB + s * 16, g);
    }
    cpa_commit();

    float out[8][4];
#pragma unroll
    for (int i = 0; i < 8; i++)
#pragma unroll
        for (int j = 0; j < 4; j++) out[i][j] = 0.f;
    float mrow[2] = { -1e30f, -1e30f }, lrow[2] = { 0.f, 0.f };

    const int ktmax = (qg0 + 127) >> 6;

    auto issueKV = [&](int st, int kt) {
        uint32_t s0 = sKV + st * FSTG;
        int kg0 = kt * 64;
#pragma unroll
        for (int i = 0; i < 8; i++) {
            int job = tid + i * 256;
            int pl = job >> 9, r = (job >> 3) & 63, s = job & 7;
            const uint16_t* gp = (pl == 0) ? Kh : (pl == 1) ? Kl : (pl == 2) ? Vh : Vl;
            cpa16(s0 + pl * FKPL + r * FROWB + s * 16,
                  gp + (tokb + kg0 + r) * DAA + h * DHH + s * 8);
        }
        cpa_commit();
    };
    issueKV(0, 0);

    const int qrow0 = qg0 + rb + (lane >> 2);

    for (int kt = 0; kt <= ktmax; kt++) {
        int st = kt & 1;
        int kg0 = kt * 64;
        if (kt < ktmax) { issueKV(st ^ 1, kt + 1); cpa_wait<1>(); }
        else            { cpa_wait<0>(); }
        __syncthreads();

        uint32_t sK_h = sKV + st * FSTG;
        uint32_t sK_l = sK_h + FKPL;
        uint32_t sV_h = sK_h + 2 * FKPL;
        uint32_t sV_l = sK_h + 3 * FKPL;

        float sc[8][4];
#pragma unroll
        for (int i = 0; i < 8; i++)
#pragma unroll
            for (int j = 0; j < 4; j++) sc[i][j] = 0.f;
#pragma unroll
        for (int k16 = 0; k16 < 4; k16++) {
            uint32_t qoff = (uint32_t)((rb + a_r) * FROWB + (k16 * 16 + a_c) * 2);
            uint32_t ah[4], al[4];
            ldsm4(ah[0], ah[1], ah[2], ah[3], sQh + qoff);
            ldsm4(al[0], al[1], al[2], al[3], sQl + qoff);
#pragma unroll
            for (int ntp = 0; ntp < 4; ntp++) {
                uint32_t koff = (uint32_t)((ntp * 16 + b_r) * FROWB + (k16 * 16 + b_c) * 2);
                uint32_t kh[4], kl[4];
                ldsm4(kh[0], kh[1], kh[2], kh[3], sK_h + koff);
                ldsm4(kl[0], kl[1], kl[2], kl[3], sK_l + koff);
#pragma unroll
                for (int u = 0; u < 2; u++) {
                    int nt = ntp * 2 + u;
                    uint32_t bfh[2] = { kh[u * 2], kh[u * 2 + 1] };
                    uint32_t bfl[2] = { kl[u * 2], kl[u * 2 + 1] };
                    mma16816(sc[nt], ah, bfh);
                    mma16816(sc[nt], ah, bfl);
                    mma16816(sc[nt], al, bfh);
                }
            }
        }

        const bool boundary = (kg0 + 63 >= qg0);
#pragma unroll
        for (int nt = 0; nt < 8; nt++) {
#pragma unroll
            for (int c = 0; c < 4; c++) {
                float v = sc[nt][c] * SCALE_L2E;
                if (boundary) {
                    int qg = qrow0 + (c >> 1) * 8;
                    int kg = kg0 + nt * 8 + (lane & 3) * 2 + (c & 1);
                    bool allow = ICL ? (kg < qg || (qg | kg) == 0) : (kg <= qg);
                    v = allow ? v : -1e30f;
                }
                sc[nt][c] = v;
            }
        }

#pragma unroll
        for (int ri = 0; ri < 2; ri++) {
            float mx = -1e30f;
#pragma unroll
            for (int nt = 0; nt < 8; nt++)
                mx = fmaxf(mx, fmaxf(sc[nt][ri * 2], sc[nt][ri * 2 + 1]));
            mx = fmaxf(mx, __shfl_xor_sync(0xffffffffu, mx, 1));
            mx = fmaxf(mx, __shfl_xor_sync(0xffffffffu, mx, 2));
            float mn = fmaxf(mrow[ri], mx);
            float corr = exp2p(mrow[ri] - mn);
            mrow[ri] = mn;
            float rs = 0.f;
#pragma unroll
            for (int nt = 0; nt < 8; nt++) {
                float p0 = exp2p(sc[nt][ri * 2] - mn);
                float p1 = exp2p(sc[nt][ri * 2 + 1] - mn);
                sc[nt][ri * 2] = p0;
                sc[nt][ri * 2 + 1] = p1;
                rs += p0 + p1;
            }
            rs += __shfl_xor_sync(0xffffffffu, rs, 1);
            rs += __shfl_xor_sync(0xffffffffu, rs, 2);
            lrow[ri] = lrow[ri] * corr + rs;
#pragma unroll
            for (int nt = 0; nt < 8; nt++) {
                out[nt][ri * 2] *= corr;
                out[nt][ri * 2 + 1] *= corr;
            }
        }

#pragma unroll
        for (int j = 0; j < 4; j++) {
            uint32_t aP[4];
            aP[0] = pk2(__float2bfloat16(sc[2 * j][0]),     __float2bfloat16(sc[2 * j][1]));
            aP[1] = pk2(__float2bfloat16(sc[2 * j][2]),     __float2bfloat16(sc[2 * j][3]));
            aP[2] = pk2(__float2bfloat16(sc[2 * j + 1][0]), __float2bfloat16(sc[2 * j + 1][1]));
            aP[3] = pk2(__float2bfloat16(sc[2 * j + 1][2]), __float2bfloat16(sc[2 * j + 1][3]));
#pragma unroll
            for (int nt2 = 0; nt2 < 4; nt2++) {
                uint32_t voff = (uint32_t)((j * 16 + (grp & 1) * 8 + rl) * FROWB
                                           + (nt2 * 16 + (grp >> 1) * 8) * 2);
                uint32_t bv[4];
                ldsm4t(bv[0], bv[1], bv[2], bv[3], sV_h + voff);
                {
                    uint32_t b0[2] = { bv[0], bv[1] }, b1[2] = { bv[2], bv[3] };
                    mma16816(out[nt2 * 2], aP, b0);
                    mma16816(out[nt2 * 2 + 1], aP, b1);
                }
                ldsm4t(bv[0], bv[1], bv[2], bv[3], sV_l + voff);
                {
                    uint32_t b0[2] = { bv[0], bv[1] }, b1[2] = { bv[2], bv[3] };
                    mma16816(out[nt2 * 2], aP, b0);
                    mma16816(out[nt2 * 2 + 1], aP, b1);
                }
            }
        }
        __syncthreads();
    }

#pragma unroll
    for (int ri = 0; ri < 2; ri++) {
        float inv = 1.0f / lrow[ri];
        size_t rbase = (tokb + qrow0 + ri * 8) * DAA + h * DHH + (lane & 3) * 2;
#pragma unroll
        for (int nt = 0; nt < 8; nt++) {
            float v0 = out[nt][ri * 2] * inv;
            float v1 = out[nt][ri * 2 + 1] * inv;
            __nv_bfloat16 h0, h1, l0, l1;
            split1(v0, h0, l0); split1(v1, h1, l1);
            *(uint32_t*)&Oh[rbase + nt * 8] = pk2(h0, h1);
            *(uint32_t*)&Ol[rbase + nt * 8] = pk2(l0, l1);
        }
    }
}

// ---------------- host driver ----------------
#define GETSYM(T, var, sym) T* var; { void* _p; cudaGetSymbolAddress(&_p, sym); var = (T*)_p; }

extern "C" void kernel_launch(void* const* d_in, const int* in_sizes, int n_in,
                              void* d_out, int out_size)
{
    const float* cov_in  = (const float*)d_in[0];
    const float* tgt_in  = (const float*)d_in[1];
    const float* fu_in   = (const float*)d_in[2];
    const float* fc1w    = (const float*)d_in[3];
    const float* fc1b    = (const float*)d_in[4];
    const float* fc2w    = (const float*)d_in[5];
    const float* fc2b    = (const float*)d_in[6];
    const float* icl_wq  = (const float*)d_in[7];
    const float* icl_wk  = (const float*)d_in[8];
    const float* icl_wv  = (const float*)d_in[9];
    const float* icl_wo  = (const float*)d_in[10];
    const float* cov_wq  = (const float*)d_in[11];
    const float* cov_wk  = (const float*)d_in[12];
    const float* cov_wv  = (const float*)d_in[13];
    const float* cov_wo  = (const float*)d_in[14];
    const float* ln_cm_g = (const float*)d_in[15];
    const float* ln_cm_b = (const float*)d_in[16];
    const float* ln_ia_g = (const float*)d_in[17];
    const float* ln_ia_b = (const float*)d_in[18];
    const float* ln_im_g = (const float*)d_in[19];
    const float* ln_im_b = (const float*)d_in[20];

    float* out_cov = (float*)d_out;
    float* out_tgt = out_cov + (size_t)NTOK * EE;
    float* out_fu  = out_tgt + (size_t)NTOK * EE;

    GETSYM(float, qkvI, g_qkvI)    GETSYM(float, qkvC, g_qkvC)
    GETSYM(uint16_t, lnh, pLNh)    GETSYM(uint16_t, lnl, pLNl)
    GETSYM(uint16_t, ln2h, pLN2h)  GETSYM(uint16_t, ln2l, pLN2l)
    GETSYM(uint16_t, midh, pMIDh)  GETSYM(uint16_t, midl, pMIDl)
    GETSYM(uint16_t, mid2h, pMID2h) GETSYM(uint16_t, mid2l, pMID2l)
    GETSYM(uint16_t, qh, pQh)      GETSYM(uint16_t, ql, pQl)
    GETSYM(uint16_t, tgh, pTGTh)   GETSYM(uint16_t, tgl, pTGTl)
    GETSYM(uint16_t, aoIh, pAOIh)  GETSYM(uint16_t, aoIl, pAOIl)
    GETSYM(uint16_t, aoCh, pAOCh)  GETSYM(uint16_t, aoCl, pAOCl)
    GETSYM(uint16_t, fqIh, pFQIh)  GETSYM(uint16_t, fqIl, pFQIl)
    GETSYM(uint16_t, fkIh, pFKIh)  GETSYM(uint16_t, fkIl, pFKIl)
    GETSYM(uint16_t, fvIh, pFVIh)  GETSYM(uint16_t, fvIl, pFVIl)
    GETSYM(uint16_t, fqCh, pFQCh)  GETSYM(uint16_t, fqCl, pFQCl)
    GETSYM(uint16_t, fkCh, pFKCh)  GETSYM(uint16_t, fkCl, pFKCl)
    GETSYM(uint16_t, fvCh, pFVCh)  GETSYM(uint16_t, fvCl, pFVCl)
    GETSYM(uint16_t, w1h, pW1h)    GETSYM(uint16_t, w1l, pW1l)
    GETSYM(uint16_t, w2h, pW2h)    GETSYM(uint16_t, w2l, pW2l)
    GETSYM(uint16_t, iqkh, pIQKh)  GETSYM(uint16_t, iqkl, pIQKl)
    GETSYM(uint16_t, ivh, pIVh)    GETSYM(uint16_t, ivl, pIVl)
    GETSYM(uint16_t, ioh, pIOh)    GETSYM(uint16_t, iol, pIOl)
    GETSYM(uint16_t, cqkvh, pCQKVh) GETSYM(uint16_t, cqkvl, pCQKVl)
    GETSYM(uint16_t, coh, pCOh)    GETSYM(uint16_t, col, pCOl)

    static cudaStream_t s2 = nullptr;
    static cudaEvent_t ev0 = nullptr, evq = nullptr, evend = nullptr;
    if (!s2) {
        cudaStreamCreateWithFlags(&s2, cudaStreamNonBlocking);
        cudaEventCreateWithFlags(&ev0, cudaEventDisableTiming);
        cudaEventCreateWithFlags(&evq, cudaEventDisableTiming);
        cudaEventCreateWithFlags(&evend, cudaEventDisableTiming);
        cudaFuncSetAttribute(gemm_tc<0>, cudaFuncAttributeMaxDynamicSharedMemorySize, SMEM_GEMM);
        cudaFuncSetAttribute(gemm_tc<1>, cudaFuncAttributeMaxDynamicSharedMemorySize, SMEM_GEMM);
        cudaFuncSetAttribute(gemm_tc<2>, cudaFuncAttributeMaxDynamicSharedMemorySize, SMEM_GEMM);
        cudaFuncSetAttribute(gemm_tc<3>, cudaFuncAttributeMaxDynamicSharedMemorySize, SMEM_GEMM);
        cudaFuncSetAttribute(flash_mma<0>, cudaFuncAttributeMaxDynamicSharedMemorySize, SMEM_FLASH);
        cudaFuncSetAttribute(flash_mma<1>, cudaFuncAttributeMaxDynamicSharedMemorySize, SMEM_FLASH);
    }

    const dim3 thr(256);
    const dim3 gFC1(DMLP / 128, NTOK / 128);
    const dim3 gFC2(EE / 128, NTOK / 128);
    const dim3 gQK(8, NTOK / 128);
    const dim3 gV(4, NTOK / 128);
    const dim3 gQKV(12, NTOK / 128);
    const dim3 gWO(EE / 128, NTOK / 128);
    const dim3 gFLASH(SS / 128, BB * HH);

    // ---- all weight conversions, one launch ----
    ConvJobs cj;
    cj.src[0] = fc1w;   cj.dh[0] = w1h;              cj.dl[0] = w1l;              cj.K[0] = EE;   cj.N[0] = DMLP;
    cj.src[1] = fc2w;   cj.dh[1] = w2h;              cj.dl[1] = w2l;              cj.K[1] = DMLP; cj.N[1] = EE;
    cj.src[2] = icl_wq; cj.dh[2] = iqkh;             cj.dl[2] = iqkl;             cj.K[2] = EE;   cj.N[2] = DAA;
    cj.src[3] = icl_wk; cj.dh[3] = iqkh + 512 * EE;  cj.dl[3] = iqkl + 512 * EE;  cj.K[3] = EE;   cj.N[3] = DAA;
    cj.src[4] = icl_wv; cj.dh[4] = ivh;              cj.dl[4] = ivl;              cj.K[4] = EE;   cj.N[4] = DAA;
    cj.src[5] = cov_wq; cj.dh[5] = cqkvh;            cj.dl[5] = cqkvl;            cj.K[5] = EE;   cj.N[5] = DAA;
    cj.src[6] = cov_wk; cj.dh[6] = cqkvh + 512 * EE; cj.dl[6] = cqkvl + 512 * EE; cj.K[6] = EE;   cj.N[6] = DAA;
    cj.src[7] = cov_wv; cj.dh[7] = cqkvh + 1024 * EE;cj.dl[7] = cqkvl + 1024 * EE;cj.K[7] = EE;   cj.N[7] = DAA;
    cj.src[8] = icl_wo; cj.dh[8] = ioh;              cj.dl[8] = iol;              cj.K[8] = DAA;  cj.N[8] = EE;
    cj.src[9] = cov_wo; cj.dh[9] = coh;              cj.dl[9] = col;              cj.K[9] = DAA;  cj.N[9] = EE;
    conv_all<<<dim3(16, 32, 10), thr>>>(cj);
    cudaEventRecord(ev0, 0);
    cudaStreamWaitEvent(s2, ev0, 0);

    // ---- chain2 on s2: tgt = targets + MLP(LN(functional_update)) ----
    ln_split<<<NTOK, thr, 0, s2>>>(fu_in, ln_im_g, ln_im_b, ln2h, ln2l);
    gemm_tc<1><<<gFC1, thr, SMEM_GEMM, s2>>>(ln2h, ln2l, w1h, w1l, fc1b, nullptr,
                                             nullptr, mid2h, mid2l, DMLP, EE, DMLP);
    gemm_tc<2><<<gFC2, thr, SMEM_GEMM, s2>>>(mid2h, mid2l, w2h, w2l, fc2b, tgt_in,
                                             out_tgt, tgh, tgl, EE, DMLP, EE);
    // V-projection depends only on tgt — run before waiting for q
    gemm_tc<0><<<gV, thr, SMEM_GEMM, s2>>>(tgh, tgl, ivh, ivl, nullptr, nullptr,
                                           qkvI + 1024, nullptr, nullptr, DAA, EE, 1536);

    // ---- chain1 on legacy: cov = covariates + MLP(LN(covariates)); q = LN(cov) ----
    ln_split<<<NTOK, thr>>>(cov_in, ln_cm_g, ln_cm_b, lnh, lnl);
    gemm_tc<1><<<gFC1, thr, SMEM_GEMM>>>(lnh, lnl, w1h, w1l, fc1b, nullptr,
                                         nullptr, midh, midl, DMLP, EE, DMLP);
    gemm_tc<2><<<gFC2, thr, SMEM_GEMM>>>(midh, midl, w2h, w2l, fc2b, cov_in,
                                         out_cov, nullptr, nullptr, EE, DMLP, EE);
    ln_split<<<NTOK, thr>>>(out_cov, ln_ia_g, ln_ia_b, qh, ql);
    cudaEventRecord(evq, 0);

    // ---- ICL attention on s2 (needs q + tgt) ----
    cudaStreamWaitEvent(s2, evq, 0);
    gemm_tc<0><<<gQK, thr, SMEM_GEMM, s2>>>(qh, ql, iqkh, iqkl, nullptr, nullptr,
                                            qkvI, nullptr, nullptr, 1024, EE, 1536);
    rope_split<<<NTOK, thr, 0, s2>>>(qkvI, fqIh, fqIl, fkIh, fkIl, fvIh, fvIl);
    flash_mma<1><<<gFLASH, thr, SMEM_FLASH, s2>>>(fqIh, fqIl, fkIh, fkIl, fvIh, fvIl, aoIh, aoIl);
    gemm_tc<3><<<gWO, thr, SMEM_GEMM, s2>>>(aoIh, aoIl, ioh, iol, nullptr, fu_in,
                                            out_fu, nullptr, nullptr, EE, DAA, EE);
    cudaEventRecord(evend, s2);

    // ---- COV attention on legacy (needs only q) ----
    gemm_tc<0><<<gQKV, thr, SMEM_GEMM>>>(qh, ql, cqkvh, cqkvl, nullptr, nullptr,
                                         qkvC, nullptr, nullptr, 1536, EE, 1536);
    rope_split<<<NTOK, thr>>>(qkvC, fqCh, fqCl, fkCh, fkCl, fvCh, fvCl);
    flash_mma<0><<<gFLASH, thr, SMEM_FLASH>>>(fqCh, fqCl, fkCh, fkCl, fvCh, fvCl, aoCh, aoCl);
    gemm_tc<3><<<gWO, thr, SMEM_GEMM>>>(aoCh, aoCl, coh, col, nullptr, out_cov,
                                        out_cov, nullptr, nullptr, EE, DAA, EE);

    // join
    cudaStreamWaitEvent(0, evend, 0);
}

// round 10
// speedup vs baseline: 1.0465x; 1.0465x over previous
#include <cuda_runtime.h>
#include <cuda_bf16.h>
#include <math.h>
#include <stdint.h>

#define BB 2
#define SS 2048
#define EE 1024
#define HH 8
#define DHH 64
#define DAA 512
#define DMLP 2048
#define NTOK 4096
#define SCALE_ATTN 0.04419417382415922f
#define SCALE_L2E 0.06375944628228341f   // SCALE_ATTN * log2(e)
#define LN_EPS 1e-5f

// GEMM: 128x128 CTA tile, warp 64x32, K-chunk 32.
// Swizzled 64B rows (no pad): addr = row*64 + (off ^ ((row&6)<<3)) -> conflict-free ldmatrix.
// Stage = 32KB; 3 stages = 96KB; 2 CTAs/SM = 192KB <= 228KB. launch_bounds forces regs<=128.
#define GROWB 64
#define PLANE_B 8192
#define STAGE_B 32768
#define SMEM_GEMM (3 * STAGE_B)
#define GSWZ(row, off) ((uint32_t)(off) ^ (((uint32_t)(row) & 6u) << 3))

#define FROWB 144
#define FQPL 18432
#define FKPL 9216
#define FSTG 36864
#define SMEM_FLASH (2 * FQPL + 2 * FSTG)

// ---------------- scratch ----------------
__device__ float g_qkvI[NTOK * 1536];
__device__ float g_qkvC[NTOK * 1536];

__device__ uint16_t pLNh[NTOK * EE],     pLNl[NTOK * EE];
__device__ uint16_t pLN2h[NTOK * EE],    pLN2l[NTOK * EE];
__device__ uint16_t pMIDh[NTOK * DMLP],  pMIDl[NTOK * DMLP];
__device__ uint16_t pMID2h[NTOK * DMLP], pMID2l[NTOK * DMLP];
__device__ uint16_t pQh[NTOK * EE],      pQl[NTOK * EE];
__device__ uint16_t pTGTh[NTOK * EE],    pTGTl[NTOK * EE];
__device__ uint16_t pAOIh[NTOK * DAA],   pAOIl[NTOK * DAA];
__device__ uint16_t pAOCh[NTOK * DAA],   pAOCl[NTOK * DAA];
__device__ uint16_t pFQIh[NTOK * DAA],   pFQIl[NTOK * DAA];
__device__ uint16_t pFKIh[NTOK * DAA],   pFKIl[NTOK * DAA];
__device__ uint16_t pFVIh[NTOK * DAA],   pFVIl[NTOK * DAA];
__device__ uint16_t pFQCh[NTOK * DAA],   pFQCl[NTOK * DAA];
__device__ uint16_t pFKCh[NTOK * DAA],   pFKCl[NTOK * DAA];
__device__ uint16_t pFVCh[NTOK * DAA],   pFVCl[NTOK * DAA];

__device__ uint16_t pW1h[DMLP * EE],    pW1l[DMLP * EE];
__device__ uint16_t pW2h[EE * DMLP],    pW2l[EE * DMLP];
__device__ uint16_t pIQKh[1024 * EE],   pIQKl[1024 * EE];
__device__ uint16_t pIVh[DAA * EE],     pIVl[DAA * EE];
__device__ uint16_t pIOh[EE * DAA],     pIOl[EE * DAA];
__device__ uint16_t pCQKVh[1536 * EE],  pCQKVl[1536 * EE];
__device__ uint16_t pCOh[EE * DAA],     pCOl[EE * DAA];

// ---------------- helpers ----------------
__device__ __forceinline__ uint32_t pk2(__nv_bfloat16 a, __nv_bfloat16 b) {
    uint16_t ra = *reinterpret_cast<uint16_t*>(&a);
    uint16_t rb = *reinterpret_cast<uint16_t*>(&b);
    return (uint32_t)ra | ((uint32_t)rb << 16);
}
__device__ __forceinline__ void split1(float x, __nv_bfloat16& h, __nv_bfloat16& l) {
    h = __float2bfloat16(x);
    l = __float2bfloat16(x - __bfloat162float(h));
}
__device__ __forceinline__ void mma16816(float* c, const uint32_t* a, const uint32_t* b) {
    asm volatile(
        "mma.sync.aligned.m16n8k16.row.col.f32.bf16.bf16.f32 "
        "{%0,%1,%2,%3}, {%4,%5,%6,%7}, {%8,%9}, {%0,%1,%2,%3};"
        : "+f"(c[0]), "+f"(c[1]), "+f"(c[2]), "+f"(c[3])
        : "r"(a[0]), "r"(a[1]), "r"(a[2]), "r"(a[3]), "r"(b[0]), "r"(b[1]));
}
__device__ __forceinline__ void ldsm4(uint32_t& r0, uint32_t& r1, uint32_t& r2, uint32_t& r3,
                                      uint32_t addr) {
    asm volatile("ldmatrix.sync.aligned.m8n8.x4.shared.b16 {%0,%1,%2,%3}, [%4];"
                 : "=r"(r0), "=r"(r1), "=r"(r2), "=r"(r3) : "r"(addr));
}
__device__ __forceinline__ void ldsm4t(uint32_t& r0, uint32_t& r1, uint32_t& r2, uint32_t& r3,
                                       uint32_t addr) {
    asm volatile("ldmatrix.sync.aligned.m8n8.x4.trans.shared.b16 {%0,%1,%2,%3}, [%4];"
                 : "=r"(r0), "=r"(r1), "=r"(r2), "=r"(r3) : "r"(addr));
}
__device__ __forceinline__ void cpa16(uint32_t s, const void* g) {
    asm volatile("cp.async.ca.shared.global [%0], [%1], 16;" :: "r"(s), "l"(g));
}
__device__ __forceinline__ void cpa_commit() {
    asm volatile("cp.async.commit_group;" ::: "memory");
}
template<int N>
__device__ __forceinline__ void cpa_wait() {
    asm volatile("cp.async.wait_group %0;" :: "n"(N) : "memory");
}
__device__ __forceinline__ float exp2p(float x) {
    x = fmaxf(x, -80.f);
    float n = rintf(x);
    float f = x - n;
    float p = 1.3333558146428443e-3f;
    p = p * f + 9.618129107628477e-3f;
    p = p * f + 5.550410866482158e-2f;
    p = p * f + 2.402265069591007e-1f;
    p = p * f + 6.931471805599453e-1f;
    p = p * f + 1.0f;
    return p * __int_as_float(((int)n + 127) << 23);
}

__device__ __forceinline__ float block_reduce_sum(float v) {
    __shared__ float red[32];
    int lane = threadIdx.x & 31, w = threadIdx.x >> 5;
#pragma unroll
    for (int o = 16; o > 0; o >>= 1) v += __shfl_xor_sync(0xffffffffu, v, o);
    __syncthreads();
    if (lane == 0) red[w] = v;
    __syncthreads();
    v = (lane < 8) ? red[lane] : 0.f;
#pragma unroll
    for (int o = 16; o > 0; o >>= 1) v += __shfl_xor_sync(0xffffffffu, v, o);
    return v;
}

// ---------------- LayerNorm -> bf16 hi/lo planes ----------------
__global__ void ln_split(const float* __restrict__ x, const float* __restrict__ g,
                         const float* __restrict__ b,
                         uint16_t* __restrict__ oh, uint16_t* __restrict__ ol) {
    int row = blockIdx.x, t = threadIdx.x;
    float4 v = *(const float4*)&x[(size_t)row * EE + 4 * t];
    float s = v.x + v.y + v.z + v.w;
    float mean = block_reduce_sum(s) * (1.0f / EE);
    float d0 = v.x - mean, d1 = v.y - mean, d2 = v.z - mean, d3 = v.w - mean;
    float var = block_reduce_sum(d0 * d0 + d1 * d1 + d2 * d2 + d3 * d3) * (1.0f / EE);
    float rstd = rsqrtf(var + LN_EPS);
    float4 gg = *(const float4*)&g[4 * t];
    float4 bb = *(const float4*)&b[4 * t];
    float y0 = d0 * rstd * gg.x + bb.x;
    float y1 = d1 * rstd * gg.y + bb.y;
    float y2 = d2 * rstd * gg.z + bb.z;
    float y3 = d3 * rstd * gg.w + bb.w;
    __nv_bfloat16 h0, h1, h2, h3, l0, l1, l2, l3;
    split1(y0, h0, l0); split1(y1, h1, l1); split1(y2, h2, l2); split1(y3, h3, l3);
    size_t off = (size_t)row * EE + 4 * t;
    *(uint2*)&oh[off] = make_uint2(pk2(h0, h1), pk2(h2, h3));
    *(uint2*)&ol[off] = make_uint2(pk2(l0, l1), pk2(l2, l3));
}

// ---------------- weight conversion, single launch ----------------
__device__ __forceinline__ void convB_body(const float* __restrict__ W,
                                           uint16_t* __restrict__ Bh,
                                           uint16_t* __restrict__ Bl, int K, int N) {
    __shared__ float ts[64][129];
    int nt = blockIdx.x, kt = blockIdx.y, tid = threadIdx.x;
    int k0 = kt * 64, n0 = nt * 128;
#pragma unroll
    for (int i = 0; i < 32; i++) {
        int idx = tid + i * 256;
        int kk = idx >> 7, nn = idx & 127;
        ts[kk][nn] = W[(size_t)(k0 + kk) * N + n0 + nn];
    }
    __syncthreads();
#pragma unroll
    for (int j = 0; j < 4; j++) {
        int job = tid + j * 256;
        int n = job >> 3, kg = (job & 7) * 8;
        __nv_bfloat16 h[8], l[8];
#pragma unroll
        for (int i = 0; i < 8; i++) split1(ts[kg + i][n], h[i], l[i]);
        uint4 uh = make_uint4(pk2(h[0], h[1]), pk2(h[2], h[3]), pk2(h[4], h[5]), pk2(h[6], h[7]));
        uint4 ul = make_uint4(pk2(l[0], l[1]), pk2(l[2], l[3]), pk2(l[4], l[5]), pk2(l[6], l[7]));
        size_t off = (size_t)(n0 + n) * K + k0 + kg;
        *(uint4*)&Bh[off] = uh;
        *(uint4*)&Bl[off] = ul;
    }
}

struct ConvJobs {
    const float* src[10];
    uint16_t* dh[10];
    uint16_t* dl[10];
    int K[10], N[10];
};
__global__ void conv_all(ConvJobs j) {
    int w = blockIdx.z;
    int K = j.K[w], N = j.N[w];
    if (blockIdx.x * 128 >= N || blockIdx.y * 64 >= K) return;
    convB_body(j.src[w], j.dh[w], j.dl[w], K, N);
}

// ---------------- HMMA bf16-split GEMM: 128x128, warp 64x32, 3-stage, 1 sync/chunk ----------------
// launch_bounds(256,2): force regs<=128 so 2 CTAs/SM stay resident.
// MODE 0: C=AB(fp32, ldC)  1: planes=gelu(AB+bias)  2: C=AB+bias+R (+planes)  3: C=AB+R
template<int MODE>
__global__ void __launch_bounds__(256, 2) gemm_tc(
    const uint16_t* __restrict__ Ah, const uint16_t* __restrict__ Al,
    const uint16_t* __restrict__ Bh, const uint16_t* __restrict__ Bl,
    const float* __restrict__ bias, const float* __restrict__ R,
    float* __restrict__ C, uint16_t* __restrict__ Ch, uint16_t* __restrict__ Cl,
    int N, int K, int ldC)
{
    extern __shared__ char sm[];
    const uint32_t sbase = (uint32_t)__cvta_generic_to_shared(sm);
    const int tid = threadIdx.x;
    const int warp = tid >> 5, lane = tid & 31;
    const int wm = warp & 1, wn = warp >> 1;
    const int m0 = blockIdx.y * 128, n0 = blockIdx.x * 128;
    const int KT = K >> 5;

    const uint16_t* gA[2] = { Ah + (size_t)m0 * K, Al + (size_t)m0 * K };
    const uint16_t* gB[2] = { Bh + (size_t)n0 * K, Bl + (size_t)n0 * K };

    const int rl = lane & 7, grp = lane >> 3;
    const int a_r = rl + (grp & 1) * 8;
    const int a_c = (grp >> 1) * 8;
    const int b_r = rl + ((grp >> 1) & 1) * 8;
    const int b_c = (grp & 1) * 8;

    float acc[4][4][4];
#pragma unroll
    for (int i = 0; i < 4; i++)
#pragma unroll
        for (int j = 0; j < 4; j++)
#pragma unroll
            for (int k = 0; k < 4; k++) acc[i][j][k] = 0.f;

    auto issue = [&](int stage, int kt) {
        uint32_t s0 = sbase + stage * STAGE_B;
        int kel = kt * 32;
#pragma unroll
        for (int pl = 0; pl < 4; pl++) {
            const uint16_t* g = (pl < 2) ? gA[pl] : gB[pl - 2];
#pragma unroll
            for (int i = 0; i < 2; i++) {
                int seg = tid + i * 256;
                int m = seg >> 2, s = seg & 3;
                cpa16(s0 + pl * PLANE_B + m * GROWB + GSWZ(m, s * 16),
                      g + (size_t)m * K + kel + s * 8);
            }
        }
        cpa_commit();
    };

    issue(0, 0);
    if (KT > 1) issue(1, 1);

    int st = 0;
    for (int kt = 0; kt < KT; kt++) {
        if (kt + 1 < KT) cpa_wait<1>(); else cpa_wait<0>();
        __syncthreads();
        if (kt + 2 < KT) {
            int s2 = st + 2; if (s2 >= 3) s2 -= 3;
            issue(s2, kt + 2);
        }

        uint32_t sA_h = sbase + st * STAGE_B;
        uint32_t sA_l = sA_h + PLANE_B;
        uint32_t sB_h = sA_h + 2 * PLANE_B;
        uint32_t sB_l = sA_h + 3 * PLANE_B;

#pragma unroll
        for (int ks = 0; ks < 2; ks++) {
            const int kkb = ks * 32;
            uint32_t bh[2][4], bl[2][4];
#pragma unroll
            for (int ntp = 0; ntp < 2; ntp++) {
                int row = wn * 32 + ntp * 16 + b_r;
                uint32_t off = (uint32_t)row * GROWB + GSWZ(row, kkb + b_c * 2);
                ldsm4(bh[ntp][0], bh[ntp][1], bh[ntp][2], bh[ntp][3], sB_h + off);
                ldsm4(bl[ntp][0], bl[ntp][1], bl[ntp][2], bl[ntp][3], sB_l + off);
            }
#pragma unroll
            for (int mt = 0; mt < 4; mt++) {
                int row = wm * 64 + mt * 16 + a_r;
                uint32_t off = (uint32_t)row * GROWB + GSWZ(row, kkb + a_c * 2);
                uint32_t ah[4], al[4];
                ldsm4(ah[0], ah[1], ah[2], ah[3], sA_h + off);
                ldsm4(al[0], al[1], al[2], al[3], sA_l + off);
#pragma unroll
                for (int nt = 0; nt < 4; nt++) {
                    uint32_t bfh[2] = { bh[nt >> 1][(nt & 1) * 2], bh[nt >> 1][(nt & 1) * 2 + 1] };
                    uint32_t bfl[2] = { bl[nt >> 1][(nt & 1) * 2], bl[nt >> 1][(nt & 1) * 2 + 1] };
                    mma16816(acc[mt][nt], ah, bfh);
                    mma16816(acc[mt][nt], ah, bfl);
                    mma16816(acc[mt][nt], al, bfh);
                }
            }
        }
        st++; if (st >= 3) st -= 3;
    }

    const int r = lane >> 2, q = lane & 3;
#pragma unroll
    for (int mt = 0; mt < 4; mt++) {
#pragma unroll
        for (int nt = 0; nt < 4; nt++) {
            int row = m0 + wm * 64 + mt * 16 + r;
            int col = n0 + wn * 32 + nt * 8 + q * 2;
#pragma unroll
            for (int half = 0; half < 2; half++) {
                int rr2 = row + half * 8;
                float v0 = acc[mt][nt][half * 2 + 0];
                float v1 = acc[mt][nt][half * 2 + 1];
                size_t gidx = (size_t)rr2 * ldC + col;
                if (MODE == 1) {
                    v0 += bias[col];
                    v1 += bias[col + 1];
                    v0 = 0.5f * v0 * (1.0f + erff(v0 * 0.70710678118654752f));
                    v1 = 0.5f * v1 * (1.0f + erff(v1 * 0.70710678118654752f));
                    __nv_bfloat16 h0, h1, l0, l1;
                    split1(v0, h0, l0); split1(v1, h1, l1);
                    *(uint32_t*)&Ch[gidx] = pk2(h0, h1);
                    *(uint32_t*)&Cl[gidx] = pk2(l0, l1);
                } else {
                    if (MODE == 2) {
                        float2 rv = *(const float2*)&R[gidx];
                        v0 += bias[col] + rv.x;
                        v1 += bias[col + 1] + rv.y;
                    } else if (MODE == 3) {
                        float2 rv = *(const float2*)&R[gidx];
                        v0 += rv.x;
                        v1 += rv.y;
                    }
                    *(float2*)&C[gidx] = make_float2(v0, v1);
                    if (MODE == 2 && Ch) {
                        __nv_bfloat16 h0, h1, l0, l1;
                        split1(v0, h0, l0); split1(v1, h1, l1);
                        *(uint32_t*)&Ch[gidx] = pk2(h0, h1);
                        *(uint32_t*)&Cl[gidx] = pk2(l0, l1);
                    }
                }
            }
        }
    }
}

// ---------------- RoPE + split to flash planes ----------------
__global__ void rope_split(const float* __restrict__ qkv,
                           uint16_t* __restrict__ fqh, uint16_t* __restrict__ fql,
                           uint16_t* __restrict__ fkh, uint16_t* __restrict__ fkl,
                           uint16_t* __restrict__ fvh, uint16_t* __restrict__ fvl) {
    int row = blockIdx.x, t = threadIdx.x;
    int i = t & 31;
    int s = row & (SS - 1);
    float inv = __expf(-logf(10000.0f) * ((float)i / 32.0f));
    float ang = (float)s * inv;
    float c = cosf(ang), sn = sinf(ang);
    const float* base = qkv + (size_t)row * 1536;
    size_t dst = (size_t)row * DAA + 2 * t;

    float x1 = base[2 * t], x2 = base[2 * t + 1];
    float o1 = x1 * c - x2 * sn, o2 = x1 * sn + x2 * c;
    __nv_bfloat16 h0, h1, l0, l1;
    split1(o1, h0, l0); split1(o2, h1, l1);
    *(uint32_t*)&fqh[dst] = pk2(h0, h1);
    *(uint32_t*)&fql[dst] = pk2(l0, l1);

    x1 = base[512 + 2 * t]; x2 = base[512 + 2 * t + 1];
    o1 = x1 * c - x2 * sn; o2 = x1 * sn + x2 * c;
    split1(o1, h0, l0); split1(o2, h1, l1);
    *(uint32_t*)&fkh[dst] = pk2(h0, h1);
    *(uint32_t*)&fkl[dst] = pk2(l0, l1);

    x1 = base[1024 + 2 * t]; x2 = base[1024 + 2 * t + 1];
    split1(x1, h0, l0); split1(x2, h1, l1);
    *(uint32_t*)&fvh[dst] = pk2(h0, h1);
    *(uint32_t*)&fvl[dst] = pk2(l0, l1);
}

// ---------------- Flash attention, HMMA + poly exp2 ----------------
template<int ICL>
__global__ void __launch_bounds__(256) flash_mma(
    const uint16_t* __restrict__ Qh, const uint16_t* __restrict__ Ql,
    const uint16_t* __restrict__ Kh, const uint16_t* __restrict__ Kl,
    const uint16_t* __restrict__ Vh, const uint16_t* __restrict__ Vl,
    uint16_t* __restrict__ Oh, uint16_t* __restrict__ Ol)
{
    extern __shared__ char sm[];
    const uint32_t sb = (uint32_t)__cvta_generic_to_shared(sm);
    const uint32_t sQh = sb, sQl = sb + FQPL;
    const uint32_t sKV = sb + 2 * FQPL;
    const int tid = threadIdx.x, warp = tid >> 5, lane = tid & 31;
    const int qt = gridDim.x - 1 - blockIdx.x;
    const int bh = blockIdx.y, b = bh >> 3, h = bh & 7;
    const int qg0 = qt * 128;
    const size_t tokb = (size_t)b * SS;
    const int rb = warp * 16;

    const int rl = lane & 7, grp = lane >> 3;
    const int a_r = rl + (grp & 1) * 8;
    const int a_c = (grp >> 1) * 8;
    const int b_r = rl + ((grp >> 1) & 1) * 8;
    const int b_c = (grp & 1) * 8;

#pragma unroll
    for (int i = 0; i < 8; i++) {
        int job = tid + i * 256;
        int pl = job >> 10, r = (job >> 3) & 127, s = job & 7;
        const uint16_t* g = (pl ? Ql : Qh) + (tokb + qg0 + r) * DAA + h * DHH + s * 8;
        cpa16((pl ? sQl : sQh) + r * FROWB + s * 16, g);
    }
    cpa_commit();

    float out[8][4];
#pragma unroll
    for (int i = 0; i < 8; i++)
#pragma unroll
        for (int j = 0; j < 4; j++) out[i][j] = 0.f;
    float mrow[2] = { -1e30f, -1e30f }, lrow[2] = { 0.f, 0.f };

    const int ktmax = (qg0 + 127) >> 6;

    auto issueKV = [&](int st, int kt) {
        uint32_t s0 = sKV + st * FSTG;
        int kg0 = kt * 64;
#pragma unroll
        for (int i = 0; i < 8; i++) {
            int job = tid + i * 256;
            int pl = job >> 9, r = (job >> 3) & 63, s = job & 7;
            const uint16_t* gp = (pl == 0) ? Kh : (pl == 1) ? Kl : (pl == 2) ? Vh : Vl;
            cpa16(s0 + pl * FKPL + r * FROWB + s * 16,
                  gp + (tokb + kg0 + r) * DAA + h * DHH + s * 8);
        }
        cpa_commit();
    };
    issueKV(0, 0);

    const int qrow0 = qg0 + rb + (lane >> 2);

    for (int kt = 0; kt <= ktmax; kt++) {
        int st = kt & 1;
        int kg0 = kt * 64;
        if (kt < ktmax) { issueKV(st ^ 1, kt + 1); cpa_wait<1>(); }
        else            { cpa_wait<0>(); }
        __syncthreads();

        uint32_t sK_h = sKV + st * FSTG;
        uint32_t sK_l = sK_h + FKPL;
        uint32_t sV_h = sK_h + 2 * FKPL;
        uint32_t sV_l = sK_h + 3 * FKPL;

        float sc[8][4];
#pragma unroll
        for (int i = 0; i < 8; i++)
#pragma unroll
            for (int j = 0; j < 4; j++) sc[i][j] = 0.f;
#pragma unroll
        for (int k16 = 0; k16 < 4; k16++) {
            uint32_t qoff = (uint32_t)((rb + a_r) * FROWB + (k16 * 16 + a_c) * 2);
            uint32_t ah[4], al[4];
            ldsm4(ah[0], ah[1], ah[2], ah[3], sQh + qoff);
            ldsm4(al[0], al[1], al[2], al[3], sQl + qoff);
#pragma unroll
            for (int ntp = 0; ntp < 4; ntp++) {
                uint32_t koff = (uint32_t)((ntp * 16 + b_r) * FROWB + (k16 * 16 + b_c) * 2);
                uint32_t kh[4], kl[4];
                ldsm4(kh[0], kh[1], kh[2], kh[3], sK_h + koff);
                ldsm4(kl[0], kl[1], kl[2], kl[3], sK_l + koff);
#pragma unroll
                for (int u = 0; u < 2; u++) {
                    int nt = ntp * 2 + u;
                    uint32_t bfh[2] = { kh[u * 2], kh[u * 2 + 1] };
                    uint32_t bfl[2] = { kl[u * 2], kl[u * 2 + 1] };
                    mma16816(sc[nt], ah, bfh);
                    mma16816(sc[nt], ah, bfl);
                    mma16816(sc[nt], al, bfh);
                }
            }
        }

        const bool boundary = (kg0 + 63 >= qg0);
#pragma unroll
        for (int nt = 0; nt < 8; nt++) {
#pragma unroll
            for (int c = 0; c < 4; c++) {
                float v = sc[nt][c] * SCALE_L2E;
                if (boundary) {
                    int qg = qrow0 + (c >> 1) * 8;
                    int kg = kg0 + nt * 8 + (lane & 3) * 2 + (c & 1);
                    bool allow = ICL ? (kg < qg || (qg | kg) == 0) : (kg <= qg);
                    v = allow ? v : -1e30f;
                }
                sc[nt][c] = v;
            }
        }

#pragma unroll
        for (int ri = 0; ri < 2; ri++) {
            float mx = -1e30f;
#pragma unroll
            for (int nt = 0; nt < 8; nt++)
                mx = fmaxf(mx, fmaxf(sc[nt][ri * 2], sc[nt][ri * 2 + 1]));
            mx = fmaxf(mx, __shfl_xor_sync(0xffffffffu, mx, 1));
            mx = fmaxf(mx, __shfl_xor_sync(0xffffffffu, mx, 2));
            float mn = fmaxf(mrow[ri], mx);
            float corr = exp2p(mrow[ri] - mn);
            mrow[ri] = mn;
            float rs = 0.f;
#pragma unroll
            for (int nt = 0; nt < 8; nt++) {
                float p0 = exp2p(sc[nt][ri * 2] - mn);
                float p1 = exp2p(sc[nt][ri * 2 + 1] - mn);
                sc[nt][ri * 2] = p0;
                sc[nt][ri * 2 + 1] = p1;
                rs += p0 + p1;
            }
            rs += __shfl_xor_sync(0xffffffffu, rs, 1);
            rs += __shfl_xor_sync(0xffffffffu, rs, 2);
            lrow[ri] = lrow[ri] * corr + rs;
#pragma unroll
            for (int nt = 0; nt < 8; nt++) {
                out[nt][ri * 2] *= corr;
                out[nt][ri * 2 + 1] *= corr;
            }
        }

#pragma unroll
        for (int j = 0; j < 4; j++) {
            uint32_t aP[4];
            aP[0] = pk2(__float2bfloat16(sc[2 * j][0]),     __float2bfloat16(sc[2 * j][1]));
            aP[1] = pk2(__float2bfloat16(sc[2 * j][2]),     __float2bfloat16(sc[2 * j][3]));
            aP[2] = pk2(__float2bfloat16(sc[2 * j + 1][0]), __float2bfloat16(sc[2 * j + 1][1]));
            aP[3] = pk2(__float2bfloat16(sc[2 * j + 1][2]), __float2bfloat16(sc[2 * j + 1][3]));
#pragma unroll
            for (int nt2 = 0; nt2 < 4; nt2++) {
                uint32_t voff = (uint32_t)((j * 16 + (grp & 1) * 8 + rl) * FROWB
                                           + (nt2 * 16 + (grp >> 1) * 8) * 2);
                uint32_t bv[4];
                ldsm4t(bv[0], bv[1], bv[2], bv[3], sV_h + voff);
                {
                    uint32_t b0[2] = { bv[0], bv[1] }, b1[2] = { bv[2], bv[3] };
                    mma16816(out[nt2 * 2], aP, b0);
                    mma16816(out[nt2 * 2 + 1], aP, b1);
                }
                ldsm4t(bv[0], bv[1], bv[2], bv[3], sV_l + voff);
                {
                    uint32_t b0[2] = { bv[0], bv[1] }, b1[2] = { bv[2], bv[3] };
                    mma16816(out[nt2 * 2], aP, b0);
                    mma16816(out[nt2 * 2 + 1], aP, b1);
                }
            }
        }
        __syncthreads();
    }

#pragma unroll
    for (int ri = 0; ri < 2; ri++) {
        float inv = 1.0f / lrow[ri];
        size_t rbase = (tokb + qrow0 + ri * 8) * DAA + h * DHH + (lane & 3) * 2;
#pragma unroll
        for (int nt = 0; nt < 8; nt++) {
            float v0 = out[nt][ri * 2] * inv;
            float v1 = out[nt][ri * 2 + 1] * inv;
            __nv_bfloat16 h0, h1, l0, l1;
            split1(v0, h0, l0); split1(v1, h1, l1);
            *(uint32_t*)&Oh[rbase + nt * 8] = pk2(h0, h1);
            *(uint32_t*)&Ol[rbase + nt * 8] = pk2(l0, l1);
        }
    }
}

// ---------------- host driver ----------------
#define GETSYM(T, var, sym) T* var; { void* _p; cudaGetSymbolAddress(&_p, sym); var = (T*)_p; }

extern "C" void kernel_launch(void* const* d_in, const int* in_sizes, int n_in,
                              void* d_out, int out_size)
{
    const float* cov_in  = (const float*)d_in[0];
    const float* tgt_in  = (const float*)d_in[1];
    const float* fu_in   = (const float*)d_in[2];
    const float* fc1w    = (const float*)d_in[3];
    const float* fc1b    = (const float*)d_in[4];
    const float* fc2w    = (const float*)d_in[5];
    const float* fc2b    = (const float*)d_in[6];
    const float* icl_wq  = (const float*)d_in[7];
    const float* icl_wk  = (const float*)d_in[8];
    const float* icl_wv  = (const float*)d_in[9];
    const float* icl_wo  = (const float*)d_in[10];
    const float* cov_wq  = (const float*)d_in[11];
    const float* cov_wk  = (const float*)d_in[12];
    const float* cov_wv  = (const float*)d_in[13];
    const float* cov_wo  = (const float*)d_in[14];
    const float* ln_cm_g = (const float*)d_in[15];
    const float* ln_cm_b = (const float*)d_in[16];
    const float* ln_ia_g = (const float*)d_in[17];
    const float* ln_ia_b = (const float*)d_in[18];
    const float* ln_im_g = (const float*)d_in[19];
    const float* ln_im_b = (const float*)d_in[20];

    float* out_cov = (float*)d_out;
    float* out_tgt = out_cov + (size_t)NTOK * EE;
    float* out_fu  = out_tgt + (size_t)NTOK * EE;

    GETSYM(float, qkvI, g_qkvI)    GETSYM(float, qkvC, g_qkvC)
    GETSYM(uint16_t, lnh, pLNh)    GETSYM(uint16_t, lnl, pLNl)
    GETSYM(uint16_t, ln2h, pLN2h)  GETSYM(uint16_t, ln2l, pLN2l)
    GETSYM(uint16_t, midh, pMIDh)  GETSYM(uint16_t, midl, pMIDl)
    GETSYM(uint16_t, mid2h, pMID2h) GETSYM(uint16_t, mid2l, pMID2l)
    GETSYM(uint16_t, qh, pQh)      GETSYM(uint16_t, ql, pQl)
    GETSYM(uint16_t, tgh, pTGTh)   GETSYM(uint16_t, tgl, pTGTl)
    GETSYM(uint16_t, aoIh, pAOIh)  GETSYM(uint16_t, aoIl, pAOIl)
    GETSYM(uint16_t, aoCh, pAOCh)  GETSYM(uint16_t, aoCl, pAOCl)
    GETSYM(uint16_t, fqIh, pFQIh)  GETSYM(uint16_t, fqIl, pFQIl)
    GETSYM(uint16_t, fkIh, pFKIh)  GETSYM(uint16_t, fkIl, pFKIl)
    GETSYM(uint16_t, fvIh, pFVIh)  GETSYM(uint16_t, fvIl, pFVIl)
    GETSYM(uint16_t, fqCh, pFQCh)  GETSYM(uint16_t, fqCl, pFQCl)
    GETSYM(uint16_t, fkCh, pFKCh)  GETSYM(uint16_t, fkCl, pFKCl)
    GETSYM(uint16_t, fvCh, pFVCh)  GETSYM(uint16_t, fvCl, pFVCl)
    GETSYM(uint16_t, w1h, pW1h)    GETSYM(uint16_t, w1l, pW1l)
    GETSYM(uint16_t, w2h, pW2h)    GETSYM(uint16_t, w2l, pW2l)
    GETSYM(uint16_t, iqkh, pIQKh)  GETSYM(uint16_t, iqkl, pIQKl)
    GETSYM(uint16_t, ivh, pIVh)    GETSYM(uint16_t, ivl, pIVl)
    GETSYM(uint16_t, ioh, pIOh)    GETSYM(uint16_t, iol, pIOl)
    GETSYM(uint16_t, cqkvh, pCQKVh) GETSYM(uint16_t, cqkvl, pCQKVl)
    GETSYM(uint16_t, coh, pCOh)    GETSYM(uint16_t, col, pCOl)

    static cudaStream_t s2 = nullptr;
    static cudaEvent_t ev0 = nullptr, evq = nullptr, evend = nullptr;
    if (!s2) {
        cudaStreamCreateWithFlags(&s2, cudaStreamNonBlocking);
        cudaEventCreateWithFlags(&ev0, cudaEventDisableTiming);
        cudaEventCreateWithFlags(&evq, cudaEventDisableTiming);
        cudaEventCreateWithFlags(&evend, cudaEventDisableTiming);
        cudaFuncSetAttribute(gemm_tc<0>, cudaFuncAttributeMaxDynamicSharedMemorySize, SMEM_GEMM);
        cudaFuncSetAttribute(gemm_tc<1>, cudaFuncAttributeMaxDynamicSharedMemorySize, SMEM_GEMM);
        cudaFuncSetAttribute(gemm_tc<2>, cudaFuncAttributeMaxDynamicSharedMemorySize, SMEM_GEMM);
        cudaFuncSetAttribute(gemm_tc<3>, cudaFuncAttributeMaxDynamicSharedMemorySize, SMEM_GEMM);
        cudaFuncSetAttribute(flash_mma<0>, cudaFuncAttributeMaxDynamicSharedMemorySize, SMEM_FLASH);
        cudaFuncSetAttribute(flash_mma<1>, cudaFuncAttributeMaxDynamicSharedMemorySize, SMEM_FLASH);
    }

    const dim3 thr(256);
    const dim3 gFC1(DMLP / 128, NTOK / 128);
    const dim3 gFC2(EE / 128, NTOK / 128);
    const dim3 gQK(8, NTOK / 128);
    const dim3 gV(4, NTOK / 128);
    const dim3 gQKV(12, NTOK / 128);
    const dim3 gWO(EE / 128, NTOK / 128);
    const dim3 gFLASH(SS / 128, BB * HH);

    // ---- all weight conversions, one launch ----
    ConvJobs cj;
    cj.src[0] = fc1w;   cj.dh[0] = w1h;              cj.dl[0] = w1l;              cj.K[0] = EE;   cj.N[0] = DMLP;
    cj.src[1] = fc2w;   cj.dh[1] = w2h;              cj.dl[1] = w2l;              cj.K[1] = DMLP; cj.N[1] = EE;
    cj.src[2] = icl_wq; cj.dh[2] = iqkh;             cj.dl[2] = iqkl;             cj.K[2] = EE;   cj.N[2] = DAA;
    cj.src[3] = icl_wk; cj.dh[3] = iqkh + 512 * EE;  cj.dl[3] = iqkl + 512 * EE;  cj.K[3] = EE;   cj.N[3] = DAA;
    cj.src[4] = icl_wv; cj.dh[4] = ivh;              cj.dl[4] = ivl;              cj.K[4] = EE;   cj.N[4] = DAA;
    cj.src[5] = cov_wq; cj.dh[5] = cqkvh;            cj.dl[5] = cqkvl;            cj.K[5] = EE;   cj.N[5] = DAA;
    cj.src[6] = cov_wk; cj.dh[6] = cqkvh + 512 * EE; cj.dl[6] = cqkvl + 512 * EE; cj.K[6] = EE;   cj.N[6] = DAA;
    cj.src[7] = cov_wv; cj.dh[7] = cqkvh + 1024 * EE;cj.dl[7] = cqkvl + 1024 * EE;cj.K[7] = EE;   cj.N[7] = DAA;
    cj.src[8] = icl_wo; cj.dh[8] = ioh;              cj.dl[8] = iol;              cj.K[8] = DAA;  cj.N[8] = EE;
    cj.src[9] = cov_wo; cj.dh[9] = coh;              cj.dl[9] = col;              cj.K[9] = DAA;  cj.N[9] = EE;
    conv_all<<<dim3(16, 32, 10), thr>>>(cj);
    cudaEventRecord(ev0, 0);
    cudaStreamWaitEvent(s2, ev0, 0);

    // ---- chain2 on s2: tgt = targets + MLP(LN(functional_update)) ----
    ln_split<<<NTOK, thr, 0, s2>>>(fu_in, ln_im_g, ln_im_b, ln2h, ln2l);
    gemm_tc<1><<<gFC1, thr, SMEM_GEMM, s2>>>(ln2h, ln2l, w1h, w1l, fc1b, nullptr,
                                             nullptr, mid2h, mid2l, DMLP, EE, DMLP);
    gemm_tc<2><<<gFC2, thr, SMEM_GEMM, s2>>>(mid2h, mid2l, w2h, w2l, fc2b, tgt_in,
                                             out_tgt, tgh, tgl, EE, DMLP, EE);
    // V-projection depends only on tgt — run before waiting for q
    gemm_tc<0><<<gV, thr, SMEM_GEMM, s2>>>(tgh, tgl, ivh, ivl, nullptr, nullptr,
                                           qkvI + 1024, nullptr, nullptr, DAA, EE, 1536);

    // ---- chain1 on legacy: cov = covariates + MLP(LN(covariates)); q = LN(cov) ----
    ln_split<<<NTOK, thr>>>(cov_in, ln_cm_g, ln_cm_b, lnh, lnl);
    gemm_tc<1><<<gFC1, thr, SMEM_GEMM>>>(lnh, lnl, w1h, w1l, fc1b, nullptr,
                                         nullptr, midh, midl, DMLP, EE, DMLP);
    gemm_tc<2><<<gFC2, thr, SMEM_GEMM>>>(midh, midl, w2h, w2l, fc2b, cov_in,
                                         out_cov, nullptr, nullptr, EE, DMLP, EE);
    ln_split<<<NTOK, thr>>>(out_cov, ln_ia_g, ln_ia_b, qh, ql);
    cudaEventRecord(evq, 0);

    // ---- ICL attention on s2 (needs q + tgt) ----
    cudaStreamWaitEvent(s2, evq, 0);
    gemm_tc<0><<<gQK, thr, SMEM_GEMM, s2>>>(qh, ql, iqkh, iqkl, nullptr, nullptr,
                                            qkvI, nullptr, nullptr, 1024, EE, 1536);
    rope_split<<<NTOK, thr, 0, s2>>>(qkvI, fqIh, fqIl, fkIh, fkIl, fvIh, fvIl);
    flash_mma<1><<<gFLASH, thr, SMEM_FLASH, s2>>>(fqIh, fqIl, fkIh, fkIl, fvIh, fvIl, aoIh, aoIl);
    gemm_tc<3><<<gWO, thr, SMEM_GEMM, s2>>>(aoIh, aoIl, ioh, iol, nullptr, fu_in,
                                            out_fu, nullptr, nullptr, EE, DAA, EE);
    cudaEventRecord(evend, s2);

    // ---- COV attention on legacy (needs only q) ----
    gemm_tc<0><<<gQKV, thr, SMEM_GEMM>>>(qh, ql, cqkvh, cqkvl, nullptr, nullptr,
                                         qkvC, nullptr, nullptr, 1536, EE, 1536);
    rope_split<<<NTOK, thr>>>(qkvC, fqCh, fqCl, fkCh, fkCl, fvCh, fvCl);
    flash_mma<0><<<gFLASH, thr, SMEM_FLASH>>>(fqCh, fqCl, fkCh, fkCl, fvCh, fvCl, aoCh, aoCl);
    gemm_tc<3><<<gWO, thr, SMEM_GEMM>>>(aoCh, aoCl, coh, col, nullptr, out_cov,
                                        out_cov, nullptr, nullptr, EE, DAA, EE);

    // join
    cudaStreamWaitEvent(0, evend, 0);
}

// round 12
// speedup vs baseline: 1.0548x; 1.0079x over previous
#include <cuda_runtime.h>
#include <cuda_bf16.h>
#include <math.h>
#include <stdint.h>

#define BB 2
#define SS 2048
#define EE 1024
#define HH 8
#define DHH 64
#define DAA 512
#define DMLP 2048
#define NTOK 4096
#define SCALE_ATTN 0.04419417382415922f
#define SCALE_L2E 0.06375944628228341f   // SCALE_ATTN * log2(e)
#define LN_EPS 1e-5f

// GEMM (round-8 proven config): 128x128 tile, warp 64x32, K-chunk 32, 2-stage,
// padded 80B rows (conflict-free ldmatrix).
#define ROWB 80
#define PLANE_B 10240
#define STAGE_B 40960
#define SMEM_GEMM (2 * STAGE_B)

#define FROWB 144
#define FQPL 18432
#define FKPL 9216
#define FSTG 36864
#define SMEM_FLASH (2 * FQPL + 2 * FSTG)

// ---------------- scratch ----------------
__device__ uint16_t pLNh[NTOK * EE],     pLNl[NTOK * EE];
__device__ uint16_t pLN2h[NTOK * EE],    pLN2l[NTOK * EE];
__device__ uint16_t pMIDh[NTOK * DMLP],  pMIDl[NTOK * DMLP];
__device__ uint16_t pMID2h[NTOK * DMLP], pMID2l[NTOK * DMLP];
__device__ uint16_t pQh[NTOK * EE],      pQl[NTOK * EE];
__device__ uint16_t pTGTh[NTOK * EE],    pTGTl[NTOK * EE];
__device__ uint16_t pAOIh[NTOK * DAA],   pAOIl[NTOK * DAA];
__device__ uint16_t pAOCh[NTOK * DAA],   pAOCl[NTOK * DAA];
__device__ uint16_t pFQIh[NTOK * DAA],   pFQIl[NTOK * DAA];
__device__ uint16_t pFKIh[NTOK * DAA],   pFKIl[NTOK * DAA];
__device__ uint16_t pFVIh[NTOK * DAA],   pFVIl[NTOK * DAA];
__device__ uint16_t pFQCh[NTOK * DAA],   pFQCl[NTOK * DAA];
__device__ uint16_t pFKCh[NTOK * DAA],   pFKCl[NTOK * DAA];
__device__ uint16_t pFVCh[NTOK * DAA],   pFVCl[NTOK * DAA];

__device__ uint16_t pW1h[DMLP * EE],    pW1l[DMLP * EE];
__device__ uint16_t pW2h[EE * DMLP],    pW2l[EE * DMLP];
__device__ uint16_t pIQKh[1024 * EE],   pIQKl[1024 * EE];
__device__ uint16_t pIVh[DAA * EE],     pIVl[DAA * EE];
__device__ uint16_t pIOh[EE * DAA],     pIOl[EE * DAA];
__device__ uint16_t pCQKVh[1536 * EE],  pCQKVl[1536 * EE];
__device__ uint16_t pCOh[EE * DAA],     pCOl[EE * DAA];

// plane destinations + column offset for the fused RoPE epilogue (MODE 4)
struct RopeOut {
    uint16_t *qh, *ql, *kh, *kl, *vh, *vl;
    int colOff;
};

// ---------------- helpers ----------------
__device__ __forceinline__ uint32_t pk2(__nv_bfloat16 a, __nv_bfloat16 b) {
    uint16_t ra = *reinterpret_cast<uint16_t*>(&a);
    uint16_t rb = *reinterpret_cast<uint16_t*>(&b);
    return (uint32_t)ra | ((uint32_t)rb << 16);
}
__device__ __forceinline__ void split1(float x, __nv_bfloat16& h, __nv_bfloat16& l) {
    h = __float2bfloat16(x);
    l = __float2bfloat16(x - __bfloat162float(h));
}
__device__ __forceinline__ void mma16816(float* c, const uint32_t* a, const uint32_t* b) {
    asm volatile(
        "mma.sync.aligned.m16n8k16.row.col.f32.bf16.bf16.f32 "
        "{%0,%1,%2,%3}, {%4,%5,%6,%7}, {%8,%9}, {%0,%1,%2,%3};"
        : "+f"(c[0]), "+f"(c[1]), "+f"(c[2]), "+f"(c[3])
        : "r"(a[0]), "r"(a[1]), "r"(a[2]), "r"(a[3]), "r"(b[0]), "r"(b[1]));
}
__device__ __forceinline__ void ldsm4(uint32_t& r0, uint32_t& r1, uint32_t& r2, uint32_t& r3,
                                      uint32_t addr) {
    asm volatile("ldmatrix.sync.aligned.m8n8.x4.shared.b16 {%0,%1,%2,%3}, [%4];"
                 : "=r"(r0), "=r"(r1), "=r"(r2), "=r"(r3) : "r"(addr));
}
__device__ __forceinline__ void ldsm4t(uint32_t& r0, uint32_t& r1, uint32_t& r2, uint32_t& r3,
                                       uint32_t addr) {
    asm volatile("ldmatrix.sync.aligned.m8n8.x4.trans.shared.b16 {%0,%1,%2,%3}, [%4];"
                 : "=r"(r0), "=r"(r1), "=r"(r2), "=r"(r3) : "r"(addr));
}
__device__ __forceinline__ void cpa16(uint32_t s, const void* g) {
    asm volatile("cp.async.ca.shared.global [%0], [%1], 16;" :: "r"(s), "l"(g));
}
__device__ __forceinline__ void cpa_commit() {
    asm volatile("cp.async.commit_group;" ::: "memory");
}
template<int N>
__device__ __forceinline__ void cpa_wait() {
    asm volatile("cp.async.wait_group %0;" :: "n"(N) : "memory");
}
__device__ __forceinline__ float exp2p(float x) {
    x = fmaxf(x, -80.f);
    float n = rintf(x);
    float f = x - n;
    float p = 1.3333558146428443e-3f;
    p = p * f + 9.618129107628477e-3f;
    p = p * f + 5.550410866482158e-2f;
    p = p * f + 2.402265069591007e-1f;
    p = p * f + 6.931471805599453e-1f;
    p = p * f + 1.0f;
    return p * __int_as_float(((int)n + 127) << 23);
}

__device__ __forceinline__ float block_reduce_sum(float v) {
    __shared__ float red[32];
    int lane = threadIdx.x & 31, w = threadIdx.x >> 5;
#pragma unroll
    for (int o = 16; o > 0; o >>= 1) v += __shfl_xor_sync(0xffffffffu, v, o);
    __syncthreads();
    if (lane == 0) red[w] = v;
    __syncthreads();
    v = (lane < 8) ? red[lane] : 0.f;
#pragma unroll
    for (int o = 16; o > 0; o >>= 1) v += __shfl_xor_sync(0xffffffffu, v, o);
    return v;
}

// ---------------- LayerNorm -> bf16 hi/lo planes ----------------
__global__ void ln_split(const float* __restrict__ x, const float* __restrict__ g,
                         const float* __restrict__ b,
                         uint16_t* __restrict__ oh, uint16_t* __restrict__ ol) {
    int row = blockIdx.x, t = threadIdx.x;
    float4 v = *(const float4*)&x[(size_t)row * EE + 4 * t];
    float s = v.x + v.y + v.z + v.w;
    float mean = block_reduce_sum(s) * (1.0f / EE);
    float d0 = v.x - mean, d1 = v.y - mean, d2 = v.z - mean, d3 = v.w - mean;
    float var = block_reduce_sum(d0 * d0 + d1 * d1 + d2 * d2 + d3 * d3) * (1.0f / EE);
    float rstd = rsqrtf(var + LN_EPS);
    float4 gg = *(const float4*)&g[4 * t];
    float4 bb = *(const float4*)&b[4 * t];
    float y0 = d0 * rstd * gg.x + bb.x;
    float y1 = d1 * rstd * gg.y + bb.y;
    float y2 = d2 * rstd * gg.z + bb.z;
    float y3 = d3 * rstd * gg.w + bb.w;
    __nv_bfloat16 h0, h1, h2, h3, l0, l1, l2, l3;
    split1(y0, h0, l0); split1(y1, h1, l1); split1(y2, h2, l2); split1(y3, h3, l3);
    size_t off = (size_t)row * EE + 4 * t;
    *(uint2*)&oh[off] = make_uint2(pk2(h0, h1), pk2(h2, h3));
    *(uint2*)&ol[off] = make_uint2(pk2(l0, l1), pk2(l2, l3));
}

// ---------------- weight conversion, single launch ----------------
__device__ __forceinline__ void convB_body(const float* __restrict__ W,
                                           uint16_t* __restrict__ Bh,
                                           uint16_t* __restrict__ Bl, int K, int N) {
    __shared__ float ts[64][129];
    int nt = blockIdx.x, kt = blockIdx.y, tid = threadIdx.x;
    int k0 = kt * 64, n0 = nt * 128;
#pragma unroll
    for (int i = 0; i < 32; i++) {
        int idx = tid + i * 256;
        int kk = idx >> 7, nn = idx & 127;
        ts[kk][nn] = W[(size_t)(k0 + kk) * N + n0 + nn];
    }
    __syncthreads();
#pragma unroll
    for (int j = 0; j < 4; j++) {
        int job = tid + j * 256;
        int n = job >> 3, kg = (job & 7) * 8;
        __nv_bfloat16 h[8], l[8];
#pragma unroll
        for (int i = 0; i < 8; i++) split1(ts[kg + i][n], h[i], l[i]);
        uint4 uh = make_uint4(pk2(h[0], h[1]), pk2(h[2], h[3]), pk2(h[4], h[5]), pk2(h[6], h[7]));
        uint4 ul = make_uint4(pk2(l[0], l[1]), pk2(l[2], l[3]), pk2(l[4], l[5]), pk2(l[6], l[7]));
        size_t off = (size_t)(n0 + n) * K + k0 + kg;
        *(uint4*)&Bh[off] = uh;
        *(uint4*)&Bl[off] = ul;
    }
}

struct ConvJobs {
    const float* src[10];
    uint16_t* dh[10];
    uint16_t* dl[10];
    int K[10], N[10];
};
__global__ void conv_all(ConvJobs j) {
    int w = blockIdx.z;
    int K = j.K[w], N = j.N[w];
    if (blockIdx.x * 128 >= N || blockIdx.y * 64 >= K) return;
    convB_body(j.src[w], j.dh[w], j.dl[w], K, N);
}

// ---------------- HMMA bf16-split GEMM (round-8 mainloop) ----------------
// MODE 0: C=AB(fp32, ldC)   1: planes=gelu(AB+bias)   2: C=AB+bias+R (+planes)
// MODE 3: C=AB+R            4: fused RoPE+split -> flash planes (RopeOut)
template<int MODE>
__global__ void __launch_bounds__(256, 2) gemm_tc(
    const uint16_t* __restrict__ Ah, const uint16_t* __restrict__ Al,
    const uint16_t* __restrict__ Bh, const uint16_t* __restrict__ Bl,
    const float* __restrict__ bias, const float* __restrict__ R,
    float* __restrict__ C, uint16_t* __restrict__ Ch, uint16_t* __restrict__ Cl,
    RopeOut ro, int N, int K, int ldC)
{
    extern __shared__ char sm[];
    const uint32_t sbase = (uint32_t)__cvta_generic_to_shared(sm);
    const int tid = threadIdx.x;
    const int warp = tid >> 5, lane = tid & 31;
    const int wm = warp & 1, wn = warp >> 1;
    const int m0 = blockIdx.y * 128, n0 = blockIdx.x * 128;
    const int KT = K >> 5;

    const uint16_t* gA[2] = { Ah + (size_t)m0 * K, Al + (size_t)m0 * K };
    const uint16_t* gB[2] = { Bh + (size_t)n0 * K, Bl + (size_t)n0 * K };

    const int rl = lane & 7, grp = lane >> 3;
    const int a_r = rl + (grp & 1) * 8;
    const int a_c = (grp >> 1) * 8;
    const int b_r = rl + ((grp >> 1) & 1) * 8;
    const int b_c = (grp & 1) * 8;

    float acc[4][4][4];
#pragma unroll
    for (int i = 0; i < 4; i++)
#pragma unroll
        for (int j = 0; j < 4; j++)
#pragma unroll
            for (int k = 0; k < 4; k++) acc[i][j][k] = 0.f;

    auto issue = [&](int stage, int kt) {
        uint32_t s0 = sbase + stage * STAGE_B;
        int kel = kt * 32;
#pragma unroll
        for (int pl = 0; pl < 4; pl++) {
            const uint16_t* g = (pl < 2) ? gA[pl] : gB[pl - 2];
#pragma unroll
            for (int i = 0; i < 2; i++) {
                int seg = tid + i * 256;
                int m = seg >> 2, s = seg & 3;
                cpa16(s0 + pl * PLANE_B + m * ROWB + s * 16,
                      g + (size_t)m * K + kel + s * 8);
            }
        }
        cpa_commit();
    };

    issue(0, 0);
    for (int kt = 0; kt < KT; kt++) {
        int st = kt & 1;
        if (kt + 1 < KT) { issue(st ^ 1, kt + 1); cpa_wait<1>(); }
        else             { cpa_wait<0>(); }
        __syncthreads();

        uint32_t sA_h = sbase + st * STAGE_B;
        uint32_t sA_l = sA_h + PLANE_B;
        uint32_t sB_h = sA_h + 2 * PLANE_B;
        uint32_t sB_l = sA_h + 3 * PLANE_B;

#pragma unroll
        for (int ks = 0; ks < 2; ks++) {
            const int kk = ks * 16;
            uint32_t bh[2][4], bl[2][4];
#pragma unroll
            for (int ntp = 0; ntp < 2; ntp++) {
                uint32_t off = (uint32_t)((wn * 32 + ntp * 16 + b_r) * ROWB + (kk + b_c) * 2);
                ldsm4(bh[ntp][0], bh[ntp][1], bh[ntp][2], bh[ntp][3], sB_h + off);
                ldsm4(bl[ntp][0], bl[ntp][1], bl[ntp][2], bl[ntp][3], sB_l + off);
            }
#pragma unroll
            for (int mt = 0; mt < 4; mt++) {
                uint32_t off = (uint32_t)((wm * 64 + mt * 16 + a_r) * ROWB + (kk + a_c) * 2);
                uint32_t ah[4], al[4];
                ldsm4(ah[0], ah[1], ah[2], ah[3], sA_h + off);
                ldsm4(al[0], al[1], al[2], al[3], sA_l + off);
#pragma unroll
                for (int nt = 0; nt < 4; nt++) {
                    uint32_t bfh[2] = { bh[nt >> 1][(nt & 1) * 2], bh[nt >> 1][(nt & 1) * 2 + 1] };
                    uint32_t bfl[2] = { bl[nt >> 1][(nt & 1) * 2], bl[nt >> 1][(nt & 1) * 2 + 1] };
                    mma16816(acc[mt][nt], ah, bfh);
                    mma16816(acc[mt][nt], ah, bfl);
                    mma16816(acc[mt][nt], al, bfh);
                }
            }
        }
        __syncthreads();
    }

    const int r = lane >> 2, q = lane & 3;
#pragma unroll
    for (int mt = 0; mt < 4; mt++) {
#pragma unroll
        for (int nt = 0; nt < 4; nt++) {
            int row = m0 + wm * 64 + mt * 16 + r;
            int col = n0 + wn * 32 + nt * 8 + q * 2;
#pragma unroll
            for (int half = 0; half < 2; half++) {
                int rr2 = row + half * 8;
                float v0 = acc[mt][nt][half * 2 + 0];
                float v1 = acc[mt][nt][half * 2 + 1];
                if (MODE == 4) {
                    // fused RoPE + split to flash planes
                    int colg = ro.colOff + col;
                    int region = colg >> 9;          // 0=q, 1=k, 2=v
                    int cl = colg & 511;
                    float o0 = v0, o1 = v1;
                    if (region < 2) {
                        int i = (cl >> 1) & 31;
                        float inv = __expf(-9.210340371976184f * ((float)i / 32.0f));
                        float ang = (float)(rr2 & (SS - 1)) * inv;
                        float cc = cosf(ang), sn = sinf(ang);
                        o0 = v0 * cc - v1 * sn;
                        o1 = v0 * sn + v1 * cc;
                    }
                    uint16_t* dh = (region == 0) ? ro.qh : (region == 1) ? ro.kh : ro.vh;
                    uint16_t* dl = (region == 0) ? ro.ql : (region == 1) ? ro.kl : ro.vl;
                    __nv_bfloat16 h0, h1, l0, l1;
                    split1(o0, h0, l0); split1(o1, h1, l1);
                    size_t didx = (size_t)rr2 * DAA + cl;
                    *(uint32_t*)&dh[didx] = pk2(h0, h1);
                    *(uint32_t*)&dl[didx] = pk2(l0, l1);
                    continue;
                }
                size_t gidx = (size_t)rr2 * ldC + col;
                if (MODE == 1) {
                    v0 += bias[col];
                    v1 += bias[col + 1];
                    v0 = 0.5f * v0 * (1.0f + erff(v0 * 0.70710678118654752f));
                    v1 = 0.5f * v1 * (1.0f + erff(v1 * 0.70710678118654752f));
                    __nv_bfloat16 h0, h1, l0, l1;
                    split1(v0, h0, l0); split1(v1, h1, l1);
                    *(uint32_t*)&Ch[gidx] = pk2(h0, h1);
                    *(uint32_t*)&Cl[gidx] = pk2(l0, l1);
                } else {
                    if (MODE == 2) {
                        float2 rv = *(const float2*)&R[gidx];
                        v0 += bias[col] + rv.x;
                        v1 += bias[col + 1] + rv.y;
                    } else if (MODE == 3) {
                        float2 rv = *(const float2*)&R[gidx];
                        v0 += rv.x;
                        v1 += rv.y;
                    }
                    *(float2*)&C[gidx] = make_float2(v0, v1);
                    if (MODE == 2 && Ch) {
                        __nv_bfloat16 h0, h1, l0, l1;
                        split1(v0, h0, l0); split1(v1, h1, l1);
                        *(uint32_t*)&Ch[gidx] = pk2(h0, h1);
                        *(uint32_t*)&Cl[gidx] = pk2(l0, l1);
                    }
                }
            }
        }
    }
}

// ---------------- Flash attention, HMMA + poly exp2 ----------------
template<int ICL>
__global__ void __launch_bounds__(256) flash_mma(
    const uint16_t* __restrict__ Qh, const uint16_t* __restrict__ Ql,
    const uint16_t* __restrict__ Kh, const uint16_t* __restrict__ Kl,
    const uint16_t* __restrict__ Vh, const uint16_t* __restrict__ Vl,
    uint16_t* __restrict__ Oh, uint16_t* __restrict__ Ol)
{
    extern __shared__ char sm[];
    const uint32_t sb = (uint32_t)__cvta_generic_to_shared(sm);
    const uint32_t sQh = sb, sQl = sb + FQPL;
    const uint32_t sKV = sb + 2 * FQPL;
    const int tid = threadIdx.x, warp = tid >> 5, lane = tid & 31;
    const int qt = gridDim.x - 1 - blockIdx.x;
    const int bh = blockIdx.y, b = bh >> 3, h = bh & 7;
    const int qg0 = qt * 128;
    const size_t tokb = (size_t)b * SS;
    const int rb = warp * 16;

    const int rl = lane & 7, grp = lane >> 3;
    const int a_r = rl + (grp & 1) * 8;
    const int a_c = (grp >> 1) * 8;
    const int b_r = rl + ((grp >> 1) & 1) * 8;
    const int b_c = (grp & 1) * 8;

#pragma unroll
    for (int i = 0; i < 8; i++) {
        int job = tid + i * 256;
        int pl = job >> 10, r = (job >> 3) & 127, s = job & 7;
        const uint16_t* g = (pl ? Ql : Qh) + (tokb + qg0 + r) * DAA + h * DHH + s * 8;
        cpa16((pl ? sQl : sQh) + r * FROWB + s * 16, g);
    }
    cpa_commit();

    float out[8][4];
#pragma unroll
    for (int i = 0; i < 8; i++)
#pragma unroll
        for (int j = 0; j < 4; j++) out[i][j] = 0.f;
    float mrow[2] = { -1e30f, -1e30f }, lrow[2] = { 0.f, 0.f };

    const int ktmax = (qg0 + 127) >> 6;

    auto issueKV = [&](int st, int kt) {
        uint32_t s0 = sKV + st * FSTG;
        int kg0 = kt * 64;
#pragma unroll
        for (int i = 0; i < 8; i++) {
            int job = tid + i * 256;
            int pl = job >> 9, r = (job >> 3) & 63, s = job & 7;
            const uint16_t* gp = (pl == 0) ? Kh : (pl == 1) ? Kl : (pl == 2) ? Vh : Vl;
            cpa16(s0 + pl * FKPL + r * FROWB + s * 16,
                  gp + (tokb + kg0 + r) * DAA + h * DHH + s * 8);
        }
        cpa_commit();
    };
    issueKV(0, 0);

    const int qrow0 = qg0 + rb + (lane >> 2);

    for (int kt = 0; kt <= ktmax; kt++) {
        int st = kt & 1;
        int kg0 = kt * 64;
        if (kt < ktmax) { issueKV(st ^ 1, kt + 1); cpa_wait<1>(); }
        else            { cpa_wait<0>(); }
        __syncthreads();

        uint32_t sK_h = sKV + st * FSTG;
        uint32_t sK_l = sK_h + FKPL;
        uint32_t sV_h = sK_h + 2 * FKPL;
        uint32_t sV_l = sK_h + 3 * FKPL;

        float sc[8][4];
#pragma unroll
        for (int i = 0; i < 8; i++)
#pragma unroll
            for (int j = 0; j < 4; j++) sc[i][j] = 0.f;
#pragma unroll
        for (int k16 = 0; k16 < 4; k16++) {
            uint32_t qoff = (uint32_t)((rb + a_r) * FROWB + (k16 * 16 + a_c) * 2);
            uint32_t ah[4], al[4];
            ldsm4(ah[0], ah[1], ah[2], ah[3], sQh + qoff);
            ldsm4(al[0], al[1], al[2], al[3], sQl + qoff);
#pragma unroll
            for (int ntp = 0; ntp < 4; ntp++) {
                uint32_t koff = (uint32_t)((ntp * 16 + b_r) * FROWB + (k16 * 16 + b_c) * 2);
                uint32_t kh[4], kl[4];
                ldsm4(kh[0], kh[1], kh[2], kh[3], sK_h + koff);
                ldsm4(kl[0], kl[1], kl[2], kl[3], sK_l + koff);
#pragma unroll
                for (int u = 0; u < 2; u++) {
                    int nt = ntp * 2 + u;
                    uint32_t bfh[2] = { kh[u * 2], kh[u * 2 + 1] };
                    uint32_t bfl[2] = { kl[u * 2], kl[u * 2 + 1] };
                    mma16816(sc[nt], ah, bfh);
                    mma16816(sc[nt], ah, bfl);
                    mma16816(sc[nt], al, bfh);
                }
            }
        }

        const bool boundary = (kg0 + 63 >= qg0);
#pragma unroll
        for (int nt = 0; nt < 8; nt++) {
#pragma unroll
            for (int c = 0; c < 4; c++) {
                float v = sc[nt][c] * SCALE_L2E;
                if (boundary) {
                    int qg = qrow0 + (c >> 1) * 8;
                    int kg = kg0 + nt * 8 + (lane & 3) * 2 + (c & 1);
                    bool allow = ICL ? (kg < qg || (qg | kg) == 0) : (kg <= qg);
                    v = allow ? v : -1e30f;
                }
                sc[nt][c] = v;
            }
        }

#pragma unroll
        for (int ri = 0; ri < 2; ri++) {
            float mx = -1e30f;
#pragma unroll
            for (int nt = 0; nt < 8; nt++)
                mx = fmaxf(mx, fmaxf(sc[nt][ri * 2], sc[nt][ri * 2 + 1]));
            mx = fmaxf(mx, __shfl_xor_sync(0xffffffffu, mx, 1));
            mx = fmaxf(mx, __shfl_xor_sync(0xffffffffu, mx, 2));
            float mn = fmaxf(mrow[ri], mx);
            float corr = exp2p(mrow[ri] - mn);
            mrow[ri] = mn;
            float rs = 0.f;
#pragma unroll
            for (int nt = 0; nt < 8; nt++) {
                float p0 = exp2p(sc[nt][ri * 2] - mn);
                float p1 = exp2p(sc[nt][ri * 2 + 1] - mn);
                sc[nt][ri * 2] = p0;
                sc[nt][ri * 2 + 1] = p1;
                rs += p0 + p1;
            }
            rs += __shfl_xor_sync(0xffffffffu, rs, 1);
            rs += __shfl_xor_sync(0xffffffffu, rs, 2);
            lrow[ri] = lrow[ri] * corr + rs;
#pragma unroll
            for (int nt = 0; nt < 8; nt++) {
                out[nt][ri * 2] *= corr;
                out[nt][ri * 2 + 1] *= corr;
            }
        }

#pragma unroll
        for (int j = 0; j < 4; j++) {
            uint32_t aP[4];
            aP[0] = pk2(__float2bfloat16(sc[2 * j][0]),     __float2bfloat16(sc[2 * j][1]));
            aP[1] = pk2(__float2bfloat16(sc[2 * j][2]),     __float2bfloat16(sc[2 * j][3]));
            aP[2] = pk2(__float2bfloat16(sc[2 * j + 1][0]), __float2bfloat16(sc[2 * j + 1][1]));
            aP[3] = pk2(__float2bfloat16(sc[2 * j + 1][2]), __float2bfloat16(sc[2 * j + 1][3]));
#pragma unroll
            for (int nt2 = 0; nt2 < 4; nt2++) {
                uint32_t voff = (uint32_t)((j * 16 + (grp & 1) * 8 + rl) * FROWB
                                           + (nt2 * 16 + (grp >> 1) * 8) * 2);
                uint32_t bv[4];
                ldsm4t(bv[0], bv[1], bv[2], bv[3], sV_h + voff);
                {
                    uint32_t b0[2] = { bv[0], bv[1] }, b1[2] = { bv[2], bv[3] };
                    mma16816(out[nt2 * 2], aP, b0);
                    mma16816(out[nt2 * 2 + 1], aP, b1);
                }
                ldsm4t(bv[0], bv[1], bv[2], bv[3], sV_l + voff);
                {
                    uint32_t b0[2] = { bv[0], bv[1] }, b1[2] = { bv[2], bv[3] };
                    mma16816(out[nt2 * 2], aP, b0);
                    mma16816(out[nt2 * 2 + 1], aP, b1);
                }
            }
        }
        __syncthreads();
    }

#pragma unroll
    for (int ri = 0; ri < 2; ri++) {
        float inv = 1.0f / lrow[ri];
        size_t rbase = (tokb + qrow0 + ri * 8) * DAA + h * DHH + (lane & 3) * 2;
#pragma unroll
        for (int nt = 0; nt < 8; nt++) {
            float v0 = out[nt][ri * 2] * inv;
            float v1 = out[nt][ri * 2 + 1] * inv;
            __nv_bfloat16 h0, h1, l0, l1;
            split1(v0, h0, l0); split1(v1, h1, l1);
            *(uint32_t*)&Oh[rbase + nt * 8] = pk2(h0, h1);
            *(uint32_t*)&Ol[rbase + nt * 8] = pk2(l0, l1);
        }
    }
}

// ---------------- host driver ----------------
#define GETSYM(T, var, sym) T* var; { void* _p; cudaGetSymbolAddress(&_p, sym); var = (T*)_p; }

extern "C" void kernel_launch(void* const* d_in, const int* in_sizes, int n_in,
                              void* d_out, int out_size)
{
    const float* cov_in  = (const float*)d_in[0];
    const float* tgt_in  = (const float*)d_in[1];
    const float* fu_in   = (const float*)d_in[2];
    const float* fc1w    = (const float*)d_in[3];
    const float* fc1b    = (const float*)d_in[4];
    const float* fc2w    = (const float*)d_in[5];
    const float* fc2b    = (const float*)d_in[6];
    const float* icl_wq  = (const float*)d_in[7];
    const float* icl_wk  = (const float*)d_in[8];
    const float* icl_wv  = (const float*)d_in[9];
    const float* icl_wo  = (const float*)d_in[10];
    const float* cov_wq  = (const float*)d_in[11];
    const float* cov_wk  = (const float*)d_in[12];
    const float* cov_wv  = (const float*)d_in[13];
    const float* cov_wo  = (const float*)d_in[14];
    const float* ln_cm_g = (const float*)d_in[15];
    const float* ln_cm_b = (const float*)d_in[16];
    const float* ln_ia_g = (const float*)d_in[17];
    const float* ln_ia_b = (const float*)d_in[18];
    const float* ln_im_g = (const float*)d_in[19];
    const float* ln_im_b = (const float*)d_in[20];

    float* out_cov = (float*)d_out;
    float* out_tgt = out_cov + (size_t)NTOK * EE;
    float* out_fu  = out_tgt + (size_t)NTOK * EE;

    GETSYM(uint16_t, lnh, pLNh)    GETSYM(uint16_t, lnl, pLNl)
    GETSYM(uint16_t, ln2h, pLN2h)  GETSYM(uint16_t, ln2l, pLN2l)
    GETSYM(uint16_t, midh, pMIDh)  GETSYM(uint16_t, midl, pMIDl)
    GETSYM(uint16_t, mid2h, pMID2h) GETSYM(uint16_t, mid2l, pMID2l)
    GETSYM(uint16_t, qh, pQh)      GETSYM(uint16_t, ql, pQl)
    GETSYM(uint16_t, tgh, pTGTh)   GETSYM(uint16_t, tgl, pTGTl)
    GETSYM(uint16_t, aoIh, pAOIh)  GETSYM(uint16_t, aoIl, pAOIl)
    GETSYM(uint16_t, aoCh, pAOCh)  GETSYM(uint16_t, aoCl, pAOCl)
    GETSYM(uint16_t, fqIh, pFQIh)  GETSYM(uint16_t, fqIl, pFQIl)
    GETSYM(uint16_t, fkIh, pFKIh)  GETSYM(uint16_t, fkIl, pFKIl)
    GETSYM(uint16_t, fvIh, pFVIh)  GETSYM(uint16_t, fvIl, pFVIl)
    GETSYM(uint16_t, fqCh, pFQCh)  GETSYM(uint16_t, fqCl, pFQCl)
    GETSYM(uint16_t, fkCh, pFKCh)  GETSYM(uint16_t, fkCl, pFKCl)
    GETSYM(uint16_t, fvCh, pFVCh)  GETSYM(uint16_t, fvCl, pFVCl)
    GETSYM(uint16_t, w1h, pW1h)    GETSYM(uint16_t, w1l, pW1l)
    GETSYM(uint16_t, w2h, pW2h)    GETSYM(uint16_t, w2l, pW2l)
    GETSYM(uint16_t, iqkh, pIQKh)  GETSYM(uint16_t, iqkl, pIQKl)
    GETSYM(uint16_t, ivh, pIVh)    GETSYM(uint16_t, ivl, pIVl)
    GETSYM(uint16_t, ioh, pIOh)    GETSYM(uint16_t, iol, pIOl)
    GETSYM(uint16_t, cqkvh, pCQKVh) GETSYM(uint16_t, cqkvl, pCQKVl)
    GETSYM(uint16_t, coh, pCOh)    GETSYM(uint16_t, col, pCOl)

    static cudaStream_t s2 = nullptr;
    static cudaEvent_t evF = nullptr, evL = nullptr, evC = nullptr, evq = nullptr, evend = nullptr;
    if (!s2) {
        cudaStreamCreateWithFlags(&s2, cudaStreamNonBlocking);
        cudaEventCreateWithFlags(&evF, cudaEventDisableTiming);
        cudaEventCreateWithFlags(&evL, cudaEventDisableTiming);
        cudaEventCreateWithFlags(&evC, cudaEventDisableTiming);
        cudaEventCreateWithFlags(&evq, cudaEventDisableTiming);
        cudaEventCreateWithFlags(&evend, cudaEventDisableTiming);
        cudaFuncSetAttribute(gemm_tc<0>, cudaFuncAttributeMaxDynamicSharedMemorySize, SMEM_GEMM);
        cudaFuncSetAttribute(gemm_tc<1>, cudaFuncAttributeMaxDynamicSharedMemorySize, SMEM_GEMM);
        cudaFuncSetAttribute(gemm_tc<2>, cudaFuncAttributeMaxDynamicSharedMemorySize, SMEM_GEMM);
        cudaFuncSetAttribute(gemm_tc<3>, cudaFuncAttributeMaxDynamicSharedMemorySize, SMEM_GEMM);
        cudaFuncSetAttribute(gemm_tc<4>, cudaFuncAttributeMaxDynamicSharedMemorySize, SMEM_GEMM);
        cudaFuncSetAttribute(flash_mma<0>, cudaFuncAttributeMaxDynamicSharedMemorySize, SMEM_FLASH);
        cudaFuncSetAttribute(flash_mma<1>, cudaFuncAttributeMaxDynamicSharedMemorySize, SMEM_FLASH);
    }

    const dim3 thr(256);
    const dim3 gFC1(DMLP / 128, NTOK / 128);
    const dim3 gFC2(EE / 128, NTOK / 128);
    const dim3 gQK(8, NTOK / 128);
    const dim3 gV(4, NTOK / 128);
    const dim3 gQKV(12, NTOK / 128);
    const dim3 gWO(EE / 128, NTOK / 128);
    const dim3 gFLASH(SS / 128, BB * HH);

    RopeOut r0{};
    RopeOut rI { fqIh, fqIl, fkIh, fkIl, fvIh, fvIl, 0 };
    RopeOut rIV{ fqIh, fqIl, fkIh, fkIl, fvIh, fvIl, 1024 };
    RopeOut rC { fqCh, fqCl, fkCh, fkCl, fvCh, fvCl, 0 };

    ConvJobs cj;
    cj.src[0] = fc1w;   cj.dh[0] = w1h;              cj.dl[0] = w1l;              cj.K[0] = EE;   cj.N[0] = DMLP;
    cj.src[1] = fc2w;   cj.dh[1] = w2h;              cj.dl[1] = w2l;              cj.K[1] = DMLP; cj.N[1] = EE;
    cj.src[2] = icl_wq; cj.dh[2] = iqkh;             cj.dl[2] = iqkl;             cj.K[2] = EE;   cj.N[2] = DAA;
    cj.src[3] = icl_wk; cj.dh[3] = iqkh + 512 * EE;  cj.dl[3] = iqkl + 512 * EE;  cj.K[3] = EE;   cj.N[3] = DAA;
    cj.src[4] = icl_wv; cj.dh[4] = ivh;              cj.dl[4] = ivl;              cj.K[4] = EE;   cj.N[4] = DAA;
    cj.src[5] = cov_wq; cj.dh[5] = cqkvh;            cj.dl[5] = cqkvl;            cj.K[5] = EE;   cj.N[5] = DAA;
    cj.src[6] = cov_wk; cj.dh[6] = cqkvh + 512 * EE; cj.dl[6] = cqkvl + 512 * EE; cj.K[6] = EE;   cj.N[6] = DAA;
    cj.src[7] = cov_wv; cj.dh[7] = cqkvh + 1024 * EE;cj.dl[7] = cqkvl + 1024 * EE;cj.K[7] = EE;   cj.N[7] = DAA;
    cj.src[8] = icl_wo; cj.dh[8] = ioh;              cj.dl[8] = iol;              cj.K[8] = DAA;  cj.N[8] = EE;
    cj.src[9] = cov_wo; cj.dh[9] = coh;              cj.dl[9] = col;              cj.K[9] = DAA;  cj.N[9] = EE;

    // ---- fork s2 into the capture graph FIRST, then overlap conv (s2) with LNs (legacy) ----
    cudaEventRecord(evF, 0);
    cudaStreamWaitEvent(s2, evF, 0);
    conv_all<<<dim3(16, 32, 10), thr, 0, s2>>>(cj);
    cudaEventRecord(evC, s2);

    ln_split<<<NTOK, thr>>>(cov_in, ln_cm_g, ln_cm_b, lnh, lnl);
    ln_split<<<NTOK, thr>>>(fu_in, ln_im_g, ln_im_b, ln2h, ln2l);
    cudaEventRecord(evL, 0);

    cudaStreamWaitEvent(0, evC, 0);    // legacy needs weights
    cudaStreamWaitEvent(s2, evL, 0);   // s2 needs ln2 planes

    // ---- chain2 on s2: tgt = targets + MLP(LN(functional_update)); then ICL V ----
    gemm_tc<1><<<gFC1, thr, SMEM_GEMM, s2>>>(ln2h, ln2l, w1h, w1l, fc1b, nullptr,
                                             nullptr, mid2h, mid2l, r0, DMLP, EE, DMLP);
    gemm_tc<2><<<gFC2, thr, SMEM_GEMM, s2>>>(mid2h, mid2l, w2h, w2l, fc2b, tgt_in,
                                             out_tgt, tgh, tgl, r0, EE, DMLP, EE);
    gemm_tc<4><<<gV, thr, SMEM_GEMM, s2>>>(tgh, tgl, ivh, ivl, nullptr, nullptr,
                                           nullptr, nullptr, nullptr, rIV, DAA, EE, 0);

    // ---- chain1 on legacy: cov = covariates + MLP(LN(covariates)); q = LN(cov) ----
    gemm_tc<1><<<gFC1, thr, SMEM_GEMM>>>(lnh, lnl, w1h, w1l, fc1b, nullptr,
                                         nullptr, midh, midl, r0, DMLP, EE, DMLP);
    gemm_tc<2><<<gFC2, thr, SMEM_GEMM>>>(midh, midl, w2h, w2l, fc2b, cov_in,
                                         out_cov, nullptr, nullptr, r0, EE, DMLP, EE);
    ln_split<<<NTOK, thr>>>(out_cov, ln_ia_g, ln_ia_b, qh, ql);
    cudaEventRecord(evq, 0);

    // ---- ICL attention on s2 (needs q + tgt) ----
    cudaStreamWaitEvent(s2, evq, 0);
    gemm_tc<4><<<gQK, thr, SMEM_GEMM, s2>>>(qh, ql, iqkh, iqkl, nullptr, nullptr,
                                            nullptr, nullptr, nullptr, rI, 1024, EE, 0);
    flash_mma<1><<<gFLASH, thr, SMEM_FLASH, s2>>>(fqIh, fqIl, fkIh, fkIl, fvIh, fvIl, aoIh, aoIl);
    gemm_tc<3><<<gWO, thr, SMEM_GEMM, s2>>>(aoIh, aoIl, ioh, iol, nullptr, fu_in,
                                            out_fu, nullptr, nullptr, r0, EE, DAA, EE);
    cudaEventRecord(evend, s2);

    // ---- COV attention on legacy (needs only q) ----
    gemm_tc<4><<<gQKV, thr, SMEM_GEMM>>>(qh, ql, cqkvh, cqkvl, nullptr, nullptr,
                                         nullptr, nullptr, nullptr, rC, 1536, EE, 0);
    flash_mma<0><<<gFLASH, thr, SMEM_FLASH>>>(fqCh, fqCl, fkCh, fkCl, fvCh, fvCl, aoCh, aoCl);
    gemm_tc<3><<<gWO, thr, SMEM_GEMM>>>(aoCh, aoCl, coh, col, nullptr, out_cov,
                                        out_cov, nullptr, nullptr, r0, EE, DAA, EE);

    // join
    cudaStreamWaitEvent(0, evend, 0);
}

// round 13
// speedup vs baseline: 1.1419x; 1.0826x over previous
#include <cuda_runtime.h>
#include <cuda_bf16.h>
#include <math.h>
#include <stdint.h>

#define BB 2
#define SS 2048
#define EE 1024
#define HH 8
#define DHH 64
#define DAA 512
#define DMLP 2048
#define NTOK 4096
#define SCALE_ATTN 0.04419417382415922f
#define SCALE_L2E 0.06375944628228341f   // SCALE_ATTN * log2(e)
#define LN_EPS 1e-5f

// GEMM (round-8 proven config): 128x128 tile, warp 64x32, K-chunk 32, 2-stage,
// padded 80B rows (conflict-free ldmatrix).
#define ROWB 80
#define PLANE_B 10240
#define STAGE_B 40960
#define SMEM_GEMM (2 * STAGE_B)

// Flash: Q hi/lo staged once; KV stages carry Kh + Vh only (lo terms dropped
// by precision budget). Stage = 2 planes.
#define FROWB 144
#define FQPL 18432
#define FKPL 9216
#define FSTG 18432
#define SMEM_FLASH (2 * FQPL + 2 * FSTG)   // 73728

// ---------------- scratch ----------------
__device__ float g_qkvI[NTOK * 1536];
__device__ float g_qkvC[NTOK * 1536];

__device__ uint16_t pLNh[NTOK * EE],     pLNl[NTOK * EE];
__device__ uint16_t pLN2h[NTOK * EE],    pLN2l[NTOK * EE];
__device__ uint16_t pMIDh[NTOK * DMLP],  pMIDl[NTOK * DMLP];
__device__ uint16_t pMID2h[NTOK * DMLP], pMID2l[NTOK * DMLP];
__device__ uint16_t pQh[NTOK * EE],      pQl[NTOK * EE];
__device__ uint16_t pTGTh[NTOK * EE],    pTGTl[NTOK * EE];
__device__ uint16_t pAOIh[NTOK * DAA],   pAOIl[NTOK * DAA];
__device__ uint16_t pAOCh[NTOK * DAA],   pAOCl[NTOK * DAA];
__device__ uint16_t pFQIh[NTOK * DAA],   pFQIl[NTOK * DAA];
__device__ uint16_t pFKIh[NTOK * DAA];
__device__ uint16_t pFVIh[NTOK * DAA];
__device__ uint16_t pFQCh[NTOK * DAA],   pFQCl[NTOK * DAA];
__device__ uint16_t pFKCh[NTOK * DAA];
__device__ uint16_t pFVCh[NTOK * DAA];

__device__ uint16_t pW1h[DMLP * EE],    pW1l[DMLP * EE];
__device__ uint16_t pW2h[EE * DMLP],    pW2l[EE * DMLP];
__device__ uint16_t pIQKh[1024 * EE],   pIQKl[1024 * EE];
__device__ uint16_t pIVh[DAA * EE],     pIVl[DAA * EE];
__device__ uint16_t pIOh[EE * DAA],     pIOl[EE * DAA];
__device__ uint16_t pCQKVh[1536 * EE],  pCQKVl[1536 * EE];
__device__ uint16_t pCOh[EE * DAA],     pCOl[EE * DAA];

// ---------------- helpers ----------------
__device__ __forceinline__ uint32_t pk2(__nv_bfloat16 a, __nv_bfloat16 b) {
    uint16_t ra = *reinterpret_cast<uint16_t*>(&a);
    uint16_t rb = *reinterpret_cast<uint16_t*>(&b);
    return (uint32_t)ra | ((uint32_t)rb << 16);
}
__device__ __forceinline__ void split1(float x, __nv_bfloat16& h, __nv_bfloat16& l) {
    h = __float2bfloat16(x);
    l = __float2bfloat16(x - __bfloat162float(h));
}
__device__ __forceinline__ void mma16816(float* c, const uint32_t* a, const uint32_t* b) {
    asm volatile(
        "mma.sync.aligned.m16n8k16.row.col.f32.bf16.bf16.f32 "
        "{%0,%1,%2,%3}, {%4,%5,%6,%7}, {%8,%9}, {%0,%1,%2,%3};"
        : "+f"(c[0]), "+f"(c[1]), "+f"(c[2]), "+f"(c[3])
        : "r"(a[0]), "r"(a[1]), "r"(a[2]), "r"(a[3]), "r"(b[0]), "r"(b[1]));
}
__device__ __forceinline__ void ldsm4(uint32_t& r0, uint32_t& r1, uint32_t& r2, uint32_t& r3,
                                      uint32_t addr) {
    asm volatile("ldmatrix.sync.aligned.m8n8.x4.shared.b16 {%0,%1,%2,%3}, [%4];"
                 : "=r"(r0), "=r"(r1), "=r"(r2), "=r"(r3) : "r"(addr));
}
__device__ __forceinline__ void ldsm4t(uint32_t& r0, uint32_t& r1, uint32_t& r2, uint32_t& r3,
                                       uint32_t addr) {
    asm volatile("ldmatrix.sync.aligned.m8n8.x4.trans.shared.b16 {%0,%1,%2,%3}, [%4];"
                 : "=r"(r0), "=r"(r1), "=r"(r2), "=r"(r3) : "r"(addr));
}
__device__ __forceinline__ void cpa16(uint32_t s, const void* g) {
    asm volatile("cp.async.ca.shared.global [%0], [%1], 16;" :: "r"(s), "l"(g));
}
__device__ __forceinline__ void cpa_commit() {
    asm volatile("cp.async.commit_group;" ::: "memory");
}
template<int N>
__device__ __forceinline__ void cpa_wait() {
    asm volatile("cp.async.wait_group %0;" :: "n"(N) : "memory");
}
__device__ __forceinline__ float exp2p(float x) {
    x = fmaxf(x, -80.f);
    float n = rintf(x);
    float f = x - n;
    float p = 1.3333558146428443e-3f;
    p = p * f + 9.618129107628477e-3f;
    p = p * f + 5.550410866482158e-2f;
    p = p * f + 2.402265069591007e-1f;
    p = p * f + 6.931471805599453e-1f;
    p = p * f + 1.0f;
    return p * __int_as_float(((int)n + 127) << 23);
}

__device__ __forceinline__ float block_reduce_sum(float v) {
    __shared__ float red[32];
    int lane = threadIdx.x & 31, w = threadIdx.x >> 5;
#pragma unroll
    for (int o = 16; o > 0; o >>= 1) v += __shfl_xor_sync(0xffffffffu, v, o);
    __syncthreads();
    if (lane == 0) red[w] = v;
    __syncthreads();
    v = (lane < 8) ? red[lane] : 0.f;
#pragma unroll
    for (int o = 16; o > 0; o >>= 1) v += __shfl_xor_sync(0xffffffffu, v, o);
    return v;
}

// ---------------- LayerNorm -> bf16 hi/lo planes ----------------
__global__ void ln_split(const float* __restrict__ x, const float* __restrict__ g,
                         const float* __restrict__ b,
                         uint16_t* __restrict__ oh, uint16_t* __restrict__ ol) {
    int row = blockIdx.x, t = threadIdx.x;
    float4 v = *(const float4*)&x[(size_t)row * EE + 4 * t];
    float s = v.x + v.y + v.z + v.w;
    float mean = block_reduce_sum(s) * (1.0f / EE);
    float d0 = v.x - mean, d1 = v.y - mean, d2 = v.z - mean, d3 = v.w - mean;
    float var = block_reduce_sum(d0 * d0 + d1 * d1 + d2 * d2 + d3 * d3) * (1.0f / EE);
    float rstd = rsqrtf(var + LN_EPS);
    float4 gg = *(const float4*)&g[4 * t];
    float4 bb = *(const float4*)&b[4 * t];
    float y0 = d0 * rstd * gg.x + bb.x;
    float y1 = d1 * rstd * gg.y + bb.y;
    float y2 = d2 * rstd * gg.z + bb.z;
    float y3 = d3 * rstd * gg.w + bb.w;
    __nv_bfloat16 h0, h1, h2, h3, l0, l1, l2, l3;
    split1(y0, h0, l0); split1(y1, h1, l1); split1(y2, h2, l2); split1(y3, h3, l3);
    size_t off = (size_t)row * EE + 4 * t;
    *(uint2*)&oh[off] = make_uint2(pk2(h0, h1), pk2(h2, h3));
    *(uint2*)&ol[off] = make_uint2(pk2(l0, l1), pk2(l2, l3));
}

// ---------------- weight conversion, single launch ----------------
__device__ __forceinline__ void convB_body(const float* __restrict__ W,
                                           uint16_t* __restrict__ Bh,
                                           uint16_t* __restrict__ Bl, int K, int N) {
    __shared__ float ts[64][129];
    int nt = blockIdx.x, kt = blockIdx.y, tid = threadIdx.x;
    int k0 = kt * 64, n0 = nt * 128;
#pragma unroll
    for (int i = 0; i < 32; i++) {
        int idx = tid + i * 256;
        int kk = idx >> 7, nn = idx & 127;
        ts[kk][nn] = W[(size_t)(k0 + kk) * N + n0 + nn];
    }
    __syncthreads();
#pragma unroll
    for (int j = 0; j < 4; j++) {
        int job = tid + j * 256;
        int n = job >> 3, kg = (job & 7) * 8;
        __nv_bfloat16 h[8], l[8];
#pragma unroll
        for (int i = 0; i < 8; i++) split1(ts[kg + i][n], h[i], l[i]);
        uint4 uh = make_uint4(pk2(h[0], h[1]), pk2(h[2], h[3]), pk2(h[4], h[5]), pk2(h[6], h[7]));
        uint4 ul = make_uint4(pk2(l[0], l[1]), pk2(l[2], l[3]), pk2(l[4], l[5]), pk2(l[6], l[7]));
        size_t off = (size_t)(n0 + n) * K + k0 + kg;
        *(uint4*)&Bh[off] = uh;
        *(uint4*)&Bl[off] = ul;
    }
}

struct ConvJobs {
    const float* src[10];
    uint16_t* dh[10];
    uint16_t* dl[10];
    int K[10], N[10];
};
__global__ void conv_all(ConvJobs j) {
    int w = blockIdx.z;
    int K = j.K[w], N = j.N[w];
    if (blockIdx.x * 128 >= N || blockIdx.y * 64 >= K) return;
    convB_body(j.src[w], j.dh[w], j.dl[w], K, N);
}

// ---------------- HMMA bf16-split GEMM (round-8 mainloop) ----------------
// MODE 0: C=AB(fp32, ldC)  1: planes=gelu(AB+bias)  2: C=AB+bias+R (+planes)  3: C=AB+R
template<int MODE>
__global__ void __launch_bounds__(256, 2) gemm_tc(
    const uint16_t* __restrict__ Ah, const uint16_t* __restrict__ Al,
    const uint16_t* __restrict__ Bh, const uint16_t* __restrict__ Bl,
    const float* __restrict__ bias, const float* __restrict__ R,
    float* __restrict__ C, uint16_t* __restrict__ Ch, uint16_t* __restrict__ Cl,
    int N, int K, int ldC)
{
    extern __shared__ char sm[];
    const uint32_t sbase = (uint32_t)__cvta_generic_to_shared(sm);
    const int tid = threadIdx.x;
    const int warp = tid >> 5, lane = tid & 31;
    const int wm = warp & 1, wn = warp >> 1;
    const int m0 = blockIdx.y * 128, n0 = blockIdx.x * 128;
    const int KT = K >> 5;

    const uint16_t* gA[2] = { Ah + (size_t)m0 * K, Al + (size_t)m0 * K };
    const uint16_t* gB[2] = { Bh + (size_t)n0 * K, Bl + (size_t)n0 * K };

    const int rl = lane & 7, grp = lane >> 3;
    const int a_r = rl + (grp & 1) * 8;
    const int a_c = (grp >> 1) * 8;
    const int b_r = rl + ((grp >> 1) & 1) * 8;
    const int b_c = (grp & 1) * 8;

    float acc[4][4][4];
#pragma unroll
    for (int i = 0; i < 4; i++)
#pragma unroll
        for (int j = 0; j < 4; j++)
#pragma unroll
            for (int k = 0; k < 4; k++) acc[i][j][k] = 0.f;

    auto issue = [&](int stage, int kt) {
        uint32_t s0 = sbase + stage * STAGE_B;
        int kel = kt * 32;
#pragma unroll
        for (int pl = 0; pl < 4; pl++) {
            const uint16_t* g = (pl < 2) ? gA[pl] : gB[pl - 2];
#pragma unroll
            for (int i = 0; i < 2; i++) {
                int seg = tid + i * 256;
                int m = seg >> 2, s = seg & 3;
                cpa16(s0 + pl * PLANE_B + m * ROWB + s * 16,
                      g + (size_t)m * K + kel + s * 8);
            }
        }
        cpa_commit();
    };

    issue(0, 0);
    for (int kt = 0; kt < KT; kt++) {
        int st = kt & 1;
        if (kt + 1 < KT) { issue(st ^ 1, kt + 1); cpa_wait<1>(); }
        else             { cpa_wait<0>(); }
        __syncthreads();

        uint32_t sA_h = sbase + st * STAGE_B;
        uint32_t sA_l = sA_h + PLANE_B;
        uint32_t sB_h = sA_h + 2 * PLANE_B;
        uint32_t sB_l = sA_h + 3 * PLANE_B;

#pragma unroll
        for (int ks = 0; ks < 2; ks++) {
            const int kk = ks * 16;
            uint32_t bh[2][4], bl[2][4];
#pragma unroll
            for (int ntp = 0; ntp < 2; ntp++) {
                uint32_t off = (uint32_t)((wn * 32 + ntp * 16 + b_r) * ROWB + (kk + b_c) * 2);
                ldsm4(bh[ntp][0], bh[ntp][1], bh[ntp][2], bh[ntp][3], sB_h + off);
                ldsm4(bl[ntp][0], bl[ntp][1], bl[ntp][2], bl[ntp][3], sB_l + off);
            }
#pragma unroll
            for (int mt = 0; mt < 4; mt++) {
                uint32_t off = (uint32_t)((wm * 64 + mt * 16 + a_r) * ROWB + (kk + a_c) * 2);
                uint32_t ah[4], al[4];
                ldsm4(ah[0], ah[1], ah[2], ah[3], sA_h + off);
                ldsm4(al[0], al[1], al[2], al[3], sA_l + off);
#pragma unroll
                for (int nt = 0; nt < 4; nt++) {
                    uint32_t bfh[2] = { bh[nt >> 1][(nt & 1) * 2], bh[nt >> 1][(nt & 1) * 2 + 1] };
                    uint32_t bfl[2] = { bl[nt >> 1][(nt & 1) * 2], bl[nt >> 1][(nt & 1) * 2 + 1] };
                    mma16816(acc[mt][nt], ah, bfh);
                    mma16816(acc[mt][nt], ah, bfl);
                    mma16816(acc[mt][nt], al, bfh);
                }
            }
        }
        __syncthreads();
    }

    const int r = lane >> 2, q = lane & 3;
#pragma unroll
    for (int mt = 0; mt < 4; mt++) {
#pragma unroll
        for (int nt = 0; nt < 4; nt++) {
            int row = m0 + wm * 64 + mt * 16 + r;
            int col = n0 + wn * 32 + nt * 8 + q * 2;
#pragma unroll
            for (int half = 0; half < 2; half++) {
                int rr2 = row + half * 8;
                float v0 = acc[mt][nt][half * 2 + 0];
                float v1 = acc[mt][nt][half * 2 + 1];
                size_t gidx = (size_t)rr2 * ldC + col;
                if (MODE == 1) {
                    v0 += bias[col];
                    v1 += bias[col + 1];
                    v0 = 0.5f * v0 * (1.0f + erff(v0 * 0.70710678118654752f));
                    v1 = 0.5f * v1 * (1.0f + erff(v1 * 0.70710678118654752f));
                    __nv_bfloat16 h0, h1, l0, l1;
                    split1(v0, h0, l0); split1(v1, h1, l1);
                    *(uint32_t*)&Ch[gidx] = pk2(h0, h1);
                    *(uint32_t*)&Cl[gidx] = pk2(l0, l1);
                } else {
                    if (MODE == 2) {
                        float2 rv = *(const float2*)&R[gidx];
                        v0 += bias[col] + rv.x;
                        v1 += bias[col + 1] + rv.y;
                    } else if (MODE == 3) {
                        float2 rv = *(const float2*)&R[gidx];
                        v0 += rv.x;
                        v1 += rv.y;
                    }
                    *(float2*)&C[gidx] = make_float2(v0, v1);
                    if (MODE == 2 && Ch) {
                        __nv_bfloat16 h0, h1, l0, l1;
                        split1(v0, h0, l0); split1(v1, h1, l1);
                        *(uint32_t*)&Ch[gidx] = pk2(h0, h1);
                        *(uint32_t*)&Cl[gidx] = pk2(l0, l1);
                    }
                }
            }
        }
    }
}

// ---------------- RoPE + split to flash planes (Q hi/lo, K hi, V hi) ----------------
__global__ void rope_split(const float* __restrict__ qkv,
                           uint16_t* __restrict__ fqh, uint16_t* __restrict__ fql,
                           uint16_t* __restrict__ fkh, uint16_t* __restrict__ fvh) {
    int row = blockIdx.x, t = threadIdx.x;
    int i = t & 31;
    int s = row & (SS - 1);
    float inv = __expf(-logf(10000.0f) * ((float)i / 32.0f));
    float ang = (float)s * inv;
    float c = cosf(ang), sn = sinf(ang);
    const float* base = qkv + (size_t)row * 1536;
    size_t dst = (size_t)row * DAA + 2 * t;

    float x1 = base[2 * t], x2 = base[2 * t + 1];
    float o1 = x1 * c - x2 * sn, o2 = x1 * sn + x2 * c;
    __nv_bfloat16 h0, h1, l0, l1;
    split1(o1, h0, l0); split1(o2, h1, l1);
    *(uint32_t*)&fqh[dst] = pk2(h0, h1);
    *(uint32_t*)&fql[dst] = pk2(l0, l1);

    x1 = base[512 + 2 * t]; x2 = base[512 + 2 * t + 1];
    o1 = x1 * c - x2 * sn; o2 = x1 * sn + x2 * c;
    *(uint32_t*)&fkh[dst] = pk2(__float2bfloat16(o1), __float2bfloat16(o2));

    x1 = base[1024 + 2 * t]; x2 = base[1024 + 2 * t + 1];
    *(uint32_t*)&fvh[dst] = pk2(__float2bfloat16(x1), __float2bfloat16(x2));
}

// ---------------- Flash attention: Q hi/lo, K hi, V hi; HMMA + poly exp2 ----------------
template<int ICL>
__global__ void __launch_bounds__(256) flash_mma(
    const uint16_t* __restrict__ Qh, const uint16_t* __restrict__ Ql,
    const uint16_t* __restrict__ Kh, const uint16_t* __restrict__ Vh,
    uint16_t* __restrict__ Oh, uint16_t* __restrict__ Ol)
{
    extern __shared__ char sm[];
    const uint32_t sb = (uint32_t)__cvta_generic_to_shared(sm);
    const uint32_t sQh = sb, sQl = sb + FQPL;
    const uint32_t sKV = sb + 2 * FQPL;
    const int tid = threadIdx.x, warp = tid >> 5, lane = tid & 31;
    const int qt = gridDim.x - 1 - blockIdx.x;
    const int bh = blockIdx.y, b = bh >> 3, h = bh & 7;
    const int qg0 = qt * 128;
    const size_t tokb = (size_t)b * SS;
    const int rb = warp * 16;

    const int rl = lane & 7, grp = lane >> 3;
    const int a_r = rl + (grp & 1) * 8;
    const int a_c = (grp >> 1) * 8;
    const int b_r = rl + ((grp >> 1) & 1) * 8;
    const int b_c = (grp & 1) * 8;

#pragma unroll
    for (int i = 0; i < 8; i++) {
        int job = tid + i * 256;
        int pl = job >> 10, r = (job >> 3) & 127, s = job & 7;
        const uint16_t* g = (pl ? Ql : Qh) + (tokb + qg0 + r) * DAA + h * DHH + s * 8;
        cpa16((pl ? sQl : sQh) + r * FROWB + s * 16, g);
    }
    cpa_commit();

    float out[8][4];
#pragma unroll
    for (int i = 0; i < 8; i++)
#pragma unroll
        for (int j = 0; j < 4; j++) out[i][j] = 0.f;
    float mrow[2] = { -1e30f, -1e30f }, lrow[2] = { 0.f, 0.f };

    const int ktmax = (qg0 + 127) >> 6;

    auto issueKV = [&](int st, int kt) {
        uint32_t s0 = sKV + st * FSTG;
        int kg0 = kt * 64;
#pragma unroll
        for (int i = 0; i < 4; i++) {
            int job = tid + i * 256;          // 1024 jobs: 2 planes x 64 rows x 8 segs
            int pl = job >> 9, r = (job >> 3) & 63, s = job & 7;
            const uint16_t* gp = (pl == 0) ? Kh : Vh;
            cpa16(s0 + pl * FKPL + r * FROWB + s * 16,
                  gp + (tokb + kg0 + r) * DAA + h * DHH + s * 8);
        }
        cpa_commit();
    };
    issueKV(0, 0);

    const int qrow0 = qg0 + rb + (lane >> 2);

    for (int kt = 0; kt <= ktmax; kt++) {
        int st = kt & 1;
        int kg0 = kt * 64;
        if (kt < ktmax) { issueKV(st ^ 1, kt + 1); cpa_wait<1>(); }
        else            { cpa_wait<0>(); }
        __syncthreads();

        uint32_t sK_h = sKV + st * FSTG;
        uint32_t sV_h = sK_h + FKPL;

        float sc[8][4];
#pragma unroll
        for (int i = 0; i < 8; i++)
#pragma unroll
            for (int j = 0; j < 4; j++) sc[i][j] = 0.f;
#pragma unroll
        for (int k16 = 0; k16 < 4; k16++) {
            uint32_t qoff = (uint32_t)((rb + a_r) * FROWB + (k16 * 16 + a_c) * 2);
            uint32_t ah[4], al[4];
            ldsm4(ah[0], ah[1], ah[2], ah[3], sQh + qoff);
            ldsm4(al[0], al[1], al[2], al[3], sQl + qoff);
#pragma unroll
            for (int ntp = 0; ntp < 4; ntp++) {
                uint32_t koff = (uint32_t)((ntp * 16 + b_r) * FROWB + (k16 * 16 + b_c) * 2);
                uint32_t kh[4];
                ldsm4(kh[0], kh[1], kh[2], kh[3], sK_h + koff);
#pragma unroll
                for (int u = 0; u < 2; u++) {
                    int nt = ntp * 2 + u;
                    uint32_t bfh[2] = { kh[u * 2], kh[u * 2 + 1] };
                    mma16816(sc[nt], ah, bfh);
                    mma16816(sc[nt], al, bfh);
                }
            }
        }

        const bool boundary = (kg0 + 63 >= qg0);
#pragma unroll
        for (int nt = 0; nt < 8; nt++) {
#pragma unroll
            for (int c = 0; c < 4; c++) {
                float v = sc[nt][c] * SCALE_L2E;
                if (boundary) {
                    int qg = qrow0 + (c >> 1) * 8;
                    int kg = kg0 + nt * 8 + (lane & 3) * 2 + (c & 1);
                    bool allow = ICL ? (kg < qg || (qg | kg) == 0) : (kg <= qg);
                    v = allow ? v : -1e30f;
                }
                sc[nt][c] = v;
            }
        }

#pragma unroll
        for (int ri = 0; ri < 2; ri++) {
            float mx = -1e30f;
#pragma unroll
            for (int nt = 0; nt < 8; nt++)
                mx = fmaxf(mx, fmaxf(sc[nt][ri * 2], sc[nt][ri * 2 + 1]));
            mx = fmaxf(mx, __shfl_xor_sync(0xffffffffu, mx, 1));
            mx = fmaxf(mx, __shfl_xor_sync(0xffffffffu, mx, 2));
            float mn = fmaxf(mrow[ri], mx);
            float corr = exp2p(mrow[ri] - mn);
            mrow[ri] = mn;
            float rs = 0.f;
#pragma unroll
            for (int nt = 0; nt < 8; nt++) {
                float p0 = exp2p(sc[nt][ri * 2] - mn);
                float p1 = exp2p(sc[nt][ri * 2 + 1] - mn);
                sc[nt][ri * 2] = p0;
                sc[nt][ri * 2 + 1] = p1;
                rs += p0 + p1;
            }
            rs += __shfl_xor_sync(0xffffffffu, rs, 1);
            rs += __shfl_xor_sync(0xffffffffu, rs, 2);
            lrow[ri] = lrow[ri] * corr + rs;
#pragma unroll
            for (int nt = 0; nt < 8; nt++) {
                out[nt][ri * 2] *= corr;
                out[nt][ri * 2 + 1] *= corr;
            }
        }

#pragma unroll
        for (int j = 0; j < 4; j++) {
            uint32_t aP[4];
            aP[0] = pk2(__float2bfloat16(sc[2 * j][0]),     __float2bfloat16(sc[2 * j][1]));
            aP[1] = pk2(__float2bfloat16(sc[2 * j][2]),     __float2bfloat16(sc[2 * j][3]));
            aP[2] = pk2(__float2bfloat16(sc[2 * j + 1][0]), __float2bfloat16(sc[2 * j + 1][1]));
            aP[3] = pk2(__float2bfloat16(sc[2 * j + 1][2]), __float2bfloat16(sc[2 * j + 1][3]));
#pragma unroll
            for (int nt2 = 0; nt2 < 4; nt2++) {
                uint32_t voff = (uint32_t)((j * 16 + (grp & 1) * 8 + rl) * FROWB
                                           + (nt2 * 16 + (grp >> 1) * 8) * 2);
                uint32_t bv[4];
                ldsm4t(bv[0], bv[1], bv[2], bv[3], sV_h + voff);
                uint32_t b0[2] = { bv[0], bv[1] }, b1[2] = { bv[2], bv[3] };
                mma16816(out[nt2 * 2], aP, b0);
                mma16816(out[nt2 * 2 + 1], aP, b1);
            }
        }
        __syncthreads();
    }

#pragma unroll
    for (int ri = 0; ri < 2; ri++) {
        float inv = 1.0f / lrow[ri];
        size_t rbase = (tokb + qrow0 + ri * 8) * DAA + h * DHH + (lane & 3) * 2;
#pragma unroll
        for (int nt = 0; nt < 8; nt++) {
            float v0 = out[nt][ri * 2] * inv;
            float v1 = out[nt][ri * 2 + 1] * inv;
            __nv_bfloat16 h0, h1, l0, l1;
            split1(v0, h0, l0); split1(v1, h1, l1);
            *(uint32_t*)&Oh[rbase + nt * 8] = pk2(h0, h1);
            *(uint32_t*)&Ol[rbase + nt * 8] = pk2(l0, l1);
        }
    }
}

// ---------------- host driver ----------------
#define GETSYM(T, var, sym) T* var; { void* _p; cudaGetSymbolAddress(&_p, sym); var = (T*)_p; }

extern "C" void kernel_launch(void* const* d_in, const int* in_sizes, int n_in,
                              void* d_out, int out_size)
{
    const float* cov_in  = (const float*)d_in[0];
    const float* tgt_in  = (const float*)d_in[1];
    const float* fu_in   = (const float*)d_in[2];
    const float* fc1w    = (const float*)d_in[3];
    const float* fc1b    = (const float*)d_in[4];
    const float* fc2w    = (const float*)d_in[5];
    const float* fc2b    = (const float*)d_in[6];
    const float* icl_wq  = (const float*)d_in[7];
    const float* icl_wk  = (const float*)d_in[8];
    const float* icl_wv  = (const float*)d_in[9];
    const float* icl_wo  = (const float*)d_in[10];
    const float* cov_wq  = (const float*)d_in[11];
    const float* cov_wk  = (const float*)d_in[12];
    const float* cov_wv  = (const float*)d_in[13];
    const float* cov_wo  = (const float*)d_in[14];
    const float* ln_cm_g = (const float*)d_in[15];
    const float* ln_cm_b = (const float*)d_in[16];
    const float* ln_ia_g = (const float*)d_in[17];
    const float* ln_ia_b = (const float*)d_in[18];
    const float* ln_im_g = (const float*)d_in[19];
    const float* ln_im_b = (const float*)d_in[20];

    float* out_cov = (float*)d_out;
    float* out_tgt = out_cov + (size_t)NTOK * EE;
    float* out_fu  = out_tgt + (size_t)NTOK * EE;

    GETSYM(float, qkvI, g_qkvI)    GETSYM(float, qkvC, g_qkvC)
    GETSYM(uint16_t, lnh, pLNh)    GETSYM(uint16_t, lnl, pLNl)
    GETSYM(uint16_t, ln2h, pLN2h)  GETSYM(uint16_t, ln2l, pLN2l)
    GETSYM(uint16_t, midh, pMIDh)  GETSYM(uint16_t, midl, pMIDl)
    GETSYM(uint16_t, mid2h, pMID2h) GETSYM(uint16_t, mid2l, pMID2l)
    GETSYM(uint16_t, qh, pQh)      GETSYM(uint16_t, ql, pQl)
    GETSYM(uint16_t, tgh, pTGTh)   GETSYM(uint16_t, tgl, pTGTl)
    GETSYM(uint16_t, aoIh, pAOIh)  GETSYM(uint16_t, aoIl, pAOIl)
    GETSYM(uint16_t, aoCh, pAOCh)  GETSYM(uint16_t, aoCl, pAOCl)
    GETSYM(uint16_t, fqIh, pFQIh)  GETSYM(uint16_t, fqIl, pFQIl)
    GETSYM(uint16_t, fkIh, pFKIh)  GETSYM(uint16_t, fvIh, pFVIh)
    GETSYM(uint16_t, fqCh, pFQCh)  GETSYM(uint16_t, fqCl, pFQCl)
    GETSYM(uint16_t, fkCh, pFKCh)  GETSYM(uint16_t, fvCh, pFVCh)
    GETSYM(uint16_t, w1h, pW1h)    GETSYM(uint16_t, w1l, pW1l)
    GETSYM(uint16_t, w2h, pW2h)    GETSYM(uint16_t, w2l, pW2l)
    GETSYM(uint16_t, iqkh, pIQKh)  GETSYM(uint16_t, iqkl, pIQKl)
    GETSYM(uint16_t, ivh, pIVh)    GETSYM(uint16_t, ivl, pIVl)
    GETSYM(uint16_t, ioh, pIOh)    GETSYM(uint16_t, iol, pIOl)
    GETSYM(uint16_t, cqkvh, pCQKVh) GETSYM(uint16_t, cqkvl, pCQKVl)
    GETSYM(uint16_t, coh, pCOh)    GETSYM(uint16_t, col, pCOl)

    static cudaStream_t s2 = nullptr;
    static cudaEvent_t ev0 = nullptr, evq = nullptr, evend = nullptr;
    if (!s2) {
        cudaStreamCreateWithFlags(&s2, cudaStreamNonBlocking);
        cudaEventCreateWithFlags(&ev0, cudaEventDisableTiming);
        cudaEventCreateWithFlags(&evq, cudaEventDisableTiming);
        cudaEventCreateWithFlags(&evend, cudaEventDisableTiming);
        cudaFuncSetAttribute(gemm_tc<0>, cudaFuncAttributeMaxDynamicSharedMemorySize, SMEM_GEMM);
        cudaFuncSetAttribute(gemm_tc<1>, cudaFuncAttributeMaxDynamicSharedMemorySize, SMEM_GEMM);
        cudaFuncSetAttribute(gemm_tc<2>, cudaFuncAttributeMaxDynamicSharedMemorySize, SMEM_GEMM);
        cudaFuncSetAttribute(gemm_tc<3>, cudaFuncAttributeMaxDynamicSharedMemorySize, SMEM_GEMM);
        cudaFuncSetAttribute(flash_mma<0>, cudaFuncAttributeMaxDynamicSharedMemorySize, SMEM_FLASH);
        cudaFuncSetAttribute(flash_mma<1>, cudaFuncAttributeMaxDynamicSharedMemorySize, SMEM_FLASH);
    }

    const dim3 thr(256);
    const dim3 gFC1(DMLP / 128, NTOK / 128);
    const dim3 gFC2(EE / 128, NTOK / 128);
    const dim3 gQK(8, NTOK / 128);
    const dim3 gV(4, NTOK / 128);
    const dim3 gQKV(12, NTOK / 128);
    const dim3 gWO(EE / 128, NTOK / 128);
    const dim3 gFLASH(SS / 128, BB * HH);

    // ---- all weight conversions, one launch ----
    ConvJobs cj;
    cj.src[0] = fc1w;   cj.dh[0] = w1h;              cj.dl[0] = w1l;              cj.K[0] = EE;   cj.N[0] = DMLP;
    cj.src[1] = fc2w;   cj.dh[1] = w2h;              cj.dl[1] = w2l;              cj.K[1] = DMLP; cj.N[1] = EE;
    cj.src[2] = icl_wq; cj.dh[2] = iqkh;             cj.dl[2] = iqkl;             cj.K[2] = EE;   cj.N[2] = DAA;
    cj.src[3] = icl_wk; cj.dh[3] = iqkh + 512 * EE;  cj.dl[3] = iqkl + 512 * EE;  cj.K[3] = EE;   cj.N[3] = DAA;
    cj.src[4] = icl_wv; cj.dh[4] = ivh;              cj.dl[4] = ivl;              cj.K[4] = EE;   cj.N[4] = DAA;
    cj.src[5] = cov_wq; cj.dh[5] = cqkvh;            cj.dl[5] = cqkvl;            cj.K[5] = EE;   cj.N[5] = DAA;
    cj.src[6] = cov_wk; cj.dh[6] = cqkvh + 512 * EE; cj.dl[6] = cqkvl + 512 * EE; cj.K[6] = EE;   cj.N[6] = DAA;
    cj.src[7] = cov_wv; cj.dh[7] = cqkvh + 1024 * EE;cj.dl[7] = cqkvl + 1024 * EE;cj.K[7] = EE;   cj.N[7] = DAA;
    cj.src[8] = icl_wo; cj.dh[8] = ioh;              cj.dl[8] = iol;              cj.K[8] = DAA;  cj.N[8] = EE;
    cj.src[9] = cov_wo; cj.dh[9] = coh;              cj.dl[9] = col;              cj.K[9] = DAA;  cj.N[9] = EE;
    conv_all<<<dim3(16, 32, 10), thr>>>(cj);
    cudaEventRecord(ev0, 0);
    cudaStreamWaitEvent(s2, ev0, 0);

    // ---- chain2 on s2: tgt = targets + MLP(LN(functional_update)) ----
    ln_split<<<NTOK, thr, 0, s2>>>(fu_in, ln_im_g, ln_im_b, ln2h, ln2l);
    gemm_tc<1><<<gFC1, thr, SMEM_GEMM, s2>>>(ln2h, ln2l, w1h, w1l, fc1b, nullptr,
                                             nullptr, mid2h, mid2l, DMLP, EE, DMLP);
    gemm_tc<2><<<gFC2, thr, SMEM_GEMM, s2>>>(mid2h, mid2l, w2h, w2l, fc2b, tgt_in,
                                             out_tgt, tgh, tgl, EE, DMLP, EE);
    // V-projection depends only on tgt — run before waiting for q
    gemm_tc<0><<<gV, thr, SMEM_GEMM, s2>>>(tgh, tgl, ivh, ivl, nullptr, nullptr,
                                           qkvI + 1024, nullptr, nullptr, DAA, EE, 1536);

    // ---- chain1 on legacy: cov = covariates + MLP(LN(covariates)); q = LN(cov) ----
    ln_split<<<NTOK, thr>>>(cov_in, ln_cm_g, ln_cm_b, lnh, lnl);
    gemm_tc<1><<<gFC1, thr, SMEM_GEMM>>>(lnh, lnl, w1h, w1l, fc1b, nullptr,
                                         nullptr, midh, midl, DMLP, EE, DMLP);
    gemm_tc<2><<<gFC2, thr, SMEM_GEMM>>>(midh, midl, w2h, w2l, fc2b, cov_in,
                                         out_cov, nullptr, nullptr, EE, DMLP, EE);
    ln_split<<<NTOK, thr>>>(out_cov, ln_ia_g, ln_ia_b, qh, ql);
    cudaEventRecord(evq, 0);

    // ---- ICL attention on s2 (needs q + tgt) ----
    cudaStreamWaitEvent(s2, evq, 0);
    gemm_tc<0><<<gQK, thr, SMEM_GEMM, s2>>>(qh, ql, iqkh, iqkl, nullptr, nullptr,
                                            qkvI, nullptr, nullptr, 1024, EE, 1536);
    rope_split<<<NTOK, thr, 0, s2>>>(qkvI, fqIh, fqIl, fkIh, fvIh);
    flash_mma<1><<<gFLASH, thr, SMEM_FLASH, s2>>>(fqIh, fqIl, fkIh, fvIh, aoIh, aoIl);
    gemm_tc<3><<<gWO, thr, SMEM_GEMM, s2>>>(aoIh, aoIl, ioh, iol, nullptr, fu_in,
                                            out_fu, nullptr, nullptr, EE, DAA, EE);
    cudaEventRecord(evend, s2);

    // ---- COV attention on legacy (needs only q) ----
    gemm_tc<0><<<gQKV, thr, SMEM_GEMM>>>(qh, ql, cqkvh, cqkvl, nullptr, nullptr,
                                         qkvC, nullptr, nullptr, 1536, EE, 1536);
    rope_split<<<NTOK, thr>>>(qkvC, fqCh, fqCl, fkCh, fvCh);
    flash_mma<0><<<gFLASH, thr, SMEM_FLASH>>>(fqCh, fqCl, fkCh, fvCh, aoCh, aoCl);
    gemm_tc<3><<<gWO, thr, SMEM_GEMM>>>(aoCh, aoCl, coh, col, nullptr, out_cov,
                                        out_cov, nullptr, nullptr, EE, DAA, EE);

    // join
    cudaStreamWaitEvent(0, evend, 0);
}

// round 14
// speedup vs baseline: 1.1892x; 1.0414x over previous
#include <cuda_runtime.h>
#include <cuda_bf16.h>
#include <math.h>
#include <stdint.h>

#define BB 2
#define SS 2048
#define EE 1024
#define HH 8
#define DHH 64
#define DAA 512
#define DMLP 2048
#define NTOK 4096
#define SCALE_ATTN 0.04419417382415922f
#define SCALE_L2E 0.06375944628228341f   // SCALE_ATTN * log2(e)
#define LN_EPS 1e-5f

// GEMM (round-8 proven config): 128x128 tile, warp 64x32, K-chunk 32, 2-stage,
// padded 80B rows (conflict-free ldmatrix).
#define ROWB 80
#define PLANE_B 10240
#define STAGE_B 40960
#define SMEM_GEMM (2 * STAGE_B)

// Flash: Q hi/lo staged once; KV stages carry Kh + Vh only.
#define FROWB 144
#define FQPL 18432
#define FKPL 9216
#define FSTG 18432
#define SMEM_FLASH (2 * FQPL + 2 * FSTG)   // 73728

// ---------------- scratch ----------------
__device__ float g_qkvI[NTOK * 1536];
__device__ float g_qkvC[NTOK * 1536];

__device__ uint16_t pLNh[NTOK * EE],     pLNl[NTOK * EE];
__device__ uint16_t pLN2h[NTOK * EE],    pLN2l[NTOK * EE];
__device__ uint16_t pMIDh[NTOK * DMLP],  pMIDl[NTOK * DMLP];
__device__ uint16_t pMID2h[NTOK * DMLP], pMID2l[NTOK * DMLP];
__device__ uint16_t pQh[NTOK * EE],      pQl[NTOK * EE];
__device__ uint16_t pTGTh[NTOK * EE],    pTGTl[NTOK * EE];
__device__ uint16_t pAOIh[NTOK * DAA],   pAOIl[NTOK * DAA];
__device__ uint16_t pAOCh[NTOK * DAA],   pAOCl[NTOK * DAA];
__device__ uint16_t pFQIh[NTOK * DAA],   pFQIl[NTOK * DAA];
__device__ uint16_t pFKIh[NTOK * DAA];
__device__ uint16_t pFVIh[NTOK * DAA];
__device__ uint16_t pFQCh[NTOK * DAA],   pFQCl[NTOK * DAA];
__device__ uint16_t pFKCh[NTOK * DAA];
__device__ uint16_t pFVCh[NTOK * DAA];

__device__ uint16_t pW1h[DMLP * EE],    pW1l[DMLP * EE];
__device__ uint16_t pW2h[EE * DMLP],    pW2l[EE * DMLP];
__device__ uint16_t pIQKh[1024 * EE],   pIQKl[1024 * EE];
__device__ uint16_t pIVh[DAA * EE],     pIVl[DAA * EE];
__device__ uint16_t pIOh[EE * DAA],     pIOl[EE * DAA];
__device__ uint16_t pCQKVh[1536 * EE],  pCQKVl[1536 * EE];
__device__ uint16_t pCOh[EE * DAA],     pCOl[EE * DAA];

// ---------------- helpers ----------------
__device__ __forceinline__ uint32_t pk2(__nv_bfloat16 a, __nv_bfloat16 b) {
    uint16_t ra = *reinterpret_cast<uint16_t*>(&a);
    uint16_t rb = *reinterpret_cast<uint16_t*>(&b);
    return (uint32_t)ra | ((uint32_t)rb << 16);
}
__device__ __forceinline__ void split1(float x, __nv_bfloat16& h, __nv_bfloat16& l) {
    h = __float2bfloat16(x);
    l = __float2bfloat16(x - __bfloat162float(h));
}
__device__ __forceinline__ void mma16816(float* c, const uint32_t* a, const uint32_t* b) {
    asm volatile(
        "mma.sync.aligned.m16n8k16.row.col.f32.bf16.bf16.f32 "
        "{%0,%1,%2,%3}, {%4,%5,%6,%7}, {%8,%9}, {%0,%1,%2,%3};"
        : "+f"(c[0]), "+f"(c[1]), "+f"(c[2]), "+f"(c[3])
        : "r"(a[0]), "r"(a[1]), "r"(a[2]), "r"(a[3]), "r"(b[0]), "r"(b[1]));
}
__device__ __forceinline__ void ldsm4(uint32_t& r0, uint32_t& r1, uint32_t& r2, uint32_t& r3,
                                      uint32_t addr) {
    asm volatile("ldmatrix.sync.aligned.m8n8.x4.shared.b16 {%0,%1,%2,%3}, [%4];"
                 : "=r"(r0), "=r"(r1), "=r"(r2), "=r"(r3) : "r"(addr));
}
__device__ __forceinline__ void ldsm4t(uint32_t& r0, uint32_t& r1, uint32_t& r2, uint32_t& r3,
                                       uint32_t addr) {
    asm volatile("ldmatrix.sync.aligned.m8n8.x4.trans.shared.b16 {%0,%1,%2,%3}, [%4];"
                 : "=r"(r0), "=r"(r1), "=r"(r2), "=r"(r3) : "r"(addr));
}
__device__ __forceinline__ void cpa16(uint32_t s, const void* g) {
    asm volatile("cp.async.ca.shared.global [%0], [%1], 16;" :: "r"(s), "l"(g));
}
__device__ __forceinline__ void cpa_commit() {
    asm volatile("cp.async.commit_group;" ::: "memory");
}
template<int N>
__device__ __forceinline__ void cpa_wait() {
    asm volatile("cp.async.wait_group %0;" :: "n"(N) : "memory");
}
__device__ __forceinline__ float exp2p(float x) {
    x = fmaxf(x, -80.f);
    float n = rintf(x);
    float f = x - n;
    float p = 1.3333558146428443e-3f;
    p = p * f + 9.618129107628477e-3f;
    p = p * f + 5.550410866482158e-2f;
    p = p * f + 2.402265069591007e-1f;
    p = p * f + 6.931471805599453e-1f;
    p = p * f + 1.0f;
    return p * __int_as_float(((int)n + 127) << 23);
}

__device__ __forceinline__ float block_reduce_sum(float v) {
    __shared__ float red[32];
    int lane = threadIdx.x & 31, w = threadIdx.x >> 5;
#pragma unroll
    for (int o = 16; o > 0; o >>= 1) v += __shfl_xor_sync(0xffffffffu, v, o);
    __syncthreads();
    if (lane == 0) red[w] = v;
    __syncthreads();
    v = (lane < 8) ? red[lane] : 0.f;
#pragma unroll
    for (int o = 16; o > 0; o >>= 1) v += __shfl_xor_sync(0xffffffffu, v, o);
    return v;
}

// ---------------- LayerNorm -> bf16 hi/lo planes ----------------
__global__ void ln_split(const float* __restrict__ x, const float* __restrict__ g,
                         const float* __restrict__ b,
                         uint16_t* __restrict__ oh, uint16_t* __restrict__ ol) {
    int row = blockIdx.x, t = threadIdx.x;
    float4 v = *(const float4*)&x[(size_t)row * EE + 4 * t];
    float s = v.x + v.y + v.z + v.w;
    float mean = block_reduce_sum(s) * (1.0f / EE);
    float d0 = v.x - mean, d1 = v.y - mean, d2 = v.z - mean, d3 = v.w - mean;
    float var = block_reduce_sum(d0 * d0 + d1 * d1 + d2 * d2 + d3 * d3) * (1.0f / EE);
    float rstd = rsqrtf(var + LN_EPS);
    float4 gg = *(const float4*)&g[4 * t];
    float4 bb = *(const float4*)&b[4 * t];
    float y0 = d0 * rstd * gg.x + bb.x;
    float y1 = d1 * rstd * gg.y + bb.y;
    float y2 = d2 * rstd * gg.z + bb.z;
    float y3 = d3 * rstd * gg.w + bb.w;
    __nv_bfloat16 h0, h1, h2, h3, l0, l1, l2, l3;
    split1(y0, h0, l0); split1(y1, h1, l1); split1(y2, h2, l2); split1(y3, h3, l3);
    size_t off = (size_t)row * EE + 4 * t;
    *(uint2*)&oh[off] = make_uint2(pk2(h0, h1), pk2(h2, h3));
    *(uint2*)&ol[off] = make_uint2(pk2(l0, l1), pk2(l2, l3));
}

// ---------------- weight conversion, single launch ----------------
__device__ __forceinline__ void convB_body(const float* __restrict__ W,
                                           uint16_t* __restrict__ Bh,
                                           uint16_t* __restrict__ Bl, int K, int N) {
    __shared__ float ts[64][129];
    int nt = blockIdx.x, kt = blockIdx.y, tid = threadIdx.x;
    int k0 = kt * 64, n0 = nt * 128;
#pragma unroll
    for (int i = 0; i < 32; i++) {
        int idx = tid + i * 256;
        int kk = idx >> 7, nn = idx & 127;
        ts[kk][nn] = W[(size_t)(k0 + kk) * N + n0 + nn];
    }
    __syncthreads();
#pragma unroll
    for (int j = 0; j < 4; j++) {
        int job = tid + j * 256;
        int n = job >> 3, kg = (job & 7) * 8;
        __nv_bfloat16 h[8], l[8];
#pragma unroll
        for (int i = 0; i < 8; i++) split1(ts[kg + i][n], h[i], l[i]);
        uint4 uh = make_uint4(pk2(h[0], h[1]), pk2(h[2], h[3]), pk2(h[4], h[5]), pk2(h[6], h[7]));
        uint4 ul = make_uint4(pk2(l[0], l[1]), pk2(l[2], l[3]), pk2(l[4], l[5]), pk2(l[6], l[7]));
        size_t off = (size_t)(n0 + n) * K + k0 + kg;
        *(uint4*)&Bh[off] = uh;
        *(uint4*)&Bl[off] = ul;
    }
}

struct ConvJobs {
    const float* src[10];
    uint16_t* dh[10];
    uint16_t* dl[10];
    int K[10], N[10];
};
__global__ void conv_all(ConvJobs j) {
    int w = blockIdx.z;
    int K = j.K[w], N = j.N[w];
    if (blockIdx.x * 128 >= N || blockIdx.y * 64 >= K) return;
    convB_body(j.src[w], j.dh[w], j.dl[w], K, N);
}

// ---------------- HMMA bf16-split GEMM ----------------
// MODE 0: C=AB(fp32, ldC)  1: planes=gelu(AB+bias)  2: C=AB+bias+R (+planes)  3: C=AB+R
// BL=1: 3-term split (Ah*Bh + Ah*Bl + Al*Bh).  BL=0: B in bf16 only (2 terms, no Bl plane).
template<int MODE, int BL>
__global__ void __launch_bounds__(256, 2) gemm_tc(
    const uint16_t* __restrict__ Ah, const uint16_t* __restrict__ Al,
    const uint16_t* __restrict__ Bh, const uint16_t* __restrict__ Bl,
    const float* __restrict__ bias, const float* __restrict__ R,
    float* __restrict__ C, uint16_t* __restrict__ Ch, uint16_t* __restrict__ Cl,
    int N, int K, int ldC)
{
    extern __shared__ char sm[];
    const uint32_t sbase = (uint32_t)__cvta_generic_to_shared(sm);
    const int tid = threadIdx.x;
    const int warp = tid >> 5, lane = tid & 31;
    const int wm = warp & 1, wn = warp >> 1;
    const int m0 = blockIdx.y * 128, n0 = blockIdx.x * 128;
    const int KT = K >> 5;

    const uint16_t* gA[2] = { Ah + (size_t)m0 * K, Al + (size_t)m0 * K };
    const uint16_t* gB[2] = { Bh + (size_t)n0 * K, BL ? (Bl + (size_t)n0 * K) : nullptr };

    const int rl = lane & 7, grp = lane >> 3;
    const int a_r = rl + (grp & 1) * 8;
    const int a_c = (grp >> 1) * 8;
    const int b_r = rl + ((grp >> 1) & 1) * 8;
    const int b_c = (grp & 1) * 8;

    float acc[4][4][4];
#pragma unroll
    for (int i = 0; i < 4; i++)
#pragma unroll
        for (int j = 0; j < 4; j++)
#pragma unroll
            for (int k = 0; k < 4; k++) acc[i][j][k] = 0.f;

    auto issue = [&](int stage, int kt) {
        uint32_t s0 = sbase + stage * STAGE_B;
        int kel = kt * 32;
#pragma unroll
        for (int pl = 0; pl < 3 + BL; pl++) {
            const uint16_t* g = (pl < 2) ? gA[pl] : gB[pl - 2];
#pragma unroll
            for (int i = 0; i < 2; i++) {
                int seg = tid + i * 256;
                int m = seg >> 2, s = seg & 3;
                cpa16(s0 + pl * PLANE_B + m * ROWB + s * 16,
                      g + (size_t)m * K + kel + s * 8);
            }
        }
        cpa_commit();
    };

    issue(0, 0);
    for (int kt = 0; kt < KT; kt++) {
        int st = kt & 1;
        if (kt + 1 < KT) { issue(st ^ 1, kt + 1); cpa_wait<1>(); }
        else             { cpa_wait<0>(); }
        __syncthreads();

        uint32_t sA_h = sbase + st * STAGE_B;
        uint32_t sA_l = sA_h + PLANE_B;
        uint32_t sB_h = sA_h + 2 * PLANE_B;
        uint32_t sB_l = sA_h + 3 * PLANE_B;

#pragma unroll
        for (int ks = 0; ks < 2; ks++) {
            const int kk = ks * 16;
            uint32_t bh[2][4], bl[2][4];
#pragma unroll
            for (int ntp = 0; ntp < 2; ntp++) {
                uint32_t off = (uint32_t)((wn * 32 + ntp * 16 + b_r) * ROWB + (kk + b_c) * 2);
                ldsm4(bh[ntp][0], bh[ntp][1], bh[ntp][2], bh[ntp][3], sB_h + off);
                if (BL) ldsm4(bl[ntp][0], bl[ntp][1], bl[ntp][2], bl[ntp][3], sB_l + off);
            }
#pragma unroll
            for (int mt = 0; mt < 4; mt++) {
                uint32_t off = (uint32_t)((wm * 64 + mt * 16 + a_r) * ROWB + (kk + a_c) * 2);
                uint32_t ah[4], al[4];
                ldsm4(ah[0], ah[1], ah[2], ah[3], sA_h + off);
                ldsm4(al[0], al[1], al[2], al[3], sA_l + off);
#pragma unroll
                for (int nt = 0; nt < 4; nt++) {
                    uint32_t bfh[2] = { bh[nt >> 1][(nt & 1) * 2], bh[nt >> 1][(nt & 1) * 2 + 1] };
                    mma16816(acc[mt][nt], ah, bfh);
                    if (BL) {
                        uint32_t bfl[2] = { bl[nt >> 1][(nt & 1) * 2], bl[nt >> 1][(nt & 1) * 2 + 1] };
                        mma16816(acc[mt][nt], ah, bfl);
                    }
                    mma16816(acc[mt][nt], al, bfh);
                }
            }
        }
        __syncthreads();
    }

    const int r = lane >> 2, q = lane & 3;
#pragma unroll
    for (int mt = 0; mt < 4; mt++) {
#pragma unroll
        for (int nt = 0; nt < 4; nt++) {
            int row = m0 + wm * 64 + mt * 16 + r;
            int col = n0 + wn * 32 + nt * 8 + q * 2;
#pragma unroll
            for (int half = 0; half < 2; half++) {
                int rr2 = row + half * 8;
                float v0 = acc[mt][nt][half * 2 + 0];
                float v1 = acc[mt][nt][half * 2 + 1];
                size_t gidx = (size_t)rr2 * ldC + col;
                if (MODE == 1) {
                    v0 += bias[col];
                    v1 += bias[col + 1];
                    v0 = 0.5f * v0 * (1.0f + erff(v0 * 0.70710678118654752f));
                    v1 = 0.5f * v1 * (1.0f + erff(v1 * 0.70710678118654752f));
                    __nv_bfloat16 h0, h1, l0, l1;
                    split1(v0, h0, l0); split1(v1, h1, l1);
                    *(uint32_t*)&Ch[gidx] = pk2(h0, h1);
                    *(uint32_t*)&Cl[gidx] = pk2(l0, l1);
                } else {
                    if (MODE == 2) {
                        float2 rv = *(const float2*)&R[gidx];
                        v0 += bias[col] + rv.x;
                        v1 += bias[col + 1] + rv.y;
                    } else if (MODE == 3) {
                        float2 rv = *(const float2*)&R[gidx];
                        v0 += rv.x;
                        v1 += rv.y;
                    }
                    *(float2*)&C[gidx] = make_float2(v0, v1);
                    if (MODE == 2 && Ch) {
                        __nv_bfloat16 h0, h1, l0, l1;
                        split1(v0, h0, l0); split1(v1, h1, l1);
                        *(uint32_t*)&Ch[gidx] = pk2(h0, h1);
                        *(uint32_t*)&Cl[gidx] = pk2(l0, l1);
                    }
                }
            }
        }
    }
}

// ---------------- RoPE + split to flash planes (Q hi/lo, K hi, V hi) ----------------
__global__ void rope_split(const float* __restrict__ qkv,
                           uint16_t* __restrict__ fqh, uint16_t* __restrict__ fql,
                           uint16_t* __restrict__ fkh, uint16_t* __restrict__ fvh) {
    int row = blockIdx.x, t = threadIdx.x;
    int i = t & 31;
    int s = row & (SS - 1);
    float inv = __expf(-logf(10000.0f) * ((float)i / 32.0f));
    float ang = (float)s * inv;
    float c = cosf(ang), sn = sinf(ang);
    const float* base = qkv + (size_t)row * 1536;
    size_t dst = (size_t)row * DAA + 2 * t;

    float x1 = base[2 * t], x2 = base[2 * t + 1];
    float o1 = x1 * c - x2 * sn, o2 = x1 * sn + x2 * c;
    __nv_bfloat16 h0, h1, l0, l1;
    split1(o1, h0, l0); split1(o2, h1, l1);
    *(uint32_t*)&fqh[dst] = pk2(h0, h1);
    *(uint32_t*)&fql[dst] = pk2(l0, l1);

    x1 = base[512 + 2 * t]; x2 = base[512 + 2 * t + 1];
    o1 = x1 * c - x2 * sn; o2 = x1 * sn + x2 * c;
    *(uint32_t*)&fkh[dst] = pk2(__float2bfloat16(o1), __float2bfloat16(o2));

    x1 = base[1024 + 2 * t]; x2 = base[1024 + 2 * t + 1];
    *(uint32_t*)&fvh[dst] = pk2(__float2bfloat16(x1), __float2bfloat16(x2));
}

// ---------------- Flash attention: Q hi/lo, K hi, V hi; HMMA + poly exp2 ----------------
template<int ICL>
__global__ void __launch_bounds__(256) flash_mma(
    const uint16_t* __restrict__ Qh, const uint16_t* __restrict__ Ql,
    const uint16_t* __restrict__ Kh, const uint16_t* __restrict__ Vh,
    uint16_t* __restrict__ Oh, uint16_t* __restrict__ Ol)
{
    extern __shared__ char sm[];
    const uint32_t sb = (uint32_t)__cvta_generic_to_shared(sm);
    const uint32_t sQh = sb, sQl = sb + FQPL;
    const uint32_t sKV = sb + 2 * FQPL;
    const int tid = threadIdx.x, warp = tid >> 5, lane = tid & 31;
    const int qt = gridDim.x - 1 - blockIdx.x;
    const int bh = blockIdx.y, b = bh >> 3, h = bh & 7;
    const int qg0 = qt * 128;
    const size_t tokb = (size_t)b * SS;
    const int rb = warp * 16;

    const int rl = lane & 7, grp = lane >> 3;
    const int a_r = rl + (grp & 1) * 8;
    const int a_c = (grp >> 1) * 8;
    const int b_r = rl + ((grp >> 1) & 1) * 8;
    const int b_c = (grp & 1) * 8;

#pragma unroll
    for (int i = 0; i < 8; i++) {
        int job = tid + i * 256;
        int pl = job >> 10, r = (job >> 3) & 127, s = job & 7;
        const uint16_t* g = (pl ? Ql : Qh) + (tokb + qg0 + r) * DAA + h * DHH + s * 8;
        cpa16((pl ? sQl : sQh) + r * FROWB + s * 16, g);
    }
    cpa_commit();

    float out[8][4];
#pragma unroll
    for (int i = 0; i < 8; i++)
#pragma unroll
        for (int j = 0; j < 4; j++) out[i][j] = 0.f;
    float mrow[2] = { -1e30f, -1e30f }, lrow[2] = { 0.f, 0.f };

    const int ktmax = (qg0 + 127) >> 6;

    auto issueKV = [&](int st, int kt) {
        uint32_t s0 = sKV + st * FSTG;
        int kg0 = kt * 64;
#pragma unroll
        for (int i = 0; i < 4; i++) {
            int job = tid + i * 256;
            int pl = job >> 9, r = (job >> 3) & 63, s = job & 7;
            const uint16_t* gp = (pl == 0) ? Kh : Vh;
            cpa16(s0 + pl * FKPL + r * FROWB + s * 16,
                  gp + (tokb + kg0 + r) * DAA + h * DHH + s * 8);
        }
        cpa_commit();
    };
    issueKV(0, 0);

    const int qrow0 = qg0 + rb + (lane >> 2);

    for (int kt = 0; kt <= ktmax; kt++) {
        int st = kt & 1;
        int kg0 = kt * 64;
        if (kt < ktmax) { issueKV(st ^ 1, kt + 1); cpa_wait<1>(); }
        else            { cpa_wait<0>(); }
        __syncthreads();

        uint32_t sK_h = sKV + st * FSTG;
        uint32_t sV_h = sK_h + FKPL;

        float sc[8][4];
#pragma unroll
        for (int i = 0; i < 8; i++)
#pragma unroll
            for (int j = 0; j < 4; j++) sc[i][j] = 0.f;
#pragma unroll
        for (int k16 = 0; k16 < 4; k16++) {
            uint32_t qoff = (uint32_t)((rb + a_r) * FROWB + (k16 * 16 + a_c) * 2);
            uint32_t ah[4], al[4];
            ldsm4(ah[0], ah[1], ah[2], ah[3], sQh + qoff);
            ldsm4(al[0], al[1], al[2], al[3], sQl + qoff);
#pragma unroll
            for (int ntp = 0; ntp < 4; ntp++) {
                uint32_t koff = (uint32_t)((ntp * 16 + b_r) * FROWB + (k16 * 16 + b_c) * 2);
                uint32_t kh[4];
                ldsm4(kh[0], kh[1], kh[2], kh[3], sK_h + koff);
#pragma unroll
                for (int u = 0; u < 2; u++) {
                    int nt = ntp * 2 + u;
                    uint32_t bfh[2] = { kh[u * 2], kh[u * 2 + 1] };
                    mma16816(sc[nt], ah, bfh);
                    mma16816(sc[nt], al, bfh);
                }
            }
        }

        const bool boundary = (kg0 + 63 >= qg0);
#pragma unroll
        for (int nt = 0; nt < 8; nt++) {
#pragma unroll
            for (int c = 0; c < 4; c++) {
                float v = sc[nt][c] * SCALE_L2E;
                if (boundary) {
                    int qg = qrow0 + (c >> 1) * 8;
                    int kg = kg0 + nt * 8 + (lane & 3) * 2 + (c & 1);
                    bool allow = ICL ? (kg < qg || (qg | kg) == 0) : (kg <= qg);
                    v = allow ? v : -1e30f;
                }
                sc[nt][c] = v;
            }
        }

#pragma unroll
        for (int ri = 0; ri < 2; ri++) {
            float mx = -1e30f;
#pragma unroll
            for (int nt = 0; nt < 8; nt++)
                mx = fmaxf(mx, fmaxf(sc[nt][ri * 2], sc[nt][ri * 2 + 1]));
            mx = fmaxf(mx, __shfl_xor_sync(0xffffffffu, mx, 1));
            mx = fmaxf(mx, __shfl_xor_sync(0xffffffffu, mx, 2));
            float mn = fmaxf(mrow[ri], mx);
            float corr = exp2p(mrow[ri] - mn);
            mrow[ri] = mn;
            float rs = 0.f;
#pragma unroll
            for (int nt = 0; nt < 8; nt++) {
                float p0 = exp2p(sc[nt][ri * 2] - mn);
                float p1 = exp2p(sc[nt][ri * 2 + 1] - mn);
                sc[nt][ri * 2] = p0;
                sc[nt][ri * 2 + 1] = p1;
                rs += p0 + p1;
            }
            rs += __shfl_xor_sync(0xffffffffu, rs, 1);
            rs += __shfl_xor_sync(0xffffffffu, rs, 2);
            lrow[ri] = lrow[ri] * corr + rs;
#pragma unroll
            for (int nt = 0; nt < 8; nt++) {
                out[nt][ri * 2] *= corr;
                out[nt][ri * 2 + 1] *= corr;
            }
        }

#pragma unroll
        for (int j = 0; j < 4; j++) {
            uint32_t aP[4];
            aP[0] = pk2(__float2bfloat16(sc[2 * j][0]),     __float2bfloat16(sc[2 * j][1]));
            aP[1] = pk2(__float2bfloat16(sc[2 * j][2]),     __float2bfloat16(sc[2 * j][3]));
            aP[2] = pk2(__float2bfloat16(sc[2 * j + 1][0]), __float2bfloat16(sc[2 * j + 1][1]));
            aP[3] = pk2(__float2bfloat16(sc[2 * j + 1][2]), __float2bfloat16(sc[2 * j + 1][3]));
#pragma unroll
            for (int nt2 = 0; nt2 < 4; nt2++) {
                uint32_t voff = (uint32_t)((j * 16 + (grp & 1) * 8 + rl) * FROWB
                                           + (nt2 * 16 + (grp >> 1) * 8) * 2);
                uint32_t bv[4];
                ldsm4t(bv[0], bv[1], bv[2], bv[3], sV_h + voff);
                uint32_t b0[2] = { bv[0], bv[1] }, b1[2] = { bv[2], bv[3] };
                mma16816(out[nt2 * 2], aP, b0);
                mma16816(out[nt2 * 2 + 1], aP, b1);
            }
        }
        __syncthreads();
    }

#pragma unroll
    for (int ri = 0; ri < 2; ri++) {
        float inv = 1.0f / lrow[ri];
        size_t rbase = (tokb + qrow0 + ri * 8) * DAA + h * DHH + (lane & 3) * 2;
#pragma unroll
        for (int nt = 0; nt < 8; nt++) {
            float v0 = out[nt][ri * 2] * inv;
            float v1 = out[nt][ri * 2 + 1] * inv;
            __nv_bfloat16 h0, h1, l0, l1;
            split1(v0, h0, l0); split1(v1, h1, l1);
            *(uint32_t*)&Oh[rbase + nt * 8] = pk2(h0, h1);
            *(uint32_t*)&Ol[rbase + nt * 8] = pk2(l0, l1);
        }
    }
}

// ---------------- host driver ----------------
#define GETSYM(T, var, sym) T* var; { void* _p; cudaGetSymbolAddress(&_p, sym); var = (T*)_p; }

extern "C" void kernel_launch(void* const* d_in, const int* in_sizes, int n_in,
                              void* d_out, int out_size)
{
    const float* cov_in  = (const float*)d_in[0];
    const float* tgt_in  = (const float*)d_in[1];
    const float* fu_in   = (const float*)d_in[2];
    const float* fc1w    = (const float*)d_in[3];
    const float* fc1b    = (const float*)d_in[4];
    const float* fc2w    = (const float*)d_in[5];
    const float* fc2b    = (const float*)d_in[6];
    const float* icl_wq  = (const float*)d_in[7];
    const float* icl_wk  = (const float*)d_in[8];
    const float* icl_wv  = (const float*)d_in[9];
    const float* icl_wo  = (const float*)d_in[10];
    const float* cov_wq  = (const float*)d_in[11];
    const float* cov_wk  = (const float*)d_in[12];
    const float* cov_wv  = (const float*)d_in[13];
    const float* cov_wo  = (const float*)d_in[14];
    const float* ln_cm_g = (const float*)d_in[15];
    const float* ln_cm_b = (const float*)d_in[16];
    const float* ln_ia_g = (const float*)d_in[17];
    const float* ln_ia_b = (const float*)d_in[18];
    const float* ln_im_g = (const float*)d_in[19];
    const float* ln_im_b = (const float*)d_in[20];

    float* out_cov = (float*)d_out;
    float* out_tgt = out_cov + (size_t)NTOK * EE;
    float* out_fu  = out_tgt + (size_t)NTOK * EE;

    GETSYM(float, qkvI, g_qkvI)    GETSYM(float, qkvC, g_qkvC)
    GETSYM(uint16_t, lnh, pLNh)    GETSYM(uint16_t, lnl, pLNl)
    GETSYM(uint16_t, ln2h, pLN2h)  GETSYM(uint16_t, ln2l, pLN2l)
    GETSYM(uint16_t, midh, pMIDh)  GETSYM(uint16_t, midl, pMIDl)
    GETSYM(uint16_t, mid2h, pMID2h) GETSYM(uint16_t, mid2l, pMID2l)
    GETSYM(uint16_t, qh, pQh)      GETSYM(uint16_t, ql, pQl)
    GETSYM(uint16_t, tgh, pTGTh)   GETSYM(uint16_t, tgl, pTGTl)
    GETSYM(uint16_t, aoIh, pAOIh)  GETSYM(uint16_t, aoIl, pAOIl)
    GETSYM(uint16_t, aoCh, pAOCh)  GETSYM(uint16_t, aoCl, pAOCl)
    GETSYM(uint16_t, fqIh, pFQIh)  GETSYM(uint16_t, fqIl, pFQIl)
    GETSYM(uint16_t, fkIh, pFKIh)  GETSYM(uint16_t, fvIh, pFVIh)
    GETSYM(uint16_t, fqCh, pFQCh)  GETSYM(uint16_t, fqCl, pFQCl)
    GETSYM(uint16_t, fkCh, pFKCh)  GETSYM(uint16_t, fvCh, pFVCh)
    GETSYM(uint16_t, w1h, pW1h)    GETSYM(uint16_t, w1l, pW1l)
    GETSYM(uint16_t, w2h, pW2h)    GETSYM(uint16_t, w2l, pW2l)
    GETSYM(uint16_t, iqkh, pIQKh)  GETSYM(uint16_t, iqkl, pIQKl)
    GETSYM(uint16_t, ivh, pIVh)    GETSYM(uint16_t, ivl, pIVl)
    GETSYM(uint16_t, ioh, pIOh)    GETSYM(uint16_t, iol, pIOl)
    GETSYM(uint16_t, cqkvh, pCQKVh) GETSYM(uint16_t, cqkvl, pCQKVl)
    GETSYM(uint16_t, coh, pCOh)    GETSYM(uint16_t, col, pCOl)

    static cudaStream_t s2 = nullptr;
    static cudaEvent_t ev0 = nullptr, evq = nullptr, evend = nullptr;
    if (!s2) {
        cudaStreamCreateWithFlags(&s2, cudaStreamNonBlocking);
        cudaEventCreateWithFlags(&ev0, cudaEventDisableTiming);
        cudaEventCreateWithFlags(&evq, cudaEventDisableTiming);
        cudaEventCreateWithFlags(&evend, cudaEventDisableTiming);
        cudaFuncSetAttribute(gemm_tc<0, 0>, cudaFuncAttributeMaxDynamicSharedMemorySize, SMEM_GEMM);
        cudaFuncSetAttribute(gemm_tc<1, 1>, cudaFuncAttributeMaxDynamicSharedMemorySize, SMEM_GEMM);
        cudaFuncSetAttribute(gemm_tc<2, 1>, cudaFuncAttributeMaxDynamicSharedMemorySize, SMEM_GEMM);
        cudaFuncSetAttribute(gemm_tc<3, 1>, cudaFuncAttributeMaxDynamicSharedMemorySize, SMEM_GEMM);
        cudaFuncSetAttribute(flash_mma<0>, cudaFuncAttributeMaxDynamicSharedMemorySize, SMEM_FLASH);
        cudaFuncSetAttribute(flash_mma<1>, cudaFuncAttributeMaxDynamicSharedMemorySize, SMEM_FLASH);
    }

    const dim3 thr(256);
    const dim3 gFC1(DMLP / 128, NTOK / 128);
    const dim3 gFC2(EE / 128, NTOK / 128);
    const dim3 gQK(8, NTOK / 128);
    const dim3 gV(4, NTOK / 128);
    const dim3 gQKV(12, NTOK / 128);
    const dim3 gWO(EE / 128, NTOK / 128);
    const dim3 gFLASH(SS / 128, BB * HH);

    // ---- all weight conversions, one launch ----
    ConvJobs cj;
    cj.src[0] = fc1w;   cj.dh[0] = w1h;              cj.dl[0] = w1l;              cj.K[0] = EE;   cj.N[0] = DMLP;
    cj.src[1] = fc2w;   cj.dh[1] = w2h;              cj.dl[1] = w2l;              cj.K[1] = DMLP; cj.N[1] = EE;
    cj.src[2] = icl_wq; cj.dh[2] = iqkh;             cj.dl[2] = iqkl;             cj.K[2] = EE;   cj.N[2] = DAA;
    cj.src[3] = icl_wk; cj.dh[3] = iqkh + 512 * EE;  cj.dl[3] = iqkl + 512 * EE;  cj.K[3] = EE;   cj.N[3] = DAA;
    cj.src[4] = icl_wv; cj.dh[4] = ivh;              cj.dl[4] = ivl;              cj.K[4] = EE;   cj.N[4] = DAA;
    cj.src[5] = cov_wq; cj.dh[5] = cqkvh;            cj.dl[5] = cqkvl;            cj.K[5] = EE;   cj.N[5] = DAA;
    cj.src[6] = cov_wk; cj.dh[6] = cqkvh + 512 * EE; cj.dl[6] = cqkvl + 512 * EE; cj.K[6] = EE;   cj.N[6] = DAA;
    cj.src[7] = cov_wv; cj.dh[7] = cqkvh + 1024 * EE;cj.dl[7] = cqkvl + 1024 * EE;cj.K[7] = EE;   cj.N[7] = DAA;
    cj.src[8] = icl_wo; cj.dh[8] = ioh;              cj.dl[8] = iol;              cj.K[8] = DAA;  cj.N[8] = EE;
    cj.src[9] = cov_wo; cj.dh[9] = coh;              cj.dl[9] = col;              cj.K[9] = DAA;  cj.N[9] = EE;
    conv_all<<<dim3(16, 32, 10), thr>>>(cj);
    cudaEventRecord(ev0, 0);
    cudaStreamWaitEvent(s2, ev0, 0);

    // ---- chain2 on s2: tgt = targets + MLP(LN(functional_update)) ----
    ln_split<<<NTOK, thr, 0, s2>>>(fu_in, ln_im_g, ln_im_b, ln2h, ln2l);
    gemm_tc<1, 1><<<gFC1, thr, SMEM_GEMM, s2>>>(ln2h, ln2l, w1h, w1l, fc1b, nullptr,
                                                nullptr, mid2h, mid2l, DMLP, EE, DMLP);
    gemm_tc<2, 1><<<gFC2, thr, SMEM_GEMM, s2>>>(mid2h, mid2l, w2h, w2l, fc2b, tgt_in,
                                                out_tgt, tgh, tgl, EE, DMLP, EE);
    // V-projection depends only on tgt — 2-term (weight bf16)
    gemm_tc<0, 0><<<gV, thr, SMEM_GEMM, s2>>>(tgh, tgl, ivh, nullptr, nullptr, nullptr,
                                              qkvI + 1024, nullptr, nullptr, DAA, EE, 1536);

    // ---- chain1 on legacy: cov = covariates + MLP(LN(covariates)); q = LN(cov) ----
    ln_split<<<NTOK, thr>>>(cov_in, ln_cm_g, ln_cm_b, lnh, lnl);
    gemm_tc<1, 1><<<gFC1, thr, SMEM_GEMM>>>(lnh, lnl, w1h, w1l, fc1b, nullptr,
                                            nullptr, midh, midl, DMLP, EE, DMLP);
    gemm_tc<2, 1><<<gFC2, thr, SMEM_GEMM>>>(midh, midl, w2h, w2l, fc2b, cov_in,
                                            out_cov, nullptr, nullptr, EE, DMLP, EE);
    ln_split<<<NTOK, thr>>>(out_cov, ln_ia_g, ln_ia_b, qh, ql);
    cudaEventRecord(evq, 0);

    // ---- ICL attention on s2 (needs q + tgt) ----
    cudaStreamWaitEvent(s2, evq, 0);
    gemm_tc<0, 0><<<gQK, thr, SMEM_GEMM, s2>>>(qh, ql, iqkh, nullptr, nullptr, nullptr,
                                               qkvI, nullptr, nullptr, 1024, EE, 1536);
    rope_split<<<NTOK, thr, 0, s2>>>(qkvI, fqIh, fqIl, fkIh, fvIh);
    flash_mma<1><<<gFLASH, thr, SMEM_FLASH, s2>>>(fqIh, fqIl, fkIh, fvIh, aoIh, aoIl);
    gemm_tc<3, 1><<<gWO, thr, SMEM_GEMM, s2>>>(aoIh, aoIl, ioh, iol, nullptr, fu_in,
                                               out_fu, nullptr, nullptr, EE, DAA, EE);
    cudaEventRecord(evend, s2);

    // ---- COV attention on legacy (needs only q) ----
    gemm_tc<0, 0><<<gQKV, thr, SMEM_GEMM>>>(qh, ql, cqkvh, nullptr, nullptr, nullptr,
                                            qkvC, nullptr, nullptr, 1536, EE, 1536);
    rope_split<<<NTOK, thr>>>(qkvC, fqCh, fqCl, fkCh, fvCh);
    flash_mma<0><<<gFLASH, thr, SMEM_FLASH>>>(fqCh, fqCl, fkCh, fvCh, aoCh, aoCl);
    gemm_tc<3, 1><<<gWO, thr, SMEM_GEMM>>>(aoCh, aoCl, coh, col, nullptr, out_cov,
                                           out_cov, nullptr, nullptr, EE, DAA, EE);

    // join
    cudaStreamWaitEvent(0, evend, 0);
}

// round 15
// speedup vs baseline: 1.3013x; 1.0943x over previous
#include <cuda_runtime.h>
#include <cuda_bf16.h>
#include <math.h>
#include <stdint.h>

#define BB 2
#define SS 2048
#define EE 1024
#define HH 8
#define DHH 64
#define DAA 512
#define DMLP 2048
#define NTOK 4096
#define SCALE_ATTN 0.04419417382415922f
#define SCALE_L2E 0.06375944628228341f   // SCALE_ATTN * log2(e)
#define LN_EPS 1e-5f

// GEMM (round-8 proven config): 128x128 tile, warp 64x32, K-chunk 32, 2-stage,
// padded 80B rows (conflict-free ldmatrix).
#define ROWB 80
#define PLANE_B 10240
#define STAGE_B 40960
#define SMEM_GEMM (2 * STAGE_B)

// Flash: Q hi/lo staged once; KV stages carry Kh + Vh only.
#define FROWB 144
#define FQPL 18432
#define FKPL 9216
#define FSTG 18432
#define SMEM_FLASH (2 * FQPL + 2 * FSTG)   // 73728

// ---------------- scratch ----------------
__device__ float g_qkvI[NTOK * 1536];
__device__ float g_qkvC[NTOK * 1536];

__device__ uint16_t pLNh[NTOK * EE],     pLNl[NTOK * EE];
__device__ uint16_t pLN2h[NTOK * EE],    pLN2l[NTOK * EE];
__device__ uint16_t pMIDh[NTOK * DMLP],  pMIDl[NTOK * DMLP];
__device__ uint16_t pMID2h[NTOK * DMLP], pMID2l[NTOK * DMLP];
__device__ uint16_t pQh[NTOK * EE],      pQl[NTOK * EE];
__device__ uint16_t pTGTh[NTOK * EE],    pTGTl[NTOK * EE];
__device__ uint16_t pAOIh[NTOK * DAA],   pAOIl[NTOK * DAA];
__device__ uint16_t pAOCh[NTOK * DAA],   pAOCl[NTOK * DAA];
__device__ uint16_t pFQIh[NTOK * DAA],   pFQIl[NTOK * DAA];
__device__ uint16_t pFKIh[NTOK * DAA];
__device__ uint16_t pFVIh[NTOK * DAA];
__device__ uint16_t pFQCh[NTOK * DAA],   pFQCl[NTOK * DAA];
__device__ uint16_t pFKCh[NTOK * DAA];
__device__ uint16_t pFVCh[NTOK * DAA];

__device__ uint16_t pW1h[DMLP * EE],    pW1l[DMLP * EE];
__device__ uint16_t pW2h[EE * DMLP],    pW2l[EE * DMLP];
__device__ uint16_t pIQKh[1024 * EE],   pIQKl[1024 * EE];
__device__ uint16_t pIVh[DAA * EE],     pIVl[DAA * EE];
__device__ uint16_t pIOh[EE * DAA],     pIOl[EE * DAA];
__device__ uint16_t pCQKVh[1536 * EE],  pCQKVl[1536 * EE];
__device__ uint16_t pCOh[EE * DAA],     pCOl[EE * DAA];

// ---------------- helpers ----------------
__device__ __forceinline__ uint32_t pk2(__nv_bfloat16 a, __nv_bfloat16 b) {
    uint16_t ra = *reinterpret_cast<uint16_t*>(&a);
    uint16_t rb = *reinterpret_cast<uint16_t*>(&b);
    return (uint32_t)ra | ((uint32_t)rb << 16);
}
__device__ __forceinline__ void split1(float x, __nv_bfloat16& h, __nv_bfloat16& l) {
    h = __float2bfloat16(x);
    l = __float2bfloat16(x - __bfloat162float(h));
}
__device__ __forceinline__ void mma16816(float* c, const uint32_t* a, const uint32_t* b) {
    asm volatile(
        "mma.sync.aligned.m16n8k16.row.col.f32.bf16.bf16.f32 "
        "{%0,%1,%2,%3}, {%4,%5,%6,%7}, {%8,%9}, {%0,%1,%2,%3};"
        : "+f"(c[0]), "+f"(c[1]), "+f"(c[2]), "+f"(c[3])
        : "r"(a[0]), "r"(a[1]), "r"(a[2]), "r"(a[3]), "r"(b[0]), "r"(b[1]));
}
__device__ __forceinline__ void ldsm4(uint32_t& r0, uint32_t& r1, uint32_t& r2, uint32_t& r3,
                                      uint32_t addr) {
    asm volatile("ldmatrix.sync.aligned.m8n8.x4.shared.b16 {%0,%1,%2,%3}, [%4];"
                 : "=r"(r0), "=r"(r1), "=r"(r2), "=r"(r3) : "r"(addr));
}
__device__ __forceinline__ void ldsm4t(uint32_t& r0, uint32_t& r1, uint32_t& r2, uint32_t& r3,
                                       uint32_t addr) {
    asm volatile("ldmatrix.sync.aligned.m8n8.x4.trans.shared.b16 {%0,%1,%2,%3}, [%4];"
                 : "=r"(r0), "=r"(r1), "=r"(r2), "=r"(r3) : "r"(addr));
}
__device__ __forceinline__ void cpa16(uint32_t s, const void* g) {
    asm volatile("cp.async.ca.shared.global [%0], [%1], 16;" :: "r"(s), "l"(g));
}
__device__ __forceinline__ void cpa_commit() {
    asm volatile("cp.async.commit_group;" ::: "memory");
}
template<int N>
__device__ __forceinline__ void cpa_wait() {
    asm volatile("cp.async.wait_group %0;" :: "n"(N) : "memory");
}
__device__ __forceinline__ float exp2p(float x) {
    x = fmaxf(x, -80.f);
    float n = rintf(x);
    float f = x - n;
    float p = 1.3333558146428443e-3f;
    p = p * f + 9.618129107628477e-3f;
    p = p * f + 5.550410866482158e-2f;
    p = p * f + 2.402265069591007e-1f;
    p = p * f + 6.931471805599453e-1f;
    p = p * f + 1.0f;
    return p * __int_as_float(((int)n + 127) << 23);
}

__device__ __forceinline__ float block_reduce_sum(float v) {
    __shared__ float red[32];
    int lane = threadIdx.x & 31, w = threadIdx.x >> 5;
#pragma unroll
    for (int o = 16; o > 0; o >>= 1) v += __shfl_xor_sync(0xffffffffu, v, o);
    __syncthreads();
    if (lane == 0) red[w] = v;
    __syncthreads();
    v = (lane < 8) ? red[lane] : 0.f;
#pragma unroll
    for (int o = 16; o > 0; o >>= 1) v += __shfl_xor_sync(0xffffffffu, v, o);
    return v;
}

// ---------------- LayerNorm -> bf16 hi/lo planes ----------------
__global__ void ln_split(const float* __restrict__ x, const float* __restrict__ g,
                         const float* __restrict__ b,
                         uint16_t* __restrict__ oh, uint16_t* __restrict__ ol) {
    int row = blockIdx.x, t = threadIdx.x;
    float4 v = *(const float4*)&x[(size_t)row * EE + 4 * t];
    float s = v.x + v.y + v.z + v.w;
    float mean = block_reduce_sum(s) * (1.0f / EE);
    float d0 = v.x - mean, d1 = v.y - mean, d2 = v.z - mean, d3 = v.w - mean;
    float var = block_reduce_sum(d0 * d0 + d1 * d1 + d2 * d2 + d3 * d3) * (1.0f / EE);
    float rstd = rsqrtf(var + LN_EPS);
    float4 gg = *(const float4*)&g[4 * t];
    float4 bb = *(const float4*)&b[4 * t];
    float y0 = d0 * rstd * gg.x + bb.x;
    float y1 = d1 * rstd * gg.y + bb.y;
    float y2 = d2 * rstd * gg.z + bb.z;
    float y3 = d3 * rstd * gg.w + bb.w;
    __nv_bfloat16 h0, h1, h2, h3, l0, l1, l2, l3;
    split1(y0, h0, l0); split1(y1, h1, l1); split1(y2, h2, l2); split1(y3, h3, l3);
    size_t off = (size_t)row * EE + 4 * t;
    *(uint2*)&oh[off] = make_uint2(pk2(h0, h1), pk2(h2, h3));
    *(uint2*)&ol[off] = make_uint2(pk2(l0, l1), pk2(l2, l3));
}

// ---------------- weight conversion, single launch ----------------
__device__ __forceinline__ void convB_body(const float* __restrict__ W,
                                           uint16_t* __restrict__ Bh,
                                           uint16_t* __restrict__ Bl, int K, int N) {
    __shared__ float ts[64][129];
    int nt = blockIdx.x, kt = blockIdx.y, tid = threadIdx.x;
    int k0 = kt * 64, n0 = nt * 128;
#pragma unroll
    for (int i = 0; i < 32; i++) {
        int idx = tid + i * 256;
        int kk = idx >> 7, nn = idx & 127;
        ts[kk][nn] = W[(size_t)(k0 + kk) * N + n0 + nn];
    }
    __syncthreads();
#pragma unroll
    for (int j = 0; j < 4; j++) {
        int job = tid + j * 256;
        int n = job >> 3, kg = (job & 7) * 8;
        __nv_bfloat16 h[8], l[8];
#pragma unroll
        for (int i = 0; i < 8; i++) split1(ts[kg + i][n], h[i], l[i]);
        uint4 uh = make_uint4(pk2(h[0], h[1]), pk2(h[2], h[3]), pk2(h[4], h[5]), pk2(h[6], h[7]));
        uint4 ul = make_uint4(pk2(l[0], l[1]), pk2(l[2], l[3]), pk2(l[4], l[5]), pk2(l[6], l[7]));
        size_t off = (size_t)(n0 + n) * K + k0 + kg;
        *(uint4*)&Bh[off] = uh;
        *(uint4*)&Bl[off] = ul;
    }
}

struct ConvJobs {
    const float* src[10];
    uint16_t* dh[10];
    uint16_t* dl[10];
    int K[10], N[10];
};
__global__ void conv_all(ConvJobs j) {
    int w = blockIdx.z;
    int K = j.K[w], N = j.N[w];
    if (blockIdx.x * 128 >= N || blockIdx.y * 64 >= K) return;
    convB_body(j.src[w], j.dh[w], j.dl[w], K, N);
}

// ---------------- HMMA bf16-split GEMM ----------------
// MODE 0: C=AB(fp32, ldC)  1: planes=gelu(AB+bias)  2: C=AB+bias+R (+planes)  3: C=AB+R
// BL=1: 3-term split (Ah*Bh + Ah*Bl + Al*Bh).  BL=0: B in bf16 only (2 terms, no Bl plane).
template<int MODE, int BL>
__global__ void __launch_bounds__(256, 2) gemm_tc(
    const uint16_t* __restrict__ Ah, const uint16_t* __restrict__ Al,
    const uint16_t* __restrict__ Bh, const uint16_t* __restrict__ Bl,
    const float* __restrict__ bias, const float* __restrict__ R,
    float* __restrict__ C, uint16_t* __restrict__ Ch, uint16_t* __restrict__ Cl,
    int N, int K, int ldC)
{
    extern __shared__ char sm[];
    const uint32_t sbase = (uint32_t)__cvta_generic_to_shared(sm);
    const int tid = threadIdx.x;
    const int warp = tid >> 5, lane = tid & 31;
    const int wm = warp & 1, wn = warp >> 1;
    const int m0 = blockIdx.y * 128, n0 = blockIdx.x * 128;
    const int KT = K >> 5;

    const uint16_t* gA[2] = { Ah + (size_t)m0 * K, Al + (size_t)m0 * K };
    const uint16_t* gB[2] = { Bh + (size_t)n0 * K, BL ? (Bl + (size_t)n0 * K) : nullptr };

    const int rl = lane & 7, grp = lane >> 3;
    const int a_r = rl + (grp & 1) * 8;
    const int a_c = (grp >> 1) * 8;
    const int b_r = rl + ((grp >> 1) & 1) * 8;
    const int b_c = (grp & 1) * 8;

    float acc[4][4][4];
#pragma unroll
    for (int i = 0; i < 4; i++)
#pragma unroll
        for (int j = 0; j < 4; j++)
#pragma unroll
            for (int k = 0; k < 4; k++) acc[i][j][k] = 0.f;

    auto issue = [&](int stage, int kt) {
        uint32_t s0 = sbase + stage * STAGE_B;
        int kel = kt * 32;
#pragma unroll
        for (int pl = 0; pl < 3 + BL; pl++) {
            const uint16_t* g = (pl < 2) ? gA[pl] : gB[pl - 2];
#pragma unroll
            for (int i = 0; i < 2; i++) {
                int seg = tid + i * 256;
                int m = seg >> 2, s = seg & 3;
                cpa16(s0 + pl * PLANE_B + m * ROWB + s * 16,
                      g + (size_t)m * K + kel + s * 8);
            }
        }
        cpa_commit();
    };

    issue(0, 0);
    for (int kt = 0; kt < KT; kt++) {
        int st = kt & 1;
        if (kt + 1 < KT) { issue(st ^ 1, kt + 1); cpa_wait<1>(); }
        else             { cpa_wait<0>(); }
        __syncthreads();

        uint32_t sA_h = sbase + st * STAGE_B;
        uint32_t sA_l = sA_h + PLANE_B;
        uint32_t sB_h = sA_h + 2 * PLANE_B;
        uint32_t sB_l = sA_h + 3 * PLANE_B;

#pragma unroll
        for (int ks = 0; ks < 2; ks++) {
            const int kk = ks * 16;
            uint32_t bh[2][4], bl[2][4];
#pragma unroll
            for (int ntp = 0; ntp < 2; ntp++) {
                uint32_t off = (uint32_t)((wn * 32 + ntp * 16 + b_r) * ROWB + (kk + b_c) * 2);
                ldsm4(bh[ntp][0], bh[ntp][1], bh[ntp][2], bh[ntp][3], sB_h + off);
                if (BL) ldsm4(bl[ntp][0], bl[ntp][1], bl[ntp][2], bl[ntp][3], sB_l + off);
            }
#pragma unroll
            for (int mt = 0; mt < 4; mt++) {
                uint32_t off = (uint32_t)((wm * 64 + mt * 16 + a_r) * ROWB + (kk + a_c) * 2);
                uint32_t ah[4], al[4];
                ldsm4(ah[0], ah[1], ah[2], ah[3], sA_h + off);
                ldsm4(al[0], al[1], al[2], al[3], sA_l + off);
#pragma unroll
                for (int nt = 0; nt < 4; nt++) {
                    uint32_t bfh[2] = { bh[nt >> 1][(nt & 1) * 2], bh[nt >> 1][(nt & 1) * 2 + 1] };
                    mma16816(acc[mt][nt], ah, bfh);
                    if (BL) {
                        uint32_t bfl[2] = { bl[nt >> 1][(nt & 1) * 2], bl[nt >> 1][(nt & 1) * 2 + 1] };
                        mma16816(acc[mt][nt], ah, bfl);
                    }
                    mma16816(acc[mt][nt], al, bfh);
                }
            }
        }
        __syncthreads();
    }

    const int r = lane >> 2, q = lane & 3;
#pragma unroll
    for (int mt = 0; mt < 4; mt++) {
#pragma unroll
        for (int nt = 0; nt < 4; nt++) {
            int row = m0 + wm * 64 + mt * 16 + r;
            int col = n0 + wn * 32 + nt * 8 + q * 2;
#pragma unroll
            for (int half = 0; half < 2; half++) {
                int rr2 = row + half * 8;
                float v0 = acc[mt][nt][half * 2 + 0];
                float v1 = acc[mt][nt][half * 2 + 1];
                size_t gidx = (size_t)rr2 * ldC + col;
                if (MODE == 1) {
                    v0 += bias[col];
                    v1 += bias[col + 1];
                    v0 = 0.5f * v0 * (1.0f + erff(v0 * 0.70710678118654752f));
                    v1 = 0.5f * v1 * (1.0f + erff(v1 * 0.70710678118654752f));
                    __nv_bfloat16 h0, h1, l0, l1;
                    split1(v0, h0, l0); split1(v1, h1, l1);
                    *(uint32_t*)&Ch[gidx] = pk2(h0, h1);
                    *(uint32_t*)&Cl[gidx] = pk2(l0, l1);
                } else {
                    if (MODE == 2) {
                        float2 rv = *(const float2*)&R[gidx];
                        v0 += bias[col] + rv.x;
                        v1 += bias[col + 1] + rv.y;
                    } else if (MODE == 3) {
                        float2 rv = *(const float2*)&R[gidx];
                        v0 += rv.x;
                        v1 += rv.y;
                    }
                    *(float2*)&C[gidx] = make_float2(v0, v1);
                    if (MODE == 2 && Ch) {
                        __nv_bfloat16 h0, h1, l0, l1;
                        split1(v0, h0, l0); split1(v1, h1, l1);
                        *(uint32_t*)&Ch[gidx] = pk2(h0, h1);
                        *(uint32_t*)&Cl[gidx] = pk2(l0, l1);
                    }
                }
            }
        }
    }
}

// ---------------- RoPE + split to flash planes (Q hi/lo, K hi, V hi) ----------------
__global__ void rope_split(const float* __restrict__ qkv,
                           uint16_t* __restrict__ fqh, uint16_t* __restrict__ fql,
                           uint16_t* __restrict__ fkh, uint16_t* __restrict__ fvh) {
    int row = blockIdx.x, t = threadIdx.x;
    int i = t & 31;
    int s = row & (SS - 1);
    float inv = __expf(-logf(10000.0f) * ((float)i / 32.0f));
    float ang = (float)s * inv;
    float c = cosf(ang), sn = sinf(ang);
    const float* base = qkv + (size_t)row * 1536;
    size_t dst = (size_t)row * DAA + 2 * t;

    float x1 = base[2 * t], x2 = base[2 * t + 1];
    float o1 = x1 * c - x2 * sn, o2 = x1 * sn + x2 * c;
    __nv_bfloat16 h0, h1, l0, l1;
    split1(o1, h0, l0); split1(o2, h1, l1);
    *(uint32_t*)&fqh[dst] = pk2(h0, h1);
    *(uint32_t*)&fql[dst] = pk2(l0, l1);

    x1 = base[512 + 2 * t]; x2 = base[512 + 2 * t + 1];
    o1 = x1 * c - x2 * sn; o2 = x1 * sn + x2 * c;
    *(uint32_t*)&fkh[dst] = pk2(__float2bfloat16(o1), __float2bfloat16(o2));

    x1 = base[1024 + 2 * t]; x2 = base[1024 + 2 * t + 1];
    *(uint32_t*)&fvh[dst] = pk2(__float2bfloat16(x1), __float2bfloat16(x2));
}

// ---------------- Flash attention: Q hi/lo, K hi, V hi; HMMA + poly exp2 ----------------
template<int ICL>
__global__ void __launch_bounds__(256) flash_mma(
    const uint16_t* __restrict__ Qh, const uint16_t* __restrict__ Ql,
    const uint16_t* __restrict__ Kh, const uint16_t* __restrict__ Vh,
    uint16_t* __restrict__ Oh, uint16_t* __restrict__ Ol)
{
    extern __shared__ char sm[];
    const uint32_t sb = (uint32_t)__cvta_generic_to_shared(sm);
    const uint32_t sQh = sb, sQl = sb + FQPL;
    const uint32_t sKV = sb + 2 * FQPL;
    const int tid = threadIdx.x, warp = tid >> 5, lane = tid & 31;
    const int qt = gridDim.x - 1 - blockIdx.x;
    const int bh = blockIdx.y, b = bh >> 3, h = bh & 7;
    const int qg0 = qt * 128;
    const size_t tokb = (size_t)b * SS;
    const int rb = warp * 16;

    const int rl = lane & 7, grp = lane >> 3;
    const int a_r = rl + (grp & 1) * 8;
    const int a_c = (grp >> 1) * 8;
    const int b_r = rl + ((grp >> 1) & 1) * 8;
    const int b_c = (grp & 1) * 8;

#pragma unroll
    for (int i = 0; i < 8; i++) {
        int job = tid + i * 256;
        int pl = job >> 10, r = (job >> 3) & 127, s = job & 7;
        const uint16_t* g = (pl ? Ql : Qh) + (tokb + qg0 + r) * DAA + h * DHH + s * 8;
        cpa16((pl ? sQl : sQh) + r * FROWB + s * 16, g);
    }
    cpa_commit();

    float out[8][4];
#pragma unroll
    for (int i = 0; i < 8; i++)
#pragma unroll
        for (int j = 0; j < 4; j++) out[i][j] = 0.f;
    float mrow[2] = { -1e30f, -1e30f }, lrow[2] = { 0.f, 0.f };

    const int ktmax = (qg0 + 127) >> 6;

    auto issueKV = [&](int st, int kt) {
        uint32_t s0 = sKV + st * FSTG;
        int kg0 = kt * 64;
#pragma unroll
        for (int i = 0; i < 4; i++) {
            int job = tid + i * 256;
            int pl = job >> 9, r = (job >> 3) & 63, s = job & 7;
            const uint16_t* gp = (pl == 0) ? Kh : Vh;
            cpa16(s0 + pl * FKPL + r * FROWB + s * 16,
                  gp + (tokb + kg0 + r) * DAA + h * DHH + s * 8);
        }
        cpa_commit();
    };
    issueKV(0, 0);

    const int qrow0 = qg0 + rb + (lane >> 2);

    for (int kt = 0; kt <= ktmax; kt++) {
        int st = kt & 1;
        int kg0 = kt * 64;
        if (kt < ktmax) { issueKV(st ^ 1, kt + 1); cpa_wait<1>(); }
        else            { cpa_wait<0>(); }
        __syncthreads();

        uint32_t sK_h = sKV + st * FSTG;
        uint32_t sV_h = sK_h + FKPL;

        float sc[8][4];
#pragma unroll
        for (int i = 0; i < 8; i++)
#pragma unroll
            for (int j = 0; j < 4; j++) sc[i][j] = 0.f;
#pragma unroll
        for (int k16 = 0; k16 < 4; k16++) {
            uint32_t qoff = (uint32_t)((rb + a_r) * FROWB + (k16 * 16 + a_c) * 2);
            uint32_t ah[4], al[4];
            ldsm4(ah[0], ah[1], ah[2], ah[3], sQh + qoff);
            ldsm4(al[0], al[1], al[2], al[3], sQl + qoff);
#pragma unroll
            for (int ntp = 0; ntp < 4; ntp++) {
                uint32_t koff = (uint32_t)((ntp * 16 + b_r) * FROWB + (k16 * 16 + b_c) * 2);
                uint32_t kh[4];
                ldsm4(kh[0], kh[1], kh[2], kh[3], sK_h + koff);
#pragma unroll
                for (int u = 0; u < 2; u++) {
                    int nt = ntp * 2 + u;
                    uint32_t bfh[2] = { kh[u * 2], kh[u * 2 + 1] };
                    mma16816(sc[nt], ah, bfh);
                    mma16816(sc[nt], al, bfh);
                }
            }
        }

        const bool boundary = (kg0 + 63 >= qg0);
#pragma unroll
        for (int nt = 0; nt < 8; nt++) {
#pragma unroll
            for (int c = 0; c < 4; c++) {
                float v = sc[nt][c] * SCALE_L2E;
                if (boundary) {
                    int qg = qrow0 + (c >> 1) * 8;
                    int kg = kg0 + nt * 8 + (lane & 3) * 2 + (c & 1);
                    bool allow = ICL ? (kg < qg || (qg | kg) == 0) : (kg <= qg);
                    v = allow ? v : -1e30f;
                }
                sc[nt][c] = v;
            }
        }

#pragma unroll
        for (int ri = 0; ri < 2; ri++) {
            float mx = -1e30f;
#pragma unroll
            for (int nt = 0; nt < 8; nt++)
                mx = fmaxf(mx, fmaxf(sc[nt][ri * 2], sc[nt][ri * 2 + 1]));
            mx = fmaxf(mx, __shfl_xor_sync(0xffffffffu, mx, 1));
            mx = fmaxf(mx, __shfl_xor_sync(0xffffffffu, mx, 2));
            float mn = fmaxf(mrow[ri], mx);
            float corr = exp2p(mrow[ri] - mn);
            mrow[ri] = mn;
            float rs = 0.f;
#pragma unroll
            for (int nt = 0; nt < 8; nt++) {
                float p0 = exp2p(sc[nt][ri * 2] - mn);
                float p1 = exp2p(sc[nt][ri * 2 + 1] - mn);
                sc[nt][ri * 2] = p0;
                sc[nt][ri * 2 + 1] = p1;
                rs += p0 + p1;
            }
            rs += __shfl_xor_sync(0xffffffffu, rs, 1);
            rs += __shfl_xor_sync(0xffffffffu, rs, 2);
            lrow[ri] = lrow[ri] * corr + rs;
#pragma unroll
            for (int nt = 0; nt < 8; nt++) {
                out[nt][ri * 2] *= corr;
                out[nt][ri * 2 + 1] *= corr;
            }
        }

#pragma unroll
        for (int j = 0; j < 4; j++) {
            uint32_t aP[4];
            aP[0] = pk2(__float2bfloat16(sc[2 * j][0]),     __float2bfloat16(sc[2 * j][1]));
            aP[1] = pk2(__float2bfloat16(sc[2 * j][2]),     __float2bfloat16(sc[2 * j][3]));
            aP[2] = pk2(__float2bfloat16(sc[2 * j + 1][0]), __float2bfloat16(sc[2 * j + 1][1]));
            aP[3] = pk2(__float2bfloat16(sc[2 * j + 1][2]), __float2bfloat16(sc[2 * j + 1][3]));
#pragma unroll
            for (int nt2 = 0; nt2 < 4; nt2++) {
                uint32_t voff = (uint32_t)((j * 16 + (grp & 1) * 8 + rl) * FROWB
                                           + (nt2 * 16 + (grp >> 1) * 8) * 2);
                uint32_t bv[4];
                ldsm4t(bv[0], bv[1], bv[2], bv[3], sV_h + voff);
                uint32_t b0[2] = { bv[0], bv[1] }, b1[2] = { bv[2], bv[3] };
                mma16816(out[nt2 * 2], aP, b0);
                mma16816(out[nt2 * 2 + 1], aP, b1);
            }
        }
        __syncthreads();
    }

#pragma unroll
    for (int ri = 0; ri < 2; ri++) {
        float inv = 1.0f / lrow[ri];
        size_t rbase = (tokb + qrow0 + ri * 8) * DAA + h * DHH + (lane & 3) * 2;
#pragma unroll
        for (int nt = 0; nt < 8; nt++) {
            float v0 = out[nt][ri * 2] * inv;
            float v1 = out[nt][ri * 2 + 1] * inv;
            __nv_bfloat16 h0, h1, l0, l1;
            split1(v0, h0, l0); split1(v1, h1, l1);
            *(uint32_t*)&Oh[rbase + nt * 8] = pk2(h0, h1);
            *(uint32_t*)&Ol[rbase + nt * 8] = pk2(l0, l1);
        }
    }
}

// ---------------- host driver ----------------
#define GETSYM(T, var, sym) T* var; { void* _p; cudaGetSymbolAddress(&_p, sym); var = (T*)_p; }

extern "C" void kernel_launch(void* const* d_in, const int* in_sizes, int n_in,
                              void* d_out, int out_size)
{
    const float* cov_in  = (const float*)d_in[0];
    const float* tgt_in  = (const float*)d_in[1];
    const float* fu_in   = (const float*)d_in[2];
    const float* fc1w    = (const float*)d_in[3];
    const float* fc1b    = (const float*)d_in[4];
    const float* fc2w    = (const float*)d_in[5];
    const float* fc2b    = (const float*)d_in[6];
    const float* icl_wq  = (const float*)d_in[7];
    const float* icl_wk  = (const float*)d_in[8];
    const float* icl_wv  = (const float*)d_in[9];
    const float* icl_wo  = (const float*)d_in[10];
    const float* cov_wq  = (const float*)d_in[11];
    const float* cov_wk  = (const float*)d_in[12];
    const float* cov_wv  = (const float*)d_in[13];
    const float* cov_wo  = (const float*)d_in[14];
    const float* ln_cm_g = (const float*)d_in[15];
    const float* ln_cm_b = (const float*)d_in[16];
    const float* ln_ia_g = (const float*)d_in[17];
    const float* ln_ia_b = (const float*)d_in[18];
    const float* ln_im_g = (const float*)d_in[19];
    const float* ln_im_b = (const float*)d_in[20];

    float* out_cov = (float*)d_out;
    float* out_tgt = out_cov + (size_t)NTOK * EE;
    float* out_fu  = out_tgt + (size_t)NTOK * EE;

    GETSYM(float, qkvI, g_qkvI)    GETSYM(float, qkvC, g_qkvC)
    GETSYM(uint16_t, lnh, pLNh)    GETSYM(uint16_t, lnl, pLNl)
    GETSYM(uint16_t, ln2h, pLN2h)  GETSYM(uint16_t, ln2l, pLN2l)
    GETSYM(uint16_t, midh, pMIDh)  GETSYM(uint16_t, midl, pMIDl)
    GETSYM(uint16_t, mid2h, pMID2h) GETSYM(uint16_t, mid2l, pMID2l)
    GETSYM(uint16_t, qh, pQh)      GETSYM(uint16_t, ql, pQl)
    GETSYM(uint16_t, tgh, pTGTh)   GETSYM(uint16_t, tgl, pTGTl)
    GETSYM(uint16_t, aoIh, pAOIh)  GETSYM(uint16_t, aoIl, pAOIl)
    GETSYM(uint16_t, aoCh, pAOCh)  GETSYM(uint16_t, aoCl, pAOCl)
    GETSYM(uint16_t, fqIh, pFQIh)  GETSYM(uint16_t, fqIl, pFQIl)
    GETSYM(uint16_t, fkIh, pFKIh)  GETSYM(uint16_t, fvIh, pFVIh)
    GETSYM(uint16_t, fqCh, pFQCh)  GETSYM(uint16_t, fqCl, pFQCl)
    GETSYM(uint16_t, fkCh, pFKCh)  GETSYM(uint16_t, fvCh, pFVCh)
    GETSYM(uint16_t, w1h, pW1h)    GETSYM(uint16_t, w1l, pW1l)
    GETSYM(uint16_t, w2h, pW2h)    GETSYM(uint16_t, w2l, pW2l)
    GETSYM(uint16_t, iqkh, pIQKh)  GETSYM(uint16_t, iqkl, pIQKl)
    GETSYM(uint16_t, ivh, pIVh)    GETSYM(uint16_t, ivl, pIVl)
    GETSYM(uint16_t, ioh, pIOh)    GETSYM(uint16_t, iol, pIOl)
    GETSYM(uint16_t, cqkvh, pCQKVh) GETSYM(uint16_t, cqkvl, pCQKVl)
    GETSYM(uint16_t, coh, pCOh)    GETSYM(uint16_t, col, pCOl)

    static cudaStream_t s2 = nullptr;
    static cudaEvent_t ev0 = nullptr, evq = nullptr, evend = nullptr;
    if (!s2) {
        cudaStreamCreateWithFlags(&s2, cudaStreamNonBlocking);
        cudaEventCreateWithFlags(&ev0, cudaEventDisableTiming);
        cudaEventCreateWithFlags(&evq, cudaEventDisableTiming);
        cudaEventCreateWithFlags(&evend, cudaEventDisableTiming);
        cudaFuncSetAttribute(gemm_tc<0, 0>, cudaFuncAttributeMaxDynamicSharedMemorySize, SMEM_GEMM);
        cudaFuncSetAttribute(gemm_tc<1, 0>, cudaFuncAttributeMaxDynamicSharedMemorySize, SMEM_GEMM);
        cudaFuncSetAttribute(gemm_tc<2, 1>, cudaFuncAttributeMaxDynamicSharedMemorySize, SMEM_GEMM);
        cudaFuncSetAttribute(gemm_tc<3, 0>, cudaFuncAttributeMaxDynamicSharedMemorySize, SMEM_GEMM);
        cudaFuncSetAttribute(flash_mma<0>, cudaFuncAttributeMaxDynamicSharedMemorySize, SMEM_FLASH);
        cudaFuncSetAttribute(flash_mma<1>, cudaFuncAttributeMaxDynamicSharedMemorySize, SMEM_FLASH);
    }

    const dim3 thr(256);
    const dim3 gFC1(DMLP / 128, NTOK / 128);
    const dim3 gFC2(EE / 128, NTOK / 128);
    const dim3 gQK(8, NTOK / 128);
    const dim3 gV(4, NTOK / 128);
    const dim3 gQKV(12, NTOK / 128);
    const dim3 gWO(EE / 128, NTOK / 128);
    const dim3 gFLASH(SS / 128, BB * HH);

    // ---- all weight conversions, one launch ----
    ConvJobs cj;
    cj.src[0] = fc1w;   cj.dh[0] = w1h;              cj.dl[0] = w1l;              cj.K[0] = EE;   cj.N[0] = DMLP;
    cj.src[1] = fc2w;   cj.dh[1] = w2h;              cj.dl[1] = w2l;              cj.K[1] = DMLP; cj.N[1] = EE;
    cj.src[2] = icl_wq; cj.dh[2] = iqkh;             cj.dl[2] = iqkl;             cj.K[2] = EE;   cj.N[2] = DAA;
    cj.src[3] = icl_wk; cj.dh[3] = iqkh + 512 * EE;  cj.dl[3] = iqkl + 512 * EE;  cj.K[3] = EE;   cj.N[3] = DAA;
    cj.src[4] = icl_wv; cj.dh[4] = ivh;              cj.dl[4] = ivl;              cj.K[4] = EE;   cj.N[4] = DAA;
    cj.src[5] = cov_wq; cj.dh[5] = cqkvh;            cj.dl[5] = cqkvl;            cj.K[5] = EE;   cj.N[5] = DAA;
    cj.src[6] = cov_wk; cj.dh[6] = cqkvh + 512 * EE; cj.dl[6] = cqkvl + 512 * EE; cj.K[6] = EE;   cj.N[6] = DAA;
    cj.src[7] = cov_wv; cj.dh[7] = cqkvh + 1024 * EE;cj.dl[7] = cqkvl + 1024 * EE;cj.K[7] = EE;   cj.N[7] = DAA;
    cj.src[8] = icl_wo; cj.dh[8] = ioh;              cj.dl[8] = iol;              cj.K[8] = DAA;  cj.N[8] = EE;
    cj.src[9] = cov_wo; cj.dh[9] = coh;              cj.dl[9] = col;              cj.K[9] = DAA;  cj.N[9] = EE;
    conv_all<<<dim3(16, 32, 10), thr>>>(cj);
    cudaEventRecord(ev0, 0);
    cudaStreamWaitEvent(s2, ev0, 0);

    // ---- chain2 on s2: tgt = targets + MLP(LN(functional_update)) ----
    ln_split<<<NTOK, thr, 0, s2>>>(fu_in, ln_im_g, ln_im_b, ln2h, ln2l);
    gemm_tc<1, 0><<<gFC1, thr, SMEM_GEMM, s2>>>(ln2h, ln2l, w1h, nullptr, fc1b, nullptr,
                                                nullptr, mid2h, mid2l, DMLP, EE, DMLP);
    gemm_tc<2, 1><<<gFC2, thr, SMEM_GEMM, s2>>>(mid2h, mid2l, w2h, w2l, fc2b, tgt_in,
                                                out_tgt, tgh, tgl, EE, DMLP, EE);
    // V-projection depends only on tgt — 2-term (weight bf16)
    gemm_tc<0, 0><<<gV, thr, SMEM_GEMM, s2>>>(tgh, tgl, ivh, nullptr, nullptr, nullptr,
                                              qkvI + 1024, nullptr, nullptr, DAA, EE, 1536);

    // ---- chain1 on legacy: cov = covariates + MLP(LN(covariates)); q = LN(cov) ----
    ln_split<<<NTOK, thr>>>(cov_in, ln_cm_g, ln_cm_b, lnh, lnl);
    gemm_tc<1, 0><<<gFC1, thr, SMEM_GEMM>>>(lnh, lnl, w1h, nullptr, fc1b, nullptr,
                                            nullptr, midh, midl, DMLP, EE, DMLP);
    gemm_tc<2, 1><<<gFC2, thr, SMEM_GEMM>>>(midh, midl, w2h, w2l, fc2b, cov_in,
                                            out_cov, nullptr, nullptr, EE, DMLP, EE);
    ln_split<<<NTOK, thr>>>(out_cov, ln_ia_g, ln_ia_b, qh, ql);
    cudaEventRecord(evq, 0);

    // ---- ICL attention on s2 (needs q + tgt) ----
    cudaStreamWaitEvent(s2, evq, 0);
    gemm_tc<0, 0><<<gQK, thr, SMEM_GEMM, s2>>>(qh, ql, iqkh, nullptr, nullptr, nullptr,
                                               qkvI, nullptr, nullptr, 1024, EE, 1536);
    rope_split<<<NTOK, thr, 0, s2>>>(qkvI, fqIh, fqIl, fkIh, fvIh);
    flash_mma<1><<<gFLASH, thr, SMEM_FLASH, s2>>>(fqIh, fqIl, fkIh, fvIh, aoIh, aoIl);
    gemm_tc<3, 0><<<gWO, thr, SMEM_GEMM, s2>>>(aoIh, aoIl, ioh, nullptr, nullptr, fu_in,
                                               out_fu, nullptr, nullptr, EE, DAA, EE);
    cudaEventRecord(evend, s2);

    // ---- COV attention on legacy (needs only q) ----
    gemm_tc<0, 0><<<gQKV, thr, SMEM_GEMM>>>(qh, ql, cqkvh, nullptr, nullptr, nullptr,
                                            qkvC, nullptr, nullptr, 1536, EE, 1536);
    rope_split<<<NTOK, thr>>>(qkvC, fqCh, fqCl, fkCh, fvCh);
    flash_mma<0><<<gFLASH, thr, SMEM_FLASH>>>(fqCh, fqCl, fkCh, fvCh, aoCh, aoCl);
    gemm_tc<3, 0><<<gWO, thr, SMEM_GEMM>>>(aoCh, aoCl, coh, nullptr, nullptr, out_cov,
                                           out_cov, nullptr, nullptr, EE, DAA, EE);

    // join
    cudaStreamWaitEvent(0, evend, 0);
}

// round 16
// speedup vs baseline: 1.4063x; 1.0807x over previous
#include <cuda_runtime.h>
#include <cuda_bf16.h>
#include <math.h>
#include <stdint.h>

#define BB 2
#define SS 2048
#define EE 1024
#define HH 8
#define DHH 64
#define DAA 512
#define DMLP 2048
#define NTOK 4096
#define SCALE_ATTN 0.04419417382415922f
#define SCALE_L2E 0.06375944628228341f   // SCALE_ATTN * log2(e)
#define LN_EPS 1e-5f

// GEMM (round-8 proven config): 128x128 tile, warp 64x32, K-chunk 32, 2-stage,
// padded 80B rows (conflict-free ldmatrix).
#define ROWB 80
#define PLANE_B 10240
#define STAGE_B 40960
#define SMEM_GEMM (2 * STAGE_B)

// Flash: Q hi only, staged once; KV stages carry Kh + Vh.
#define FROWB 144
#define FQPL 18432
#define FKPL 9216
#define FSTG 18432
#define SMEM_FLASH (FQPL + 2 * FSTG)   // 55296

// ---------------- scratch ----------------
__device__ float g_qkvI[NTOK * 1536];
__device__ float g_qkvC[NTOK * 1536];

__device__ uint16_t pLNh[NTOK * EE],     pLNl[NTOK * EE];
__device__ uint16_t pLN2h[NTOK * EE],    pLN2l[NTOK * EE];
__device__ uint16_t pMIDh[NTOK * DMLP],  pMIDl[NTOK * DMLP];
__device__ uint16_t pMID2h[NTOK * DMLP], pMID2l[NTOK * DMLP];
__device__ uint16_t pQh[NTOK * EE],      pQl[NTOK * EE];
__device__ uint16_t pTGTh[NTOK * EE],    pTGTl[NTOK * EE];
__device__ uint16_t pAOIh[NTOK * DAA],   pAOIl[NTOK * DAA];
__device__ uint16_t pAOCh[NTOK * DAA],   pAOCl[NTOK * DAA];
__device__ uint16_t pFQIh[NTOK * DAA];
__device__ uint16_t pFKIh[NTOK * DAA];
__device__ uint16_t pFVIh[NTOK * DAA];
__device__ uint16_t pFQCh[NTOK * DAA];
__device__ uint16_t pFKCh[NTOK * DAA];
__device__ uint16_t pFVCh[NTOK * DAA];

__device__ uint16_t pW1h[DMLP * EE],    pW1l[DMLP * EE];
__device__ uint16_t pW2h[EE * DMLP],    pW2l[EE * DMLP];
__device__ uint16_t pIQKh[1024 * EE],   pIQKl[1024 * EE];
__device__ uint16_t pIVh[DAA * EE],     pIVl[DAA * EE];
__device__ uint16_t pIOh[EE * DAA],     pIOl[EE * DAA];
__device__ uint16_t pCQKVh[1536 * EE],  pCQKVl[1536 * EE];
__device__ uint16_t pCOh[EE * DAA],     pCOl[EE * DAA];

// ---------------- helpers ----------------
__device__ __forceinline__ uint32_t pk2(__nv_bfloat16 a, __nv_bfloat16 b) {
    uint16_t ra = *reinterpret_cast<uint16_t*>(&a);
    uint16_t rb = *reinterpret_cast<uint16_t*>(&b);
    return (uint32_t)ra | ((uint32_t)rb << 16);
}
__device__ __forceinline__ void split1(float x, __nv_bfloat16& h, __nv_bfloat16& l) {
    h = __float2bfloat16(x);
    l = __float2bfloat16(x - __bfloat162float(h));
}
__device__ __forceinline__ void mma16816(float* c, const uint32_t* a, const uint32_t* b) {
    asm volatile(
        "mma.sync.aligned.m16n8k16.row.col.f32.bf16.bf16.f32 "
        "{%0,%1,%2,%3}, {%4,%5,%6,%7}, {%8,%9}, {%0,%1,%2,%3};"
        : "+f"(c[0]), "+f"(c[1]), "+f"(c[2]), "+f"(c[3])
        : "r"(a[0]), "r"(a[1]), "r"(a[2]), "r"(a[3]), "r"(b[0]), "r"(b[1]));
}
__device__ __forceinline__ void ldsm4(uint32_t& r0, uint32_t& r1, uint32_t& r2, uint32_t& r3,
                                      uint32_t addr) {
    asm volatile("ldmatrix.sync.aligned.m8n8.x4.shared.b16 {%0,%1,%2,%3}, [%4];"
                 : "=r"(r0), "=r"(r1), "=r"(r2), "=r"(r3) : "r"(addr));
}
__device__ __forceinline__ void ldsm4t(uint32_t& r0, uint32_t& r1, uint32_t& r2, uint32_t& r3,
                                       uint32_t addr) {
    asm volatile("ldmatrix.sync.aligned.m8n8.x4.trans.shared.b16 {%0,%1,%2,%3}, [%4];"
                 : "=r"(r0), "=r"(r1), "=r"(r2), "=r"(r3) : "r"(addr));
}
__device__ __forceinline__ void cpa16(uint32_t s, const void* g) {
    asm volatile("cp.async.ca.shared.global [%0], [%1], 16;" :: "r"(s), "l"(g));
}
__device__ __forceinline__ void cpa_commit() {
    asm volatile("cp.async.commit_group;" ::: "memory");
}
template<int N>
__device__ __forceinline__ void cpa_wait() {
    asm volatile("cp.async.wait_group %0;" :: "n"(N) : "memory");
}
__device__ __forceinline__ float exp2p(float x) {
    x = fmaxf(x, -80.f);
    float n = rintf(x);
    float f = x - n;
    float p = 1.3333558146428443e-3f;
    p = p * f + 9.618129107628477e-3f;
    p = p * f + 5.550410866482158e-2f;
    p = p * f + 2.402265069591007e-1f;
    p = p * f + 6.931471805599453e-1f;
    p = p * f + 1.0f;
    return p * __int_as_float(((int)n + 127) << 23);
}

__device__ __forceinline__ float block_reduce_sum(float v) {
    __shared__ float red[32];
    int lane = threadIdx.x & 31, w = threadIdx.x >> 5;
#pragma unroll
    for (int o = 16; o > 0; o >>= 1) v += __shfl_xor_sync(0xffffffffu, v, o);
    __syncthreads();
    if (lane == 0) red[w] = v;
    __syncthreads();
    v = (lane < 8) ? red[lane] : 0.f;
#pragma unroll
    for (int o = 16; o > 0; o >>= 1) v += __shfl_xor_sync(0xffffffffu, v, o);
    return v;
}

// ---------------- LayerNorm -> bf16 hi/lo planes ----------------
__global__ void ln_split(const float* __restrict__ x, const float* __restrict__ g,
                         const float* __restrict__ b,
                         uint16_t* __restrict__ oh, uint16_t* __restrict__ ol) {
    int row = blockIdx.x, t = threadIdx.x;
    float4 v = *(const float4*)&x[(size_t)row * EE + 4 * t];
    float s = v.x + v.y + v.z + v.w;
    float mean = block_reduce_sum(s) * (1.0f / EE);
    float d0 = v.x - mean, d1 = v.y - mean, d2 = v.z - mean, d3 = v.w - mean;
    float var = block_reduce_sum(d0 * d0 + d1 * d1 + d2 * d2 + d3 * d3) * (1.0f / EE);
    float rstd = rsqrtf(var + LN_EPS);
    float4 gg = *(const float4*)&g[4 * t];
    float4 bb = *(const float4*)&b[4 * t];
    float y0 = d0 * rstd * gg.x + bb.x;
    float y1 = d1 * rstd * gg.y + bb.y;
    float y2 = d2 * rstd * gg.z + bb.z;
    float y3 = d3 * rstd * gg.w + bb.w;
    __nv_bfloat16 h0, h1, h2, h3, l0, l1, l2, l3;
    split1(y0, h0, l0); split1(y1, h1, l1); split1(y2, h2, l2); split1(y3, h3, l3);
    size_t off = (size_t)row * EE + 4 * t;
    *(uint2*)&oh[off] = make_uint2(pk2(h0, h1), pk2(h2, h3));
    *(uint2*)&ol[off] = make_uint2(pk2(l0, l1), pk2(l2, l3));
}

// ---------------- weight conversion, single launch ----------------
__device__ __forceinline__ void convB_body(const float* __restrict__ W,
                                           uint16_t* __restrict__ Bh,
                                           uint16_t* __restrict__ Bl, int K, int N) {
    __shared__ float ts[64][129];
    int nt = blockIdx.x, kt = blockIdx.y, tid = threadIdx.x;
    int k0 = kt * 64, n0 = nt * 128;
#pragma unroll
    for (int i = 0; i < 32; i++) {
        int idx = tid + i * 256;
        int kk = idx >> 7, nn = idx & 127;
        ts[kk][nn] = W[(size_t)(k0 + kk) * N + n0 + nn];
    }
    __syncthreads();
#pragma unroll
    for (int j = 0; j < 4; j++) {
        int job = tid + j * 256;
        int n = job >> 3, kg = (job & 7) * 8;
        __nv_bfloat16 h[8], l[8];
#pragma unroll
        for (int i = 0; i < 8; i++) split1(ts[kg + i][n], h[i], l[i]);
        uint4 uh = make_uint4(pk2(h[0], h[1]), pk2(h[2], h[3]), pk2(h[4], h[5]), pk2(h[6], h[7]));
        uint4 ul = make_uint4(pk2(l[0], l[1]), pk2(l[2], l[3]), pk2(l[4], l[5]), pk2(l[6], l[7]));
        size_t off = (size_t)(n0 + n) * K + k0 + kg;
        *(uint4*)&Bh[off] = uh;
        *(uint4*)&Bl[off] = ul;
    }
}

struct ConvJobs {
    const float* src[10];
    uint16_t* dh[10];
    uint16_t* dl[10];
    int K[10], N[10];
};
__global__ void conv_all(ConvJobs j) {
    int w = blockIdx.z;
    int K = j.K[w], N = j.N[w];
    if (blockIdx.x * 128 >= N || blockIdx.y * 64 >= K) return;
    convB_body(j.src[w], j.dh[w], j.dl[w], K, N);
}

// ---------------- HMMA bf16-split GEMM ----------------
// MODE 0: C=AB(fp32, ldC)  1: planes=gelu(AB+bias)  2: C=AB+bias+R (+planes)  3: C=AB+R
// AL: include Al*Bh term (activation lo plane).  BL: include Ah*Bl term (weight lo plane).
template<int MODE, int BL, int AL>
__global__ void __launch_bounds__(256, 2) gemm_tc(
    const uint16_t* __restrict__ Ah, const uint16_t* __restrict__ Al,
    const uint16_t* __restrict__ Bh, const uint16_t* __restrict__ Bl,
    const float* __restrict__ bias, const float* __restrict__ R,
    float* __restrict__ C, uint16_t* __restrict__ Ch, uint16_t* __restrict__ Cl,
    int N, int K, int ldC)
{
    extern __shared__ char sm[];
    const uint32_t sbase = (uint32_t)__cvta_generic_to_shared(sm);
    const int tid = threadIdx.x;
    const int warp = tid >> 5, lane = tid & 31;
    const int wm = warp & 1, wn = warp >> 1;
    const int m0 = blockIdx.y * 128, n0 = blockIdx.x * 128;
    const int KT = K >> 5;

    const uint16_t* gA[2] = { Ah + (size_t)m0 * K, AL ? (Al + (size_t)m0 * K) : nullptr };
    const uint16_t* gB[2] = { Bh + (size_t)n0 * K, BL ? (Bl + (size_t)n0 * K) : nullptr };

    const int rl = lane & 7, grp = lane >> 3;
    const int a_r = rl + (grp & 1) * 8;
    const int a_c = (grp >> 1) * 8;
    const int b_r = rl + ((grp >> 1) & 1) * 8;
    const int b_c = (grp & 1) * 8;

    float acc[4][4][4];
#pragma unroll
    for (int i = 0; i < 4; i++)
#pragma unroll
        for (int j = 0; j < 4; j++)
#pragma unroll
            for (int k = 0; k < 4; k++) acc[i][j][k] = 0.f;

    auto issue = [&](int stage, int kt) {
        uint32_t s0 = sbase + stage * STAGE_B;
        int kel = kt * 32;
#pragma unroll
        for (int pl = 0; pl < 4; pl++) {
            if (pl == 1 && !AL) continue;
            if (pl == 3 && !BL) continue;
            const uint16_t* g = (pl < 2) ? gA[pl] : gB[pl - 2];
#pragma unroll
            for (int i = 0; i < 2; i++) {
                int seg = tid + i * 256;
                int m = seg >> 2, s = seg & 3;
                cpa16(s0 + pl * PLANE_B + m * ROWB + s * 16,
                      g + (size_t)m * K + kel + s * 8);
            }
        }
        cpa_commit();
    };

    issue(0, 0);
    for (int kt = 0; kt < KT; kt++) {
        int st = kt & 1;
        if (kt + 1 < KT) { issue(st ^ 1, kt + 1); cpa_wait<1>(); }
        else             { cpa_wait<0>(); }
        __syncthreads();

        uint32_t sA_h = sbase + st * STAGE_B;
        uint32_t sA_l = sA_h + PLANE_B;
        uint32_t sB_h = sA_h + 2 * PLANE_B;
        uint32_t sB_l = sA_h + 3 * PLANE_B;

#pragma unroll
        for (int ks = 0; ks < 2; ks++) {
            const int kk = ks * 16;
            uint32_t bh[2][4], bl[2][4];
#pragma unroll
            for (int ntp = 0; ntp < 2; ntp++) {
                uint32_t off = (uint32_t)((wn * 32 + ntp * 16 + b_r) * ROWB + (kk + b_c) * 2);
                ldsm4(bh[ntp][0], bh[ntp][1], bh[ntp][2], bh[ntp][3], sB_h + off);
                if (BL) ldsm4(bl[ntp][0], bl[ntp][1], bl[ntp][2], bl[ntp][3], sB_l + off);
            }
#pragma unroll
            for (int mt = 0; mt < 4; mt++) {
                uint32_t off = (uint32_t)((wm * 64 + mt * 16 + a_r) * ROWB + (kk + a_c) * 2);
                uint32_t ah[4], al[4];
                ldsm4(ah[0], ah[1], ah[2], ah[3], sA_h + off);
                if (AL) ldsm4(al[0], al[1], al[2], al[3], sA_l + off);
#pragma unroll
                for (int nt = 0; nt < 4; nt++) {
                    uint32_t bfh[2] = { bh[nt >> 1][(nt & 1) * 2], bh[nt >> 1][(nt & 1) * 2 + 1] };
                    mma16816(acc[mt][nt], ah, bfh);
                    if (BL) {
                        uint32_t bfl[2] = { bl[nt >> 1][(nt & 1) * 2], bl[nt >> 1][(nt & 1) * 2 + 1] };
                        mma16816(acc[mt][nt], ah, bfl);
                    }
                    if (AL) mma16816(acc[mt][nt], al, bfh);
                }
            }
        }
        __syncthreads();
    }

    const int r = lane >> 2, q = lane & 3;
#pragma unroll
    for (int mt = 0; mt < 4; mt++) {
#pragma unroll
        for (int nt = 0; nt < 4; nt++) {
            int row = m0 + wm * 64 + mt * 16 + r;
            int col = n0 + wn * 32 + nt * 8 + q * 2;
#pragma unroll
            for (int half = 0; half < 2; half++) {
                int rr2 = row + half * 8;
                float v0 = acc[mt][nt][half * 2 + 0];
                float v1 = acc[mt][nt][half * 2 + 1];
                size_t gidx = (size_t)rr2 * ldC + col;
                if (MODE == 1) {
                    v0 += bias[col];
                    v1 += bias[col + 1];
                    v0 = 0.5f * v0 * (1.0f + erff(v0 * 0.70710678118654752f));
                    v1 = 0.5f * v1 * (1.0f + erff(v1 * 0.70710678118654752f));
                    __nv_bfloat16 h0, h1, l0, l1;
                    split1(v0, h0, l0); split1(v1, h1, l1);
                    *(uint32_t*)&Ch[gidx] = pk2(h0, h1);
                    *(uint32_t*)&Cl[gidx] = pk2(l0, l1);
                } else {
                    if (MODE == 2) {
                        float2 rv = *(const float2*)&R[gidx];
                        v0 += bias[col] + rv.x;
                        v1 += bias[col + 1] + rv.y;
                    } else if (MODE == 3) {
                        float2 rv = *(const float2*)&R[gidx];
                        v0 += rv.x;
                        v1 += rv.y;
                    }
                    *(float2*)&C[gidx] = make_float2(v0, v1);
                    if (MODE == 2 && Ch) {
                        __nv_bfloat16 h0, h1, l0, l1;
                        split1(v0, h0, l0); split1(v1, h1, l1);
                        *(uint32_t*)&Ch[gidx] = pk2(h0, h1);
                        *(uint32_t*)&Cl[gidx] = pk2(l0, l1);
                    }
                }
            }
        }
    }
}

// ---------------- RoPE + split to flash planes (Q hi, K hi, V hi) ----------------
__global__ void rope_split(const float* __restrict__ qkv,
                           uint16_t* __restrict__ fqh,
                           uint16_t* __restrict__ fkh, uint16_t* __restrict__ fvh) {
    int row = blockIdx.x, t = threadIdx.x;
    int i = t & 31;
    int s = row & (SS - 1);
    float inv = __expf(-logf(10000.0f) * ((float)i / 32.0f));
    float ang = (float)s * inv;
    float c = cosf(ang), sn = sinf(ang);
    const float* base = qkv + (size_t)row * 1536;
    size_t dst = (size_t)row * DAA + 2 * t;

    float x1 = base[2 * t], x2 = base[2 * t + 1];
    float o1 = x1 * c - x2 * sn, o2 = x1 * sn + x2 * c;
    *(uint32_t*)&fqh[dst] = pk2(__float2bfloat16(o1), __float2bfloat16(o2));

    x1 = base[512 + 2 * t]; x2 = base[512 + 2 * t + 1];
    o1 = x1 * c - x2 * sn; o2 = x1 * sn + x2 * c;
    *(uint32_t*)&fkh[dst] = pk2(__float2bfloat16(o1), __float2bfloat16(o2));

    x1 = base[1024 + 2 * t]; x2 = base[1024 + 2 * t + 1];
    *(uint32_t*)&fvh[dst] = pk2(__float2bfloat16(x1), __float2bfloat16(x2));
}

// ---------------- Flash attention: Q hi, K hi, V hi; HMMA + poly exp2 ----------------
template<int ICL>
__global__ void __launch_bounds__(256) flash_mma(
    const uint16_t* __restrict__ Qh,
    const uint16_t* __restrict__ Kh, const uint16_t* __restrict__ Vh,
    uint16_t* __restrict__ Oh, uint16_t* __restrict__ Ol)
{
    extern __shared__ char sm[];
    const uint32_t sb = (uint32_t)__cvta_generic_to_shared(sm);
    const uint32_t sQh = sb;
    const uint32_t sKV = sb + FQPL;
    const int tid = threadIdx.x, warp = tid >> 5, lane = tid & 31;
    const int qt = gridDim.x - 1 - blockIdx.x;
    const int bh = blockIdx.y, b = bh >> 3, h = bh & 7;
    const int qg0 = qt * 128;
    const size_t tokb = (size_t)b * SS;
    const int rb = warp * 16;

    const int rl = lane & 7, grp = lane >> 3;
    const int a_r = rl + (grp & 1) * 8;
    const int a_c = (grp >> 1) * 8;
    const int b_r = rl + ((grp >> 1) & 1) * 8;
    const int b_c = (grp & 1) * 8;

#pragma unroll
    for (int i = 0; i < 4; i++) {
        int job = tid + i * 256;
        int r = (job >> 3) & 127, s = job & 7;
        cpa16(sQh + r * FROWB + s * 16,
              Qh + (tokb + qg0 + r) * DAA + h * DHH + s * 8);
    }
    cpa_commit();

    float out[8][4];
#pragma unroll
    for (int i = 0; i < 8; i++)
#pragma unroll
        for (int j = 0; j < 4; j++) out[i][j] = 0.f;
    float mrow[2] = { -1e30f, -1e30f }, lrow[2] = { 0.f, 0.f };

    const int ktmax = (qg0 + 127) >> 6;

    auto issueKV = [&](int st, int kt) {
        uint32_t s0 = sKV + st * FSTG;
        int kg0 = kt * 64;
#pragma unroll
        for (int i = 0; i < 4; i++) {
            int job = tid + i * 256;
            int pl = job >> 9, r = (job >> 3) & 63, s = job & 7;
            const uint16_t* gp = (pl == 0) ? Kh : Vh;
            cpa16(s0 + pl * FKPL + r * FROWB + s * 16,
                  gp + (tokb + kg0 + r) * DAA + h * DHH + s * 8);
        }
        cpa_commit();
    };
    issueKV(0, 0);

    const int qrow0 = qg0 + rb + (lane >> 2);

    for (int kt = 0; kt <= ktmax; kt++) {
        int st = kt & 1;
        int kg0 = kt * 64;
        if (kt < ktmax) { issueKV(st ^ 1, kt + 1); cpa_wait<1>(); }
        else            { cpa_wait<0>(); }
        __syncthreads();

        uint32_t sK_h = sKV + st * FSTG;
        uint32_t sV_h = sK_h + FKPL;

        float sc[8][4];
#pragma unroll
        for (int i = 0; i < 8; i++)
#pragma unroll
            for (int j = 0; j < 4; j++) sc[i][j] = 0.f;
#pragma unroll
        for (int k16 = 0; k16 < 4; k16++) {
            uint32_t qoff = (uint32_t)((rb + a_r) * FROWB + (k16 * 16 + a_c) * 2);
            uint32_t ah[4];
            ldsm4(ah[0], ah[1], ah[2], ah[3], sQh + qoff);
#pragma unroll
            for (int ntp = 0; ntp < 4; ntp++) {
                uint32_t koff = (uint32_t)((ntp * 16 + b_r) * FROWB + (k16 * 16 + b_c) * 2);
                uint32_t kh[4];
                ldsm4(kh[0], kh[1], kh[2], kh[3], sK_h + koff);
#pragma unroll
                for (int u = 0; u < 2; u++) {
                    int nt = ntp * 2 + u;
                    uint32_t bfh[2] = { kh[u * 2], kh[u * 2 + 1] };
                    mma16816(sc[nt], ah, bfh);
                }
            }
        }

        const bool boundary = (kg0 + 63 >= qg0);
#pragma unroll
        for (int nt = 0; nt < 8; nt++) {
#pragma unroll
            for (int c = 0; c < 4; c++) {
                float v = sc[nt][c] * SCALE_L2E;
                if (boundary) {
                    int qg = qrow0 + (c >> 1) * 8;
                    int kg = kg0 + nt * 8 + (lane & 3) * 2 + (c & 1);
                    bool allow = ICL ? (kg < qg || (qg | kg) == 0) : (kg <= qg);
                    v = allow ? v : -1e30f;
                }
                sc[nt][c] = v;
            }
        }

#pragma unroll
        for (int ri = 0; ri < 2; ri++) {
            float mx = -1e30f;
#pragma unroll
            for (int nt = 0; nt < 8; nt++)
                mx = fmaxf(mx, fmaxf(sc[nt][ri * 2], sc[nt][ri * 2 + 1]));
            mx = fmaxf(mx, __shfl_xor_sync(0xffffffffu, mx, 1));
            mx = fmaxf(mx, __shfl_xor_sync(0xffffffffu, mx, 2));
            float mn = fmaxf(mrow[ri], mx);
            float corr = exp2p(mrow[ri] - mn);
            mrow[ri] = mn;
            float rs = 0.f;
#pragma unroll
            for (int nt = 0; nt < 8; nt++) {
                float p0 = exp2p(sc[nt][ri * 2] - mn);
                float p1 = exp2p(sc[nt][ri * 2 + 1] - mn);
                sc[nt][ri * 2] = p0;
                sc[nt][ri * 2 + 1] = p1;
                rs += p0 + p1;
            }
            rs += __shfl_xor_sync(0xffffffffu, rs, 1);
            rs += __shfl_xor_sync(0xffffffffu, rs, 2);
            lrow[ri] = lrow[ri] * corr + rs;
#pragma unroll
            for (int nt = 0; nt < 8; nt++) {
                out[nt][ri * 2] *= corr;
                out[nt][ri * 2 + 1] *= corr;
            }
        }

#pragma unroll
        for (int j = 0; j < 4; j++) {
            uint32_t aP[4];
            aP[0] = pk2(__float2bfloat16(sc[2 * j][0]),     __float2bfloat16(sc[2 * j][1]));
            aP[1] = pk2(__float2bfloat16(sc[2 * j][2]),     __float2bfloat16(sc[2 * j][3]));
            aP[2] = pk2(__float2bfloat16(sc[2 * j + 1][0]), __float2bfloat16(sc[2 * j + 1][1]));
            aP[3] = pk2(__float2bfloat16(sc[2 * j + 1][2]), __float2bfloat16(sc[2 * j + 1][3]));
#pragma unroll
            for (int nt2 = 0; nt2 < 4; nt2++) {
                uint32_t voff = (uint32_t)((j * 16 + (grp & 1) * 8 + rl) * FROWB
                                           + (nt2 * 16 + (grp >> 1) * 8) * 2);
                uint32_t bv[4];
                ldsm4t(bv[0], bv[1], bv[2], bv[3], sV_h + voff);
                uint32_t b0[2] = { bv[0], bv[1] }, b1[2] = { bv[2], bv[3] };
                mma16816(out[nt2 * 2], aP, b0);
                mma16816(out[nt2 * 2 + 1], aP, b1);
            }
        }
        __syncthreads();
    }

#pragma unroll
    for (int ri = 0; ri < 2; ri++) {
        float inv = 1.0f / lrow[ri];
        size_t rbase = (tokb + qrow0 + ri * 8) * DAA + h * DHH + (lane & 3) * 2;
#pragma unroll
        for (int nt = 0; nt < 8; nt++) {
            float v0 = out[nt][ri * 2] * inv;
            float v1 = out[nt][ri * 2 + 1] * inv;
            __nv_bfloat16 h0, h1, l0, l1;
            split1(v0, h0, l0); split1(v1, h1, l1);
            *(uint32_t*)&Oh[rbase + nt * 8] = pk2(h0, h1);
            *(uint32_t*)&Ol[rbase + nt * 8] = pk2(l0, l1);
        }
    }
}

// ---------------- host driver ----------------
#define GETSYM(T, var, sym) T* var; { void* _p; cudaGetSymbolAddress(&_p, sym); var = (T*)_p; }

extern "C" void kernel_launch(void* const* d_in, const int* in_sizes, int n_in,
                              void* d_out, int out_size)
{
    const float* cov_in  = (const float*)d_in[0];
    const float* tgt_in  = (const float*)d_in[1];
    const float* fu_in   = (const float*)d_in[2];
    const float* fc1w    = (const float*)d_in[3];
    const float* fc1b    = (const float*)d_in[4];
    const float* fc2w    = (const float*)d_in[5];
    const float* fc2b    = (const float*)d_in[6];
    const float* icl_wq  = (const float*)d_in[7];
    const float* icl_wk  = (const float*)d_in[8];
    const float* icl_wv  = (const float*)d_in[9];
    const float* icl_wo  = (const float*)d_in[10];
    const float* cov_wq  = (const float*)d_in[11];
    const float* cov_wk  = (const float*)d_in[12];
    const float* cov_wv  = (const float*)d_in[13];
    const float* cov_wo  = (const float*)d_in[14];
    const float* ln_cm_g = (const float*)d_in[15];
    const float* ln_cm_b = (const float*)d_in[16];
    const float* ln_ia_g = (const float*)d_in[17];
    const float* ln_ia_b = (const float*)d_in[18];
    const float* ln_im_g = (const float*)d_in[19];
    const float* ln_im_b = (const float*)d_in[20];

    float* out_cov = (float*)d_out;
    float* out_tgt = out_cov + (size_t)NTOK * EE;
    float* out_fu  = out_tgt + (size_t)NTOK * EE;

    GETSYM(float, qkvI, g_qkvI)    GETSYM(float, qkvC, g_qkvC)
    GETSYM(uint16_t, lnh, pLNh)    GETSYM(uint16_t, lnl, pLNl)
    GETSYM(uint16_t, ln2h, pLN2h)  GETSYM(uint16_t, ln2l, pLN2l)
    GETSYM(uint16_t, midh, pMIDh)  GETSYM(uint16_t, midl, pMIDl)
    GETSYM(uint16_t, mid2h, pMID2h) GETSYM(uint16_t, mid2l, pMID2l)
    GETSYM(uint16_t, qh, pQh)      GETSYM(uint16_t, ql, pQl)
    GETSYM(uint16_t, tgh, pTGTh)   GETSYM(uint16_t, tgl, pTGTl)
    GETSYM(uint16_t, aoIh, pAOIh)  GETSYM(uint16_t, aoIl, pAOIl)
    GETSYM(uint16_t, aoCh, pAOCh)  GETSYM(uint16_t, aoCl, pAOCl)
    GETSYM(uint16_t, fqIh, pFQIh)
    GETSYM(uint16_t, fkIh, pFKIh)  GETSYM(uint16_t, fvIh, pFVIh)
    GETSYM(uint16_t, fqCh, pFQCh)
    GETSYM(uint16_t, fkCh, pFKCh)  GETSYM(uint16_t, fvCh, pFVCh)
    GETSYM(uint16_t, w1h, pW1h)    GETSYM(uint16_t, w1l, pW1l)
    GETSYM(uint16_t, w2h, pW2h)    GETSYM(uint16_t, w2l, pW2l)
    GETSYM(uint16_t, iqkh, pIQKh)  GETSYM(uint16_t, iqkl, pIQKl)
    GETSYM(uint16_t, ivh, pIVh)    GETSYM(uint16_t, ivl, pIVl)
    GETSYM(uint16_t, ioh, pIOh)    GETSYM(uint16_t, iol, pIOl)
    GETSYM(uint16_t, cqkvh, pCQKVh) GETSYM(uint16_t, cqkvl, pCQKVl)
    GETSYM(uint16_t, coh, pCOh)    GETSYM(uint16_t, col, pCOl)

    static cudaStream_t s2 = nullptr;
    static cudaEvent_t ev0 = nullptr, evq = nullptr, evend = nullptr;
    if (!s2) {
        cudaStreamCreateWithFlags(&s2, cudaStreamNonBlocking);
        cudaEventCreateWithFlags(&ev0, cudaEventDisableTiming);
        cudaEventCreateWithFlags(&evq, cudaEventDisableTiming);
        cudaEventCreateWithFlags(&evend, cudaEventDisableTiming);
        cudaFuncSetAttribute((const void*)gemm_tc<0, 0, 0>, cudaFuncAttributeMaxDynamicSharedMemorySize, SMEM_GEMM);
        cudaFuncSetAttribute((const void*)gemm_tc<1, 0, 1>, cudaFuncAttributeMaxDynamicSharedMemorySize, SMEM_GEMM);
        cudaFuncSetAttribute((const void*)gemm_tc<2, 1, 1>, cudaFuncAttributeMaxDynamicSharedMemorySize, SMEM_GEMM);
        cudaFuncSetAttribute((const void*)gemm_tc<3, 0, 1>, cudaFuncAttributeMaxDynamicSharedMemorySize, SMEM_GEMM);
        cudaFuncSetAttribute((const void*)flash_mma<0>, cudaFuncAttributeMaxDynamicSharedMemorySize, SMEM_FLASH);
        cudaFuncSetAttribute((const void*)flash_mma<1>, cudaFuncAttributeMaxDynamicSharedMemorySize, SMEM_FLASH);
    }

    const dim3 thr(256);
    const dim3 gFC1(DMLP / 128, NTOK / 128);
    const dim3 gFC2(EE / 128, NTOK / 128);
    const dim3 gQK(8, NTOK / 128);
    const dim3 gV(4, NTOK / 128);
    const dim3 gQKV(12, NTOK / 128);
    const dim3 gWO(EE / 128, NTOK / 128);
    const dim3 gFLASH(SS / 128, BB * HH);

    // ---- all weight conversions, one launch ----
    ConvJobs cj;
    cj.src[0] = fc1w;   cj.dh[0] = w1h;              cj.dl[0] = w1l;              cj.K[0] = EE;   cj.N[0] = DMLP;
    cj.src[1] = fc2w;   cj.dh[1] = w2h;              cj.dl[1] = w2l;              cj.K[1] = DMLP; cj.N[1] = EE;
    cj.src[2] = icl_wq; cj.dh[2] = iqkh;             cj.dl[2] = iqkl;             cj.K[2] = EE;   cj.N[2] = DAA;
    cj.src[3] = icl_wk; cj.dh[3] = iqkh + 512 * EE;  cj.dl[3] = iqkl + 512 * EE;  cj.K[3] = EE;   cj.N[3] = DAA;
    cj.src[4] = icl_wv; cj.dh[4] = ivh;              cj.dl[4] = ivl;              cj.K[4] = EE;   cj.N[4] = DAA;
    cj.src[5] = cov_wq; cj.dh[5] = cqkvh;            cj.dl[5] = cqkvl;            cj.K[5] = EE;   cj.N[5] = DAA;
    cj.src[6] = cov_wk; cj.dh[6] = cqkvh + 512 * EE; cj.dl[6] = cqkvl + 512 * EE; cj.K[6] = EE;   cj.N[6] = DAA;
    cj.src[7] = cov_wv; cj.dh[7] = cqkvh + 1024 * EE;cj.dl[7] = cqkvl + 1024 * EE;cj.K[7] = EE;   cj.N[7] = DAA;
    cj.src[8] = icl_wo; cj.dh[8] = ioh;              cj.dl[8] = iol;              cj.K[8] = DAA;  cj.N[8] = EE;
    cj.src[9] = cov_wo; cj.dh[9] = coh;              cj.dl[9] = col;              cj.K[9] = DAA;  cj.N[9] = EE;
    conv_all<<<dim3(16, 32, 10), thr>>>(cj);
    cudaEventRecord(ev0, 0);
    cudaStreamWaitEvent(s2, ev0, 0);

    // ---- chain2 on s2: tgt = targets + MLP(LN(functional_update)) ----
    ln_split<<<NTOK, thr, 0, s2>>>(fu_in, ln_im_g, ln_im_b, ln2h, ln2l);
    gemm_tc<1, 0, 1><<<gFC1, thr, SMEM_GEMM, s2>>>(ln2h, ln2l, w1h, nullptr, fc1b, nullptr,
                                                   nullptr, mid2h, mid2l, DMLP, EE, DMLP);
    gemm_tc<2, 1, 1><<<gFC2, thr, SMEM_GEMM, s2>>>(mid2h, mid2l, w2h, w2l, fc2b, tgt_in,
                                                   out_tgt, tgh, tgl, EE, DMLP, EE);
    // V-projection depends only on tgt — pure bf16
    gemm_tc<0, 0, 0><<<gV, thr, SMEM_GEMM, s2>>>(tgh, nullptr, ivh, nullptr, nullptr, nullptr,
                                                 qkvI + 1024, nullptr, nullptr, DAA, EE, 1536);

    // ---- chain1 on legacy: cov = covariates + MLP(LN(covariates)); q = LN(cov) ----
    ln_split<<<NTOK, thr>>>(cov_in, ln_cm_g, ln_cm_b, lnh, lnl);
    gemm_tc<1, 0, 1><<<gFC1, thr, SMEM_GEMM>>>(lnh, lnl, w1h, nullptr, fc1b, nullptr,
                                               nullptr, midh, midl, DMLP, EE, DMLP);
    gemm_tc<2, 1, 1><<<gFC2, thr, SMEM_GEMM>>>(midh, midl, w2h, w2l, fc2b, cov_in,
                                               out_cov, nullptr, nullptr, EE, DMLP, EE);
    ln_split<<<NTOK, thr>>>(out_cov, ln_ia_g, ln_ia_b, qh, ql);
    cudaEventRecord(evq, 0);

    // ---- ICL attention on s2 (needs q + tgt) ----
    cudaStreamWaitEvent(s2, evq, 0);
    gemm_tc<0, 0, 0><<<gQK, thr, SMEM_GEMM, s2>>>(qh, nullptr, iqkh, nullptr, nullptr, nullptr,
                                                  qkvI, nullptr, nullptr, 1024, EE, 1536);
    rope_split<<<NTOK, thr, 0, s2>>>(qkvI, fqIh, fkIh, fvIh);
    flash_mma<1><<<gFLASH, thr, SMEM_FLASH, s2>>>(fqIh, fkIh, fvIh, aoIh, aoIl);
    gemm_tc<3, 0, 1><<<gWO, thr, SMEM_GEMM, s2>>>(aoIh, aoIl, ioh, nullptr, nullptr, fu_in,
                                                  out_fu, nullptr, nullptr, EE, DAA, EE);
    cudaEventRecord(evend, s2);

    // ---- COV attention on legacy (needs only q) ----
    gemm_tc<0, 0, 0><<<gQKV, thr, SMEM_GEMM>>>(qh, nullptr, cqkvh, nullptr, nullptr, nullptr,
                                               qkvC, nullptr, nullptr, 1536, EE, 1536);
    rope_split<<<NTOK, thr>>>(qkvC, fqCh, fkCh, fvCh);
    flash_mma<0><<<gFLASH, thr, SMEM_FLASH>>>(fqCh, fkCh, fvCh, aoCh, aoCl);
    gemm_tc<3, 0, 1><<<gWO, thr, SMEM_GEMM>>>(aoCh, aoCl, coh, nullptr, nullptr, out_cov,
                                              out_cov, nullptr, nullptr, EE, DAA, EE);

    // join
    cudaStreamWaitEvent(0, evend, 0);
}

// round 17
// speedup vs baseline: 1.5642x; 1.1123x over previous
#include <cuda_runtime.h>
#include <cuda_bf16.h>
#include <math.h>
#include <stdint.h>

#define BB 2
#define SS 2048
#define EE 1024
#define HH 8
#define DHH 64
#define DAA 512
#define DMLP 2048
#define NTOK 4096
#define SCALE_ATTN 0.04419417382415922f
#define SCALE_L2E 0.06375944628228341f   // SCALE_ATTN * log2(e)
#define LN_EPS 1e-5f

// GEMM (round-8 proven config): 128x128 tile, warp 64x32, K-chunk 32, 2-stage,
// padded 80B rows (conflict-free ldmatrix).
#define ROWB 80
#define PLANE_B 10240
#define STAGE_B 40960
#define SMEM_GEMM (2 * STAGE_B)

// Flash: Q hi only, staged once; KV stages carry Kh + Vh.
#define FROWB 144
#define FQPL 18432
#define FKPL 9216
#define FSTG 18432
#define SMEM_FLASH (FQPL + 2 * FSTG)   // 55296

// ---------------- scratch ----------------
__device__ float g_qkvI[NTOK * 1536];
__device__ float g_qkvC[NTOK * 1536];

__device__ uint16_t pLNh[NTOK * EE],     pLNl[NTOK * EE];
__device__ uint16_t pLN2h[NTOK * EE],    pLN2l[NTOK * EE];
__device__ uint16_t pMIDh[NTOK * DMLP],  pMIDl[NTOK * DMLP];
__device__ uint16_t pMID2h[NTOK * DMLP], pMID2l[NTOK * DMLP];
__device__ uint16_t pQh[NTOK * EE],      pQl[NTOK * EE];
__device__ uint16_t pTGTh[NTOK * EE],    pTGTl[NTOK * EE];
__device__ uint16_t pAOIh[NTOK * DAA],   pAOIl[NTOK * DAA];
__device__ uint16_t pAOCh[NTOK * DAA],   pAOCl[NTOK * DAA];
__device__ uint16_t pFQIh[NTOK * DAA];
__device__ uint16_t pFKIh[NTOK * DAA];
__device__ uint16_t pFVIh[NTOK * DAA];
__device__ uint16_t pFQCh[NTOK * DAA];
__device__ uint16_t pFKCh[NTOK * DAA];
__device__ uint16_t pFVCh[NTOK * DAA];

// weight planes: hi only (no consumer of weight-lo remains)
__device__ uint16_t pW1h[DMLP * EE];
__device__ uint16_t pW2h[EE * DMLP];
__device__ uint16_t pIQKh[1024 * EE];
__device__ uint16_t pIVh[DAA * EE];
__device__ uint16_t pIOh[EE * DAA];
__device__ uint16_t pCQKVh[1536 * EE];
__device__ uint16_t pCOh[EE * DAA];

// ---------------- helpers ----------------
__device__ __forceinline__ uint32_t pk2(__nv_bfloat16 a, __nv_bfloat16 b) {
    uint16_t ra = *reinterpret_cast<uint16_t*>(&a);
    uint16_t rb = *reinterpret_cast<uint16_t*>(&b);
    return (uint32_t)ra | ((uint32_t)rb << 16);
}
__device__ __forceinline__ void split1(float x, __nv_bfloat16& h, __nv_bfloat16& l) {
    h = __float2bfloat16(x);
    l = __float2bfloat16(x - __bfloat162float(h));
}
__device__ __forceinline__ void mma16816(float* c, const uint32_t* a, const uint32_t* b) {
    asm volatile(
        "mma.sync.aligned.m16n8k16.row.col.f32.bf16.bf16.f32 "
        "{%0,%1,%2,%3}, {%4,%5,%6,%7}, {%8,%9}, {%0,%1,%2,%3};"
        : "+f"(c[0]), "+f"(c[1]), "+f"(c[2]), "+f"(c[3])
        : "r"(a[0]), "r"(a[1]), "r"(a[2]), "r"(a[3]), "r"(b[0]), "r"(b[1]));
}
__device__ __forceinline__ void ldsm4(uint32_t& r0, uint32_t& r1, uint32_t& r2, uint32_t& r3,
                                      uint32_t addr) {
    asm volatile("ldmatrix.sync.aligned.m8n8.x4.shared.b16 {%0,%1,%2,%3}, [%4];"
                 : "=r"(r0), "=r"(r1), "=r"(r2), "=r"(r3) : "r"(addr));
}
__device__ __forceinline__ void ldsm4t(uint32_t& r0, uint32_t& r1, uint32_t& r2, uint32_t& r3,
                                       uint32_t addr) {
    asm volatile("ldmatrix.sync.aligned.m8n8.x4.trans.shared.b16 {%0,%1,%2,%3}, [%4];"
                 : "=r"(r0), "=r"(r1), "=r"(r2), "=r"(r3) : "r"(addr));
}
__device__ __forceinline__ void cpa16(uint32_t s, const void* g) {
    asm volatile("cp.async.ca.shared.global [%0], [%1], 16;" :: "r"(s), "l"(g));
}
__device__ __forceinline__ void cpa_commit() {
    asm volatile("cp.async.commit_group;" ::: "memory");
}
template<int N>
__device__ __forceinline__ void cpa_wait() {
    asm volatile("cp.async.wait_group %0;" :: "n"(N) : "memory");
}
__device__ __forceinline__ float exp2p(float x) {
    x = fmaxf(x, -80.f);
    float n = rintf(x);
    float f = x - n;
    float p = 1.3333558146428443e-3f;
    p = p * f + 9.618129107628477e-3f;
    p = p * f + 5.550410866482158e-2f;
    p = p * f + 2.402265069591007e-1f;
    p = p * f + 6.931471805599453e-1f;
    p = p * f + 1.0f;
    return p * __int_as_float(((int)n + 127) << 23);
}

__device__ __forceinline__ float block_reduce_sum(float v) {
    __shared__ float red[32];
    int lane = threadIdx.x & 31, w = threadIdx.x >> 5;
#pragma unroll
    for (int o = 16; o > 0; o >>= 1) v += __shfl_xor_sync(0xffffffffu, v, o);
    __syncthreads();
    if (lane == 0) red[w] = v;
    __syncthreads();
    v = (lane < 8) ? red[lane] : 0.f;
#pragma unroll
    for (int o = 16; o > 0; o >>= 1) v += __shfl_xor_sync(0xffffffffu, v, o);
    return v;
}

// ---------------- LayerNorm -> bf16 hi/lo planes ----------------
__global__ void ln_split(const float* __restrict__ x, const float* __restrict__ g,
                         const float* __restrict__ b,
                         uint16_t* __restrict__ oh, uint16_t* __restrict__ ol) {
    int row = blockIdx.x, t = threadIdx.x;
    float4 v = *(const float4*)&x[(size_t)row * EE + 4 * t];
    float s = v.x + v.y + v.z + v.w;
    float mean = block_reduce_sum(s) * (1.0f / EE);
    float d0 = v.x - mean, d1 = v.y - mean, d2 = v.z - mean, d3 = v.w - mean;
    float var = block_reduce_sum(d0 * d0 + d1 * d1 + d2 * d2 + d3 * d3) * (1.0f / EE);
    float rstd = rsqrtf(var + LN_EPS);
    float4 gg = *(const float4*)&g[4 * t];
    float4 bb = *(const float4*)&b[4 * t];
    float y0 = d0 * rstd * gg.x + bb.x;
    float y1 = d1 * rstd * gg.y + bb.y;
    float y2 = d2 * rstd * gg.z + bb.z;
    float y3 = d3 * rstd * gg.w + bb.w;
    __nv_bfloat16 h0, h1, h2, h3, l0, l1, l2, l3;
    split1(y0, h0, l0); split1(y1, h1, l1); split1(y2, h2, l2); split1(y3, h3, l3);
    size_t off = (size_t)row * EE + 4 * t;
    *(uint2*)&oh[off] = make_uint2(pk2(h0, h1), pk2(h2, h3));
    *(uint2*)&ol[off] = make_uint2(pk2(l0, l1), pk2(l2, l3));
}

// ---------------- weight conversion (hi plane only), single launch ----------------
__device__ __forceinline__ void convB_body(const float* __restrict__ W,
                                           uint16_t* __restrict__ Bh, int K, int N) {
    __shared__ float ts[64][129];
    int nt = blockIdx.x, kt = blockIdx.y, tid = threadIdx.x;
    int k0 = kt * 64, n0 = nt * 128;
#pragma unroll
    for (int i = 0; i < 32; i++) {
        int idx = tid + i * 256;
        int kk = idx >> 7, nn = idx & 127;
        ts[kk][nn] = W[(size_t)(k0 + kk) * N + n0 + nn];
    }
    __syncthreads();
#pragma unroll
    for (int j = 0; j < 4; j++) {
        int job = tid + j * 256;
        int n = job >> 3, kg = (job & 7) * 8;
        __nv_bfloat16 h[8];
#pragma unroll
        for (int i = 0; i < 8; i++) h[i] = __float2bfloat16(ts[kg + i][n]);
        uint4 uh = make_uint4(pk2(h[0], h[1]), pk2(h[2], h[3]), pk2(h[4], h[5]), pk2(h[6], h[7]));
        size_t off = (size_t)(n0 + n) * K + k0 + kg;
        *(uint4*)&Bh[off] = uh;
    }
}

struct ConvJobs {
    const float* src[10];
    uint16_t* dh[10];
    int K[10], N[10];
};
__global__ void conv_all(ConvJobs j) {
    int w = blockIdx.z;
    int K = j.K[w], N = j.N[w];
    if (blockIdx.x * 128 >= N || blockIdx.y * 64 >= K) return;
    convB_body(j.src[w], j.dh[w], K, N);
}

// ---------------- HMMA bf16-split GEMM ----------------
// MODE 0: C=AB(fp32, ldC)  1: planes=gelu(AB+bias)  2: C=AB+bias+R (+planes)  3: C=AB+R
// AL: include Al*Bh term (activation lo plane).
template<int MODE, int AL>
__global__ void __launch_bounds__(256, 2) gemm_tc(
    const uint16_t* __restrict__ Ah, const uint16_t* __restrict__ Al,
    const uint16_t* __restrict__ Bh,
    const float* __restrict__ bias, const float* __restrict__ R,
    float* __restrict__ C, uint16_t* __restrict__ Ch, uint16_t* __restrict__ Cl,
    int N, int K, int ldC)
{
    extern __shared__ char sm[];
    const uint32_t sbase = (uint32_t)__cvta_generic_to_shared(sm);
    const int tid = threadIdx.x;
    const int warp = tid >> 5, lane = tid & 31;
    const int wm = warp & 1, wn = warp >> 1;
    const int m0 = blockIdx.y * 128, n0 = blockIdx.x * 128;
    const int KT = K >> 5;

    const uint16_t* gA[2] = { Ah + (size_t)m0 * K, AL ? (Al + (size_t)m0 * K) : nullptr };
    const uint16_t* gBh = Bh + (size_t)n0 * K;

    const int rl = lane & 7, grp = lane >> 3;
    const int a_r = rl + (grp & 1) * 8;
    const int a_c = (grp >> 1) * 8;
    const int b_r = rl + ((grp >> 1) & 1) * 8;
    const int b_c = (grp & 1) * 8;

    float acc[4][4][4];
#pragma unroll
    for (int i = 0; i < 4; i++)
#pragma unroll
        for (int j = 0; j < 4; j++)
#pragma unroll
            for (int k = 0; k < 4; k++) acc[i][j][k] = 0.f;

    auto issue = [&](int stage, int kt) {
        uint32_t s0 = sbase + stage * STAGE_B;
        int kel = kt * 32;
#pragma unroll
        for (int pl = 0; pl < 3; pl++) {
            if (pl == 1 && !AL) continue;
            const uint16_t* g = (pl < 2) ? gA[pl] : gBh;
#pragma unroll
            for (int i = 0; i < 2; i++) {
                int seg = tid + i * 256;
                int m = seg >> 2, s = seg & 3;
                cpa16(s0 + pl * PLANE_B + m * ROWB + s * 16,
                      g + (size_t)m * K + kel + s * 8);
            }
        }
        cpa_commit();
    };

    issue(0, 0);
    for (int kt = 0; kt < KT; kt++) {
        int st = kt & 1;
        if (kt + 1 < KT) { issue(st ^ 1, kt + 1); cpa_wait<1>(); }
        else             { cpa_wait<0>(); }
        __syncthreads();

        uint32_t sA_h = sbase + st * STAGE_B;
        uint32_t sA_l = sA_h + PLANE_B;
        uint32_t sB_h = sA_h + 2 * PLANE_B;

#pragma unroll
        for (int ks = 0; ks < 2; ks++) {
            const int kk = ks * 16;
            uint32_t bh[2][4];
#pragma unroll
            for (int ntp = 0; ntp < 2; ntp++) {
                uint32_t off = (uint32_t)((wn * 32 + ntp * 16 + b_r) * ROWB + (kk + b_c) * 2);
                ldsm4(bh[ntp][0], bh[ntp][1], bh[ntp][2], bh[ntp][3], sB_h + off);
            }
#pragma unroll
            for (int mt = 0; mt < 4; mt++) {
                uint32_t off = (uint32_t)((wm * 64 + mt * 16 + a_r) * ROWB + (kk + a_c) * 2);
                uint32_t ah[4], al[4];
                ldsm4(ah[0], ah[1], ah[2], ah[3], sA_h + off);
                if (AL) ldsm4(al[0], al[1], al[2], al[3], sA_l + off);
#pragma unroll
                for (int nt = 0; nt < 4; nt++) {
                    uint32_t bfh[2] = { bh[nt >> 1][(nt & 1) * 2], bh[nt >> 1][(nt & 1) * 2 + 1] };
                    mma16816(acc[mt][nt], ah, bfh);
                    if (AL) mma16816(acc[mt][nt], al, bfh);
                }
            }
        }
        __syncthreads();
    }

    const int r = lane >> 2, q = lane & 3;
#pragma unroll
    for (int mt = 0; mt < 4; mt++) {
#pragma unroll
        for (int nt = 0; nt < 4; nt++) {
            int row = m0 + wm * 64 + mt * 16 + r;
            int col = n0 + wn * 32 + nt * 8 + q * 2;
#pragma unroll
            for (int half = 0; half < 2; half++) {
                int rr2 = row + half * 8;
                float v0 = acc[mt][nt][half * 2 + 0];
                float v1 = acc[mt][nt][half * 2 + 1];
                size_t gidx = (size_t)rr2 * ldC + col;
                if (MODE == 1) {
                    v0 += bias[col];
                    v1 += bias[col + 1];
                    v0 = 0.5f * v0 * (1.0f + erff(v0 * 0.70710678118654752f));
                    v1 = 0.5f * v1 * (1.0f + erff(v1 * 0.70710678118654752f));
                    __nv_bfloat16 h0, h1, l0, l1;
                    split1(v0, h0, l0); split1(v1, h1, l1);
                    *(uint32_t*)&Ch[gidx] = pk2(h0, h1);
                    *(uint32_t*)&Cl[gidx] = pk2(l0, l1);
                } else {
                    if (MODE == 2) {
                        float2 rv = *(const float2*)&R[gidx];
                        v0 += bias[col] + rv.x;
                        v1 += bias[col + 1] + rv.y;
                    } else if (MODE == 3) {
                        float2 rv = *(const float2*)&R[gidx];
                        v0 += rv.x;
                        v1 += rv.y;
                    }
                    *(float2*)&C[gidx] = make_float2(v0, v1);
                    if (MODE == 2 && Ch) {
                        __nv_bfloat16 h0, h1, l0, l1;
                        split1(v0, h0, l0); split1(v1, h1, l1);
                        *(uint32_t*)&Ch[gidx] = pk2(h0, h1);
                        *(uint32_t*)&Cl[gidx] = pk2(l0, l1);
                    }
                }
            }
        }
    }
}

// ---------------- RoPE + split to flash planes (Q hi, K hi, V hi) ----------------
__global__ void rope_split(const float* __restrict__ qkv,
                           uint16_t* __restrict__ fqh,
                           uint16_t* __restrict__ fkh, uint16_t* __restrict__ fvh) {
    int row = blockIdx.x, t = threadIdx.x;
    int i = t & 31;
    int s = row & (SS - 1);
    float inv = __expf(-logf(10000.0f) * ((float)i / 32.0f));
    float ang = (float)s * inv;
    float c = cosf(ang), sn = sinf(ang);
    const float* base = qkv + (size_t)row * 1536;
    size_t dst = (size_t)row * DAA + 2 * t;

    float x1 = base[2 * t], x2 = base[2 * t + 1];
    float o1 = x1 * c - x2 * sn, o2 = x1 * sn + x2 * c;
    *(uint32_t*)&fqh[dst] = pk2(__float2bfloat16(o1), __float2bfloat16(o2));

    x1 = base[512 + 2 * t]; x2 = base[512 + 2 * t + 1];
    o1 = x1 * c - x2 * sn; o2 = x1 * sn + x2 * c;
    *(uint32_t*)&fkh[dst] = pk2(__float2bfloat16(o1), __float2bfloat16(o2));

    x1 = base[1024 + 2 * t]; x2 = base[1024 + 2 * t + 1];
    *(uint32_t*)&fvh[dst] = pk2(__float2bfloat16(x1), __float2bfloat16(x2));
}

// ---------------- Flash attention: Q hi, K hi, V hi; HMMA + poly exp2 ----------------
template<int ICL>
__global__ void __launch_bounds__(256) flash_mma(
    const uint16_t* __restrict__ Qh,
    const uint16_t* __restrict__ Kh, const uint16_t* __restrict__ Vh,
    uint16_t* __restrict__ Oh, uint16_t* __restrict__ Ol)
{
    extern __shared__ char sm[];
    const uint32_t sb = (uint32_t)__cvta_generic_to_shared(sm);
    const uint32_t sQh = sb;
    const uint32_t sKV = sb + FQPL;
    const int tid = threadIdx.x, warp = tid >> 5, lane = tid & 31;
    const int qt = gridDim.x - 1 - blockIdx.x;
    const int bh = blockIdx.y, b = bh >> 3, h = bh & 7;
    const int qg0 = qt * 128;
    const size_t tokb = (size_t)b * SS;
    const int rb = warp * 16;

    const int rl = lane & 7, grp = lane >> 3;
    const int a_r = rl + (grp & 1) * 8;
    const int a_c = (grp >> 1) * 8;
    const int b_r = rl + ((grp >> 1) & 1) * 8;
    const int b_c = (grp & 1) * 8;

#pragma unroll
    for (int i = 0; i < 4; i++) {
        int job = tid + i * 256;
        int r = (job >> 3) & 127, s = job & 7;
        cpa16(sQh + r * FROWB + s * 16,
              Qh + (tokb + qg0 + r) * DAA + h * DHH + s * 8);
    }
    cpa_commit();

    float out[8][4];
#pragma unroll
    for (int i = 0; i < 8; i++)
#pragma unroll
        for (int j = 0; j < 4; j++) out[i][j] = 0.f;
    float mrow[2] = { -1e30f, -1e30f }, lrow[2] = { 0.f, 0.f };

    const int ktmax = (qg0 + 127) >> 6;

    auto issueKV = [&](int st, int kt) {
        uint32_t s0 = sKV + st * FSTG;
        int kg0 = kt * 64;
#pragma unroll
        for (int i = 0; i < 4; i++) {
            int job = tid + i * 256;
            int pl = job >> 9, r = (job >> 3) & 63, s = job & 7;
            const uint16_t* gp = (pl == 0) ? Kh : Vh;
            cpa16(s0 + pl * FKPL + r * FROWB + s * 16,
                  gp + (tokb + kg0 + r) * DAA + h * DHH + s * 8);
        }
        cpa_commit();
    };
    issueKV(0, 0);

    const int qrow0 = qg0 + rb + (lane >> 2);

    for (int kt = 0; kt <= ktmax; kt++) {
        int st = kt & 1;
        int kg0 = kt * 64;
        if (kt < ktmax) { issueKV(st ^ 1, kt + 1); cpa_wait<1>(); }
        else            { cpa_wait<0>(); }
        __syncthreads();

        uint32_t sK_h = sKV + st * FSTG;
        uint32_t sV_h = sK_h + FKPL;

        float sc[8][4];
#pragma unroll
        for (int i = 0; i < 8; i++)
#pragma unroll
            for (int j = 0; j < 4; j++) sc[i][j] = 0.f;
#pragma unroll
        for (int k16 = 0; k16 < 4; k16++) {
            uint32_t qoff = (uint32_t)((rb + a_r) * FROWB + (k16 * 16 + a_c) * 2);
            uint32_t ah[4];
            ldsm4(ah[0], ah[1], ah[2], ah[3], sQh + qoff);
#pragma unroll
            for (int ntp = 0; ntp < 4; ntp++) {
                uint32_t koff = (uint32_t)((ntp * 16 + b_r) * FROWB + (k16 * 16 + b_c) * 2);
                uint32_t kh[4];
                ldsm4(kh[0], kh[1], kh[2], kh[3], sK_h + koff);
#pragma unroll
                for (int u = 0; u < 2; u++) {
                    int nt = ntp * 2 + u;
                    uint32_t bfh[2] = { kh[u * 2], kh[u * 2 + 1] };
                    mma16816(sc[nt], ah, bfh);
                }
            }
        }

        const bool boundary = (kg0 + 63 >= qg0);
#pragma unroll
        for (int nt = 0; nt < 8; nt++) {
#pragma unroll
            for (int c = 0; c < 4; c++) {
                float v = sc[nt][c] * SCALE_L2E;
                if (boundary) {
                    int qg = qrow0 + (c >> 1) * 8;
                    int kg = kg0 + nt * 8 + (lane & 3) * 2 + (c & 1);
                    bool allow = ICL ? (kg < qg || (qg | kg) == 0) : (kg <= qg);
                    v = allow ? v : -1e30f;
                }
                sc[nt][c] = v;
            }
        }

#pragma unroll
        for (int ri = 0; ri < 2; ri++) {
            float mx = -1e30f;
#pragma unroll
            for (int nt = 0; nt < 8; nt++)
                mx = fmaxf(mx, fmaxf(sc[nt][ri * 2], sc[nt][ri * 2 + 1]));
            mx = fmaxf(mx, __shfl_xor_sync(0xffffffffu, mx, 1));
            mx = fmaxf(mx, __shfl_xor_sync(0xffffffffu, mx, 2));
            float mn = fmaxf(mrow[ri], mx);
            float corr = exp2p(mrow[ri] - mn);
            mrow[ri] = mn;
            float rs = 0.f;
#pragma unroll
            for (int nt = 0; nt < 8; nt++) {
                float p0 = exp2p(sc[nt][ri * 2] - mn);
                float p1 = exp2p(sc[nt][ri * 2 + 1] - mn);
                sc[nt][ri * 2] = p0;
                sc[nt][ri * 2 + 1] = p1;
                rs += p0 + p1;
            }
            rs += __shfl_xor_sync(0xffffffffu, rs, 1);
            rs += __shfl_xor_sync(0xffffffffu, rs, 2);
            lrow[ri] = lrow[ri] * corr + rs;
#pragma unroll
            for (int nt = 0; nt < 8; nt++) {
                out[nt][ri * 2] *= corr;
                out[nt][ri * 2 + 1] *= corr;
            }
        }

#pragma unroll
        for (int j = 0; j < 4; j++) {
            uint32_t aP[4];
            aP[0] = pk2(__float2bfloat16(sc[2 * j][0]),     __float2bfloat16(sc[2 * j][1]));
            aP[1] = pk2(__float2bfloat16(sc[2 * j][2]),     __float2bfloat16(sc[2 * j][3]));
            aP[2] = pk2(__float2bfloat16(sc[2 * j + 1][0]), __float2bfloat16(sc[2 * j + 1][1]));
            aP[3] = pk2(__float2bfloat16(sc[2 * j + 1][2]), __float2bfloat16(sc[2 * j + 1][3]));
#pragma unroll
            for (int nt2 = 0; nt2 < 4; nt2++) {
                uint32_t voff = (uint32_t)((j * 16 + (grp & 1) * 8 + rl) * FROWB
                                           + (nt2 * 16 + (grp >> 1) * 8) * 2);
                uint32_t bv[4];
                ldsm4t(bv[0], bv[1], bv[2], bv[3], sV_h + voff);
                uint32_t b0[2] = { bv[0], bv[1] }, b1[2] = { bv[2], bv[3] };
                mma16816(out[nt2 * 2], aP, b0);
                mma16816(out[nt2 * 2 + 1], aP, b1);
            }
        }
        __syncthreads();
    }

#pragma unroll
    for (int ri = 0; ri < 2; ri++) {
        float inv = 1.0f / lrow[ri];
        size_t rbase = (tokb + qrow0 + ri * 8) * DAA + h * DHH + (lane & 3) * 2;
#pragma unroll
        for (int nt = 0; nt < 8; nt++) {
            float v0 = out[nt][ri * 2] * inv;
            float v1 = out[nt][ri * 2 + 1] * inv;
            __nv_bfloat16 h0, h1, l0, l1;
            split1(v0, h0, l0); split1(v1, h1, l1);
            *(uint32_t*)&Oh[rbase + nt * 8] = pk2(h0, h1);
            *(uint32_t*)&Ol[rbase + nt * 8] = pk2(l0, l1);
        }
    }
}

// ---------------- host driver ----------------
#define GETSYM(T, var, sym) T* var; { void* _p; cudaGetSymbolAddress(&_p, sym); var = (T*)_p; }

extern "C" void kernel_launch(void* const* d_in, const int* in_sizes, int n_in,
                              void* d_out, int out_size)
{
    const float* cov_in  = (const float*)d_in[0];
    const float* tgt_in  = (const float*)d_in[1];
    const float* fu_in   = (const float*)d_in[2];
    const float* fc1w    = (const float*)d_in[3];
    const float* fc1b    = (const float*)d_in[4];
    const float* fc2w    = (const float*)d_in[5];
    const float* fc2b    = (const float*)d_in[6];
    const float* icl_wq  = (const float*)d_in[7];
    const float* icl_wk  = (const float*)d_in[8];
    const float* icl_wv  = (const float*)d_in[9];
    const float* icl_wo  = (const float*)d_in[10];
    const float* cov_wq  = (const float*)d_in[11];
    const float* cov_wk  = (const float*)d_in[12];
    const float* cov_wv  = (const float*)d_in[13];
    const float* cov_wo  = (const float*)d_in[14];
    const float* ln_cm_g = (const float*)d_in[15];
    const float* ln_cm_b = (const float*)d_in[16];
    const float* ln_ia_g = (const float*)d_in[17];
    const float* ln_ia_b = (const float*)d_in[18];
    const float* ln_im_g = (const float*)d_in[19];
    const float* ln_im_b = (const float*)d_in[20];

    float* out_cov = (float*)d_out;
    float* out_tgt = out_cov + (size_t)NTOK * EE;
    float* out_fu  = out_tgt + (size_t)NTOK * EE;

    GETSYM(float, qkvI, g_qkvI)    GETSYM(float, qkvC, g_qkvC)
    GETSYM(uint16_t, lnh, pLNh)    GETSYM(uint16_t, lnl, pLNl)
    GETSYM(uint16_t, ln2h, pLN2h)  GETSYM(uint16_t, ln2l, pLN2l)
    GETSYM(uint16_t, midh, pMIDh)  GETSYM(uint16_t, midl, pMIDl)
    GETSYM(uint16_t, mid2h, pMID2h) GETSYM(uint16_t, mid2l, pMID2l)
    GETSYM(uint16_t, qh, pQh)      GETSYM(uint16_t, ql, pQl)
    GETSYM(uint16_t, tgh, pTGTh)   GETSYM(uint16_t, tgl, pTGTl)
    GETSYM(uint16_t, aoIh, pAOIh)  GETSYM(uint16_t, aoIl, pAOIl)
    GETSYM(uint16_t, aoCh, pAOCh)  GETSYM(uint16_t, aoCl, pAOCl)
    GETSYM(uint16_t, fqIh, pFQIh)
    GETSYM(uint16_t, fkIh, pFKIh)  GETSYM(uint16_t, fvIh, pFVIh)
    GETSYM(uint16_t, fqCh, pFQCh)
    GETSYM(uint16_t, fkCh, pFKCh)  GETSYM(uint16_t, fvCh, pFVCh)
    GETSYM(uint16_t, w1h, pW1h)
    GETSYM(uint16_t, w2h, pW2h)
    GETSYM(uint16_t, iqkh, pIQKh)
    GETSYM(uint16_t, ivh, pIVh)
    GETSYM(uint16_t, ioh, pIOh)
    GETSYM(uint16_t, cqkvh, pCQKVh)
    GETSYM(uint16_t, coh, pCOh)

    static cudaStream_t s2 = nullptr;
    static cudaEvent_t ev0 = nullptr, evq = nullptr, evend = nullptr;
    if (!s2) {
        cudaStreamCreateWithFlags(&s2, cudaStreamNonBlocking);
        cudaEventCreateWithFlags(&ev0, cudaEventDisableTiming);
        cudaEventCreateWithFlags(&evq, cudaEventDisableTiming);
        cudaEventCreateWithFlags(&evend, cudaEventDisableTiming);
        cudaFuncSetAttribute((const void*)gemm_tc<0, 0>, cudaFuncAttributeMaxDynamicSharedMemorySize, SMEM_GEMM);
        cudaFuncSetAttribute((const void*)gemm_tc<1, 1>, cudaFuncAttributeMaxDynamicSharedMemorySize, SMEM_GEMM);
        cudaFuncSetAttribute((const void*)gemm_tc<2, 1>, cudaFuncAttributeMaxDynamicSharedMemorySize, SMEM_GEMM);
        cudaFuncSetAttribute((const void*)gemm_tc<3, 1>, cudaFuncAttributeMaxDynamicSharedMemorySize, SMEM_GEMM);
        cudaFuncSetAttribute((const void*)flash_mma<0>, cudaFuncAttributeMaxDynamicSharedMemorySize, SMEM_FLASH);
        cudaFuncSetAttribute((const void*)flash_mma<1>, cudaFuncAttributeMaxDynamicSharedMemorySize, SMEM_FLASH);
    }

    const dim3 thr(256);
    const dim3 gFC1(DMLP / 128, NTOK / 128);
    const dim3 gFC2(EE / 128, NTOK / 128);
    const dim3 gQK(8, NTOK / 128);
    const dim3 gV(4, NTOK / 128);
    const dim3 gQKV(12, NTOK / 128);
    const dim3 gWO(EE / 128, NTOK / 128);
    const dim3 gFLASH(SS / 128, BB * HH);

    // ---- all weight conversions (hi planes only), one launch ----
    ConvJobs cj;
    cj.src[0] = fc1w;   cj.dh[0] = w1h;              cj.K[0] = EE;   cj.N[0] = DMLP;
    cj.src[1] = fc2w;   cj.dh[1] = w2h;              cj.K[1] = DMLP; cj.N[1] = EE;
    cj.src[2] = icl_wq; cj.dh[2] = iqkh;             cj.K[2] = EE;   cj.N[2] = DAA;
    cj.src[3] = icl_wk; cj.dh[3] = iqkh + 512 * EE;  cj.K[3] = EE;   cj.N[3] = DAA;
    cj.src[4] = icl_wv; cj.dh[4] = ivh;              cj.K[4] = EE;   cj.N[4] = DAA;
    cj.src[5] = cov_wq; cj.dh[5] = cqkvh;            cj.K[5] = EE;   cj.N[5] = DAA;
    cj.src[6] = cov_wk; cj.dh[6] = cqkvh + 512 * EE; cj.K[6] = EE;   cj.N[6] = DAA;
    cj.src[7] = cov_wv; cj.dh[7] = cqkvh + 1024 * EE;cj.K[7] = EE;   cj.N[7] = DAA;
    cj.src[8] = icl_wo; cj.dh[8] = ioh;              cj.K[8] = DAA;  cj.N[8] = EE;
    cj.src[9] = cov_wo; cj.dh[9] = coh;              cj.K[9] = DAA;  cj.N[9] = EE;
    conv_all<<<dim3(16, 32, 10), thr>>>(cj);
    cudaEventRecord(ev0, 0);
    cudaStreamWaitEvent(s2, ev0, 0);

    // ---- chain2 on s2: tgt = targets + MLP(LN(functional_update)) ----
    ln_split<<<NTOK, thr, 0, s2>>>(fu_in, ln_im_g, ln_im_b, ln2h, ln2l);
    gemm_tc<1, 1><<<gFC1, thr, SMEM_GEMM, s2>>>(ln2h, ln2l, w1h, fc1b, nullptr,
                                                nullptr, mid2h, mid2l, DMLP, EE, DMLP);
    gemm_tc<2, 1><<<gFC2, thr, SMEM_GEMM, s2>>>(mid2h, mid2l, w2h, fc2b, tgt_in,
                                                out_tgt, tgh, tgl, EE, DMLP, EE);
    // V-projection depends only on tgt — pure bf16
    gemm_tc<0, 0><<<gV, thr, SMEM_GEMM, s2>>>(tgh, nullptr, ivh, nullptr, nullptr,
                                              qkvI + 1024, nullptr, nullptr, DAA, EE, 1536);

    // ---- chain1 on legacy: cov = covariates + MLP(LN(covariates)); q = LN(cov) ----
    ln_split<<<NTOK, thr>>>(cov_in, ln_cm_g, ln_cm_b, lnh, lnl);
    gemm_tc<1, 1><<<gFC1, thr, SMEM_GEMM>>>(lnh, lnl, w1h, fc1b, nullptr,
                                            nullptr, midh, midl, DMLP, EE, DMLP);
    gemm_tc<2, 1><<<gFC2, thr, SMEM_GEMM>>>(midh, midl, w2h, fc2b, cov_in,
                                            out_cov, nullptr, nullptr, EE, DMLP, EE);
    ln_split<<<NTOK, thr>>>(out_cov, ln_ia_g, ln_ia_b, qh, ql);
    cudaEventRecord(evq, 0);

    // ---- ICL attention on s2 (needs q + tgt) ----
    cudaStreamWaitEvent(s2, evq, 0);
    gemm_tc<0, 0><<<gQK, thr, SMEM_GEMM, s2>>>(qh, nullptr, iqkh, nullptr, nullptr,
                                               qkvI, nullptr, nullptr, 1024, EE, 1536);
    rope_split<<<NTOK, thr, 0, s2>>>(qkvI, fqIh, fkIh, fvIh);
    flash_mma<1><<<gFLASH, thr, SMEM_FLASH, s2>>>(fqIh, fkIh, fvIh, aoIh, aoIl);
    gemm_tc<3, 1><<<gWO, thr, SMEM_GEMM, s2>>>(aoIh, aoIl, ioh, nullptr, fu_in,
                                               out_fu, nullptr, nullptr, EE, DAA, EE);
    cudaEventRecord(evend, s2);

    // ---- COV attention on legacy (needs only q) ----
    gemm_tc<0, 0><<<gQKV, thr, SMEM_GEMM>>>(qh, nullptr, cqkvh, nullptr, nullptr,
                                            qkvC, nullptr, nullptr, 1536, EE, 1536);
    rope_split<<<NTOK, thr>>>(qkvC, fqCh, fkCh, fvCh);
    flash_mma<0><<<gFLASH, thr, SMEM_FLASH>>>(fqCh, fkCh, fvCh, aoCh, aoCl);
    gemm_tc<3, 1><<<gWO, thr, SMEM_GEMM>>>(aoCh, aoCl, coh, nullptr, out_cov,
                                           out_cov, nullptr, nullptr, EE, DAA, EE);

    // join
    cudaStreamWaitEvent(0, evend, 0);
}